// round 1
// baseline (speedup 1.0000x reference)
#include <cuda_runtime.h>
#include <math_constants.h>

// Problem constants
#define BB 4
#define SS 2048
#define DD 1024
#define HH 16
#define HDIM 64
#define MTOK (BB * SS)   // 8192

// Scratch (allocation-free rule: __device__ globals)
__device__ float g_q[MTOK * DD];
__device__ float g_k[MTOK * DD];
__device__ float g_v[MTOK * DD];
__device__ float g_att[MTOK * DD];

// ============================================================
// SGEMM: C[M,N] = A[M,K] @ B[K,N] (+ bias[N] if bias != null)
// 128x128 block tile, BK=8, 256 threads, 8x8 per thread.
// ============================================================
#define GBM 128
#define GBN 128
#define GBK 8

__global__ __launch_bounds__(256) void sgemm_kernel(
    const float* __restrict__ A, const float* __restrict__ Bw,
    const float* __restrict__ bias, float* __restrict__ C,
    int M, int N, int K)
{
    __shared__ float As[GBK][GBM];   // A tile stored transposed
    __shared__ float Bs[GBK][GBN];

    const int tid = threadIdx.x;
    const int br = blockIdx.y, bc = blockIdx.x;

    const float* Ab = A + (size_t)br * GBM * K;
    const float* Bb = Bw + bc * GBN;

    const int arow = tid >> 1;            // 0..127
    const int acol = (tid & 1) * 4;       // 0 or 4
    const int brow = tid >> 5;            // 0..7
    const int bcol = (tid & 31) * 4;      // 0..124
    const int tr = (tid >> 4) * 8;        // row of 8x8 micro tile
    const int tc = (tid & 15) * 8;        // col of 8x8 micro tile

    float acc[8][8];
    #pragma unroll
    for (int i = 0; i < 8; i++)
        #pragma unroll
        for (int j = 0; j < 8; j++) acc[i][j] = 0.f;

    for (int k0 = 0; k0 < K; k0 += GBK) {
        float4 a4 = *(const float4*)(Ab + (size_t)arow * K + k0 + acol);
        As[acol + 0][arow] = a4.x;
        As[acol + 1][arow] = a4.y;
        As[acol + 2][arow] = a4.z;
        As[acol + 3][arow] = a4.w;
        float4 b4 = *(const float4*)(Bb + (size_t)(k0 + brow) * N + bcol);
        *(float4*)(&Bs[brow][bcol]) = b4;
        __syncthreads();

        #pragma unroll
        for (int kk = 0; kk < GBK; kk++) {
            float ra[8], rb[8];
            *(float4*)(ra)     = *(const float4*)(&As[kk][tr]);
            *(float4*)(ra + 4) = *(const float4*)(&As[kk][tr + 4]);
            *(float4*)(rb)     = *(const float4*)(&Bs[kk][tc]);
            *(float4*)(rb + 4) = *(const float4*)(&Bs[kk][tc + 4]);
            #pragma unroll
            for (int i = 0; i < 8; i++)
                #pragma unroll
                for (int j = 0; j < 8; j++)
                    acc[i][j] += ra[i] * rb[j];
        }
        __syncthreads();
    }

    float* Cb = C + (size_t)(br * GBM + tr) * N + bc * GBN + tc;
    #pragma unroll
    for (int i = 0; i < 8; i++) {
        #pragma unroll
        for (int j = 0; j < 8; j += 4) {
            float4 o;
            o.x = acc[i][j + 0]; o.y = acc[i][j + 1];
            o.z = acc[i][j + 2]; o.w = acc[i][j + 3];
            if (bias) {
                int col = bc * GBN + tc + j;
                o.x += bias[col + 0]; o.y += bias[col + 1];
                o.z += bias[col + 2]; o.w += bias[col + 3];
            }
            *(float4*)(Cb + (size_t)i * N + j) = o;
        }
    }
}

// ============================================================
// Flash attention forward (causal), fp32, online softmax.
// One CTA per (q-tile of 64, head, batch). 256 threads = 16x16
// grid of 4x4 micro-tiles over the 64x64 score block.
// Q/K/V layouts: [b*S + s, h*HD + d] (projection output layout).
// ============================================================
#define QS_STR 68
#define KS_STR 65
#define VS_STR 68
#define PS_STR 68
#define FA_SMEM_FLOATS (64 * (QS_STR + KS_STR + VS_STR + PS_STR))

__global__ __launch_bounds__(256) void flash_kernel(
    const float* __restrict__ Q, const float* __restrict__ K,
    const float* __restrict__ V, float* __restrict__ O)
{
    extern __shared__ float sm[];
    float* Qs = sm;
    float* Ks = Qs + 64 * QS_STR;
    float* Vs = Ks + 64 * KS_STR;
    float* Ps = Vs + 64 * VS_STR;

    const int qt = blockIdx.x;        // q tile (0..31)
    const int h  = blockIdx.y;
    const int b  = blockIdx.z;
    const int tid = threadIdx.x;
    const int tx = tid & 15;          // key-dim group
    const int ty = tid >> 4;          // query-dim group

    const size_t base = ((size_t)b * SS) * DD + (size_t)h * HDIM;

    // Load Q tile once (rows qt*64..qt*64+63, 64 dims) — coalesced float4.
    {
        const float* Qg = Q + base + (size_t)(qt * 64) * DD;
        #pragma unroll
        for (int i = 0; i < 4; i++) {
            int idx = tid + i * 256;
            int r = idx >> 4;
            int c4 = (idx & 15) * 4;
            float4 v4 = *(const float4*)(Qg + (size_t)r * DD + c4);
            *(float4*)(Qs + r * QS_STR + c4) = v4;
        }
    }

    float acc[4][4];
    #pragma unroll
    for (int i = 0; i < 4; i++)
        #pragma unroll
        for (int j = 0; j < 4; j++) acc[i][j] = 0.f;

    float m_i[4], l_i[4];
    #pragma unroll
    for (int i = 0; i < 4; i++) { m_i[i] = -CUDART_INF_F; l_i[i] = 0.f; }

    const float scale = 0.125f;  // 1/sqrt(64)
    const int nk = qt + 1;       // causal: only tiles at/below diagonal

    for (int kt = 0; kt < nk; kt++) {
        __syncthreads();  // protect Ks/Vs/Ps from previous iteration readers

        // Load K, V tiles
        const float* Kg = K + base + (size_t)(kt * 64) * DD;
        const float* Vg = V + base + (size_t)(kt * 64) * DD;
        #pragma unroll
        for (int i = 0; i < 4; i++) {
            int idx = tid + i * 256;
            int r = idx >> 4;
            int c4 = (idx & 15) * 4;
            float4 kv = *(const float4*)(Kg + (size_t)r * DD + c4);
            Ks[r * KS_STR + c4 + 0] = kv.x;
            Ks[r * KS_STR + c4 + 1] = kv.y;
            Ks[r * KS_STR + c4 + 2] = kv.z;
            Ks[r * KS_STR + c4 + 3] = kv.w;
            float4 vv = *(const float4*)(Vg + (size_t)r * DD + c4);
            *(float4*)(Vs + r * VS_STR + c4) = vv;
        }
        __syncthreads();

        // S = Q @ K^T  (64x64, each thread 4x4)
        float s[4][4];
        #pragma unroll
        for (int i = 0; i < 4; i++)
            #pragma unroll
            for (int j = 0; j < 4; j++) s[i][j] = 0.f;

        #pragma unroll 4
        for (int d = 0; d < 64; d++) {
            float rq[4], rk[4];
            #pragma unroll
            for (int i = 0; i < 4; i++) rq[i] = Qs[(ty * 4 + i) * QS_STR + d];
            #pragma unroll
            for (int j = 0; j < 4; j++) rk[j] = Ks[(tx * 4 + j) * KS_STR + d];
            #pragma unroll
            for (int i = 0; i < 4; i++)
                #pragma unroll
                for (int j = 0; j < 4; j++)
                    s[i][j] += rq[i] * rk[j];
        }

        // Scale + causal mask (mask only needed on the diagonal tile)
        if (kt == qt) {
            #pragma unroll
            for (int i = 0; i < 4; i++)
                #pragma unroll
                for (int j = 0; j < 4; j++) {
                    int qr = ty * 4 + i, kc = tx * 4 + j;
                    s[i][j] = (kc <= qr) ? s[i][j] * scale : -CUDART_INF_F;
                }
        } else {
            #pragma unroll
            for (int i = 0; i < 4; i++)
                #pragma unroll
                for (int j = 0; j < 4; j++) s[i][j] *= scale;
        }

        // Row max across 16 lanes (query row owned by lanes with same ty)
        float rmax[4];
        #pragma unroll
        for (int i = 0; i < 4; i++)
            rmax[i] = fmaxf(fmaxf(s[i][0], s[i][1]), fmaxf(s[i][2], s[i][3]));
        #pragma unroll
        for (int off = 8; off > 0; off >>= 1)
            #pragma unroll
            for (int i = 0; i < 4; i++)
                rmax[i] = fmaxf(rmax[i], __shfl_xor_sync(0xffffffffu, rmax[i], off, 16));

        float corr[4];
        #pragma unroll
        for (int i = 0; i < 4; i++) {
            float mnew = fmaxf(m_i[i], rmax[i]);
            corr[i] = __expf(m_i[i] - mnew);  // exp(-inf - finite) = 0 on first tile
            m_i[i] = mnew;
        }

        float rsum[4];
        #pragma unroll
        for (int i = 0; i < 4; i++) {
            rsum[i] = 0.f;
            #pragma unroll
            for (int j = 0; j < 4; j++) {
                float p = __expf(s[i][j] - m_i[i]);  // exp(-inf) = 0 for masked
                s[i][j] = p;
                rsum[i] += p;
            }
        }
        #pragma unroll
        for (int off = 8; off > 0; off >>= 1)
            #pragma unroll
            for (int i = 0; i < 4; i++)
                rsum[i] += __shfl_xor_sync(0xffffffffu, rsum[i], off, 16);

        #pragma unroll
        for (int i = 0; i < 4; i++) {
            l_i[i] = l_i[i] * corr[i] + rsum[i];
            #pragma unroll
            for (int j = 0; j < 4; j++) acc[i][j] *= corr[i];
        }

        // Write P to shared (float4 stores)
        #pragma unroll
        for (int i = 0; i < 4; i++) {
            float4 p4;
            p4.x = s[i][0]; p4.y = s[i][1]; p4.z = s[i][2]; p4.w = s[i][3];
            *(float4*)(Ps + (ty * 4 + i) * PS_STR + tx * 4) = p4;
        }
        __syncthreads();

        // O += P @ V  (inner dim = 64 keys)
        #pragma unroll 4
        for (int c = 0; c < 64; c++) {
            float4 rv = *(const float4*)(Vs + c * VS_STR + tx * 4);
            #pragma unroll
            for (int i = 0; i < 4; i++) {
                float p = Ps[(ty * 4 + i) * PS_STR + c];  // broadcast read
                acc[i][0] += p * rv.x;
                acc[i][1] += p * rv.y;
                acc[i][2] += p * rv.z;
                acc[i][3] += p * rv.w;
            }
        }
    }

    // Epilogue: normalize and store in [b*S+s, h*HD+d] layout
    float* Og = O + base + (size_t)(qt * 64) * DD;
    #pragma unroll
    for (int i = 0; i < 4; i++) {
        float inv = 1.0f / l_i[i];   // l_i >= 1 always (diag self term)
        int r = ty * 4 + i;
        float4 o;
        o.x = acc[i][0] * inv; o.y = acc[i][1] * inv;
        o.z = acc[i][2] * inv; o.w = acc[i][3] * inv;
        *(float4*)(Og + (size_t)r * DD + tx * 4) = o;
    }
}

// ============================================================
// Launch
// ============================================================
extern "C" void kernel_launch(void* const* d_in, const int* in_sizes, int n_in,
                              void* d_out, int out_size)
{
    const float* x  = (const float*)d_in[0];
    const float* Wq = (const float*)d_in[1];
    const float* Wk = (const float*)d_in[2];
    const float* Wv = (const float*)d_in[3];
    const float* Wo = (const float*)d_in[4];
    const float* bo = (const float*)d_in[5];
    float* out = (float*)d_out;

    float *qb, *kb, *vb, *ab;
    cudaGetSymbolAddress((void**)&qb, g_q);
    cudaGetSymbolAddress((void**)&kb, g_k);
    cudaGetSymbolAddress((void**)&vb, g_v);
    cudaGetSymbolAddress((void**)&ab, g_att);

    dim3 ggrid(DD / GBN, MTOK / GBM);  // (8, 64)

    sgemm_kernel<<<ggrid, 256>>>(x, Wq, nullptr, qb, MTOK, DD, DD);
    sgemm_kernel<<<ggrid, 256>>>(x, Wk, nullptr, kb, MTOK, DD, DD);
    sgemm_kernel<<<ggrid, 256>>>(x, Wv, nullptr, vb, MTOK, DD, DD);

    const int fa_smem = FA_SMEM_FLOATS * (int)sizeof(float);  // ~68.9 KB
    cudaFuncSetAttribute(flash_kernel,
                         cudaFuncAttributeMaxDynamicSharedMemorySize, fa_smem);
    flash_kernel<<<dim3(SS / 64, HH, BB), 256, fa_smem>>>(qb, kb, vb, ab);

    sgemm_kernel<<<ggrid, 256>>>(ab, Wo, bo, out, MTOK, DD, DD);
}

// round 3
// speedup vs baseline: 1.5398x; 1.5398x over previous
#include <cuda_runtime.h>
#include <cuda_bf16.h>
#include <math_constants.h>
#include <cstdint>

// Problem constants
#define BB 4
#define SS 2048
#define DD 1024
#define HH 16
#define HDIM 64
#define MTOK (BB * SS)   // 8192
#define GK DD            // GEMM K = 1024

// ---------------- scratch (__device__ globals; allocation-free rule) -------
__device__ float g_q[MTOK * DD];
__device__ float g_k[MTOK * DD];
__device__ float g_v[MTOK * DD];
__device__ float g_att[MTOK * DD];
__device__ __nv_bfloat16 g_xh[MTOK * DD];
__device__ __nv_bfloat16 g_xl[MTOK * DD];
__device__ __nv_bfloat16 g_wqh[DD * DD], g_wql[DD * DD];
__device__ __nv_bfloat16 g_wkh[DD * DD], g_wkl[DD * DD];
__device__ __nv_bfloat16 g_wvh[DD * DD], g_wvl[DD * DD];
__device__ __nv_bfloat16 g_woh[DD * DD], g_wol[DD * DD];

// ---------------- helpers (plain sm_90-era PTX only) ------------------------
__device__ __forceinline__ uint32_t smem_u32(const void* p) {
    uint32_t a;
    asm("{ .reg .u64 t; cvta.to.shared.u64 t, %1; cvt.u32.u64 %0, t; }"
        : "=r"(a) : "l"(p));
    return a;
}
__device__ __forceinline__ void ldsm_x4(uint32_t& r0, uint32_t& r1,
                                        uint32_t& r2, uint32_t& r3, uint32_t addr) {
    asm volatile("ldmatrix.sync.aligned.m8n8.x4.shared.b16 {%0,%1,%2,%3}, [%4];"
                 : "=r"(r0), "=r"(r1), "=r"(r2), "=r"(r3) : "r"(addr));
}
__device__ __forceinline__ void mma16816(float* c, const uint32_t* a,
                                         uint32_t b0, uint32_t b1) {
    asm volatile(
        "mma.sync.aligned.m16n8k16.row.col.f32.bf16.bf16.f32 "
        "{%0,%1,%2,%3}, {%4,%5,%6,%7}, {%8,%9}, {%0,%1,%2,%3};"
        : "+f"(c[0]), "+f"(c[1]), "+f"(c[2]), "+f"(c[3])
        : "r"(a[0]), "r"(a[1]), "r"(a[2]), "r"(a[3]), "r"(b0), "r"(b1));
}
#define CP_ASYNC16(saddr, gaddr) \
    asm volatile("cp.async.cg.shared.global [%0], [%1], 16;" :: "r"(saddr), "l"(gaddr))
#define CP_COMMIT() asm volatile("cp.async.commit_group;" ::: "memory")
#define CP_WAIT(n)  asm volatile("cp.async.wait_group %0;" :: "n"(n) : "memory")

// ============================================================
// split: fp32 -> bf16 hi + bf16 lo (residual)
// ============================================================
__global__ __launch_bounds__(256) void split_kernel(
    const float* __restrict__ in, __nv_bfloat16* __restrict__ hi,
    __nv_bfloat16* __restrict__ lo, int n4)
{
    int i = blockIdx.x * blockDim.x + threadIdx.x;
    if (i >= n4) return;
    float4 v = reinterpret_cast<const float4*>(in)[i];
    __nv_bfloat16 h0 = __float2bfloat16(v.x);
    __nv_bfloat16 h1 = __float2bfloat16(v.y);
    __nv_bfloat16 h2 = __float2bfloat16(v.z);
    __nv_bfloat16 h3 = __float2bfloat16(v.w);
    __nv_bfloat16 l0 = __float2bfloat16(v.x - __bfloat162float(h0));
    __nv_bfloat16 l1 = __float2bfloat16(v.y - __bfloat162float(h1));
    __nv_bfloat16 l2 = __float2bfloat16(v.z - __bfloat162float(h2));
    __nv_bfloat16 l3 = __float2bfloat16(v.w - __bfloat162float(h3));
    __nv_bfloat16 hs[4] = {h0, h1, h2, h3};
    __nv_bfloat16 ls[4] = {l0, l1, l2, l3};
    reinterpret_cast<uint2*>(hi)[i] = *reinterpret_cast<uint2*>(hs);
    reinterpret_cast<uint2*>(lo)[i] = *reinterpret_cast<uint2*>(ls);
}

// ============================================================
// transpose + split: W[K,N] fp32 -> Wt_hi/Wt_lo[N,K] bf16
// ============================================================
__global__ __launch_bounds__(256) void transpose_split_kernel(
    const float* __restrict__ W, __nv_bfloat16* __restrict__ Th,
    __nv_bfloat16* __restrict__ Tl)
{
    __shared__ float t[32][33];
    const int bx = blockIdx.x;  // N tile
    const int by = blockIdx.y;  // K tile
    const int x = threadIdx.x, y = threadIdx.y;  // 32 x 8
    #pragma unroll
    for (int i = 0; i < 4; i++)
        t[y + 8 * i][x] = W[(size_t)(by * 32 + y + 8 * i) * DD + bx * 32 + x];
    __syncthreads();
    #pragma unroll
    for (int i = 0; i < 4; i++) {
        float v = t[x][y + 8 * i];
        __nv_bfloat16 h = __float2bfloat16(v);
        __nv_bfloat16 l = __float2bfloat16(v - __bfloat162float(h));
        size_t off = (size_t)(bx * 32 + y + 8 * i) * DD + by * 32 + x;
        Th[off] = h;
        Tl[off] = l;
    }
}

// ============================================================
// bf16x3 GEMM on mma.sync: C[M,N] = (Ah+Al)[M,K] @ (Bh+Bl)[N,K]^T (+bias)
// 128x128 CTA tile, 8 warps (4x2), warp tile 32x64, K-chunk 32,
// cp.async double-buffered. SMEM rows padded to 80B (conflict-free ldmatrix).
// ============================================================
#define CHK 32
#define ASTRB 80                 // bytes per smem row (32 bf16 + 8 pad)
#define TILEB (128 * ASTRB)      // 10240 B per tile
#define STAGEB (4 * TILEB)       // Ah, Al, Bh, Bl
#define GSMEM (2 * STAGEB)       // 81920 B

__global__ __launch_bounds__(256, 1) void gemm_mma_kernel(
    const __nv_bfloat16* __restrict__ Ah, const __nv_bfloat16* __restrict__ Al,
    const __nv_bfloat16* __restrict__ Bh, const __nv_bfloat16* __restrict__ Bl,
    const float* __restrict__ bias, float* __restrict__ C)
{
    extern __shared__ char dsm[];
    const uint32_t sbase = smem_u32(dsm);

    const int tid = threadIdx.x;
    const int lane = tid & 31;
    const int wid = tid >> 5;
    const int warp_m = wid & 3;      // 4 warps over M (32 rows each)
    const int warp_n = wid >> 2;     // 2 warps over N (64 cols each)
    const int br = blockIdx.y, bc = blockIdx.x;

    const __nv_bfloat16* gsrc[4] = {
        Ah + (size_t)(br * 128) * GK, Al + (size_t)(br * 128) * GK,
        Bh + (size_t)(bc * 128) * GK, Bl + (size_t)(bc * 128) * GK
    };

    // stage loader: 4 tiles x 128 rows x 4 x 16B chunks = 2048 cp.async / 256 thr
    auto load_stage = [&](int k0, int st) {
        const uint32_t s0 = sbase + st * STAGEB;
        #pragma unroll
        for (int p = 0; p < 8; p++) {
            int idx = tid + p * 256;
            int t   = idx >> 9;
            int rem = idx & 511;
            int row = rem >> 2;
            int ch  = rem & 3;
            uint32_t sa = s0 + t * TILEB + row * ASTRB + ch * 16;
            const __nv_bfloat16* g = gsrc[t] + (size_t)row * GK + k0 + ch * 8;
            CP_ASYNC16(sa, g);
        }
        CP_COMMIT();
    };

    float acc[2][8][4];
    #pragma unroll
    for (int mt = 0; mt < 2; mt++)
        #pragma unroll
        for (int nt = 0; nt < 8; nt++)
            #pragma unroll
            for (int j = 0; j < 4; j++) acc[mt][nt][j] = 0.f;

    load_stage(0, 0);

    const int NC = GK / CHK;   // 32
    for (int c = 0; c < NC; c++) {
        if (c + 1 < NC) {
            load_stage((c + 1) * CHK, (c + 1) & 1);
            CP_WAIT(1);
        } else {
            CP_WAIT(0);
        }
        __syncthreads();

        const uint32_t s0  = sbase + (c & 1) * STAGEB;
        const uint32_t sAh = s0, sAl = s0 + TILEB;
        const uint32_t sBh = s0 + 2 * TILEB, sBl = s0 + 3 * TILEB;
        const int lrow = lane & 15;
        const int lsel = (lane >> 4) * 16;

        #pragma unroll
        for (int kk = 0; kk < 2; kk++) {
            const int lcol = lsel + kk * 32;
            uint32_t ah[2][4], al[2][4], bh[4][4], bl[4][4];
            #pragma unroll
            for (int mt = 0; mt < 2; mt++) {
                uint32_t off = (uint32_t)(warp_m * 32 + mt * 16 + lrow) * ASTRB + lcol;
                ldsm_x4(ah[mt][0], ah[mt][1], ah[mt][2], ah[mt][3], sAh + off);
                ldsm_x4(al[mt][0], al[mt][1], al[mt][2], al[mt][3], sAl + off);
            }
            #pragma unroll
            for (int ng = 0; ng < 4; ng++) {
                uint32_t off = (uint32_t)(warp_n * 64 + ng * 16 + lrow) * ASTRB + lcol;
                ldsm_x4(bh[ng][0], bh[ng][1], bh[ng][2], bh[ng][3], sBh + off);
                ldsm_x4(bl[ng][0], bl[ng][1], bl[ng][2], bl[ng][3], sBl + off);
            }
            #pragma unroll
            for (int mt = 0; mt < 2; mt++) {
                #pragma unroll
                for (int ng = 0; ng < 4; ng++) {
                    // n-tile 2*ng: regs {0,2}; n-tile 2*ng+1: regs {1,3}
                    mma16816(acc[mt][2 * ng],     ah[mt], bh[ng][0], bh[ng][2]);
                    mma16816(acc[mt][2 * ng],     al[mt], bh[ng][0], bh[ng][2]);
                    mma16816(acc[mt][2 * ng],     ah[mt], bl[ng][0], bl[ng][2]);
                    mma16816(acc[mt][2 * ng + 1], ah[mt], bh[ng][1], bh[ng][3]);
                    mma16816(acc[mt][2 * ng + 1], al[mt], bh[ng][1], bh[ng][3]);
                    mma16816(acc[mt][2 * ng + 1], ah[mt], bl[ng][1], bl[ng][3]);
                }
            }
        }
        __syncthreads();
    }

    // Epilogue: c-frag layout (lane l: row l/4 (+8), col 2*(l%4)(+1))
    const int row0 = br * 128 + warp_m * 32;
    const int col0 = bc * 128 + warp_n * 64;
    const int qr = lane >> 2;
    const int qc = (lane & 3) * 2;
    #pragma unroll
    for (int mt = 0; mt < 2; mt++) {
        #pragma unroll
        for (int nt = 0; nt < 8; nt++) {
            int col = col0 + nt * 8 + qc;
            float b0 = 0.f, b1 = 0.f;
            if (bias) { b0 = bias[col]; b1 = bias[col + 1]; }
            float* p0 = C + (size_t)(row0 + mt * 16 + qr) * DD + col;
            float* p1 = C + (size_t)(row0 + mt * 16 + qr + 8) * DD + col;
            float2 v0, v1;
            v0.x = acc[mt][nt][0] + b0; v0.y = acc[mt][nt][1] + b1;
            v1.x = acc[mt][nt][2] + b0; v1.y = acc[mt][nt][3] + b1;
            *(float2*)p0 = v0;
            *(float2*)p1 = v1;
        }
    }
}

// ============================================================
// Flash attention forward (causal), fp32 (proven in R1)
// ============================================================
#define QS_STR 68
#define KS_STR 65
#define VS_STR 68
#define PS_STR 68
#define FA_SMEM_FLOATS (64 * (QS_STR + KS_STR + VS_STR + PS_STR))

__global__ __launch_bounds__(256) void flash_kernel(
    const float* __restrict__ Q, const float* __restrict__ K,
    const float* __restrict__ V, float* __restrict__ O)
{
    extern __shared__ float sm[];
    float* Qs = sm;
    float* Ks = Qs + 64 * QS_STR;
    float* Vs = Ks + 64 * KS_STR;
    float* Ps = Vs + 64 * VS_STR;

    const int qt = blockIdx.x;
    const int h  = blockIdx.y;
    const int b  = blockIdx.z;
    const int tid = threadIdx.x;
    const int tx = tid & 15;
    const int ty = tid >> 4;

    const size_t base = ((size_t)b * SS) * DD + (size_t)h * HDIM;

    {
        const float* Qg = Q + base + (size_t)(qt * 64) * DD;
        #pragma unroll
        for (int i = 0; i < 4; i++) {
            int idx = tid + i * 256;
            int r = idx >> 4;
            int c4 = (idx & 15) * 4;
            float4 v4 = *(const float4*)(Qg + (size_t)r * DD + c4);
            *(float4*)(Qs + r * QS_STR + c4) = v4;
        }
    }

    float acc[4][4];
    #pragma unroll
    for (int i = 0; i < 4; i++)
        #pragma unroll
        for (int j = 0; j < 4; j++) acc[i][j] = 0.f;

    float m_i[4], l_i[4];
    #pragma unroll
    for (int i = 0; i < 4; i++) { m_i[i] = -CUDART_INF_F; l_i[i] = 0.f; }

    const float scale = 0.125f;
    const int nk = qt + 1;

    for (int kt = 0; kt < nk; kt++) {
        __syncthreads();
        const float* Kg = K + base + (size_t)(kt * 64) * DD;
        const float* Vg = V + base + (size_t)(kt * 64) * DD;
        #pragma unroll
        for (int i = 0; i < 4; i++) {
            int idx = tid + i * 256;
            int r = idx >> 4;
            int c4 = (idx & 15) * 4;
            float4 kv = *(const float4*)(Kg + (size_t)r * DD + c4);
            Ks[r * KS_STR + c4 + 0] = kv.x;
            Ks[r * KS_STR + c4 + 1] = kv.y;
            Ks[r * KS_STR + c4 + 2] = kv.z;
            Ks[r * KS_STR + c4 + 3] = kv.w;
            float4 vv = *(const float4*)(Vg + (size_t)r * DD + c4);
            *(float4*)(Vs + r * VS_STR + c4) = vv;
        }
        __syncthreads();

        float s[4][4];
        #pragma unroll
        for (int i = 0; i < 4; i++)
            #pragma unroll
            for (int j = 0; j < 4; j++) s[i][j] = 0.f;

        #pragma unroll 4
        for (int d = 0; d < 64; d++) {
            float rq[4], rk[4];
            #pragma unroll
            for (int i = 0; i < 4; i++) rq[i] = Qs[(ty * 4 + i) * QS_STR + d];
            #pragma unroll
            for (int j = 0; j < 4; j++) rk[j] = Ks[(tx * 4 + j) * KS_STR + d];
            #pragma unroll
            for (int i = 0; i < 4; i++)
                #pragma unroll
                for (int j = 0; j < 4; j++)
                    s[i][j] += rq[i] * rk[j];
        }

        if (kt == qt) {
            #pragma unroll
            for (int i = 0; i < 4; i++)
                #pragma unroll
                for (int j = 0; j < 4; j++) {
                    int qr = ty * 4 + i, kc = tx * 4 + j;
                    s[i][j] = (kc <= qr) ? s[i][j] * scale : -CUDART_INF_F;
                }
        } else {
            #pragma unroll
            for (int i = 0; i < 4; i++)
                #pragma unroll
                for (int j = 0; j < 4; j++) s[i][j] *= scale;
        }

        float rmax[4];
        #pragma unroll
        for (int i = 0; i < 4; i++)
            rmax[i] = fmaxf(fmaxf(s[i][0], s[i][1]), fmaxf(s[i][2], s[i][3]));
        #pragma unroll
        for (int off = 8; off > 0; off >>= 1)
            #pragma unroll
            for (int i = 0; i < 4; i++)
                rmax[i] = fmaxf(rmax[i], __shfl_xor_sync(0xffffffffu, rmax[i], off, 16));

        float corr[4];
        #pragma unroll
        for (int i = 0; i < 4; i++) {
            float mnew = fmaxf(m_i[i], rmax[i]);
            corr[i] = __expf(m_i[i] - mnew);
            m_i[i] = mnew;
        }

        float rsum[4];
        #pragma unroll
        for (int i = 0; i < 4; i++) {
            rsum[i] = 0.f;
            #pragma unroll
            for (int j = 0; j < 4; j++) {
                float p = __expf(s[i][j] - m_i[i]);
                s[i][j] = p;
                rsum[i] += p;
            }
        }
        #pragma unroll
        for (int off = 8; off > 0; off >>= 1)
            #pragma unroll
            for (int i = 0; i < 4; i++)
                rsum[i] += __shfl_xor_sync(0xffffffffu, rsum[i], off, 16);

        #pragma unroll
        for (int i = 0; i < 4; i++) {
            l_i[i] = l_i[i] * corr[i] + rsum[i];
            #pragma unroll
            for (int j = 0; j < 4; j++) acc[i][j] *= corr[i];
        }

        #pragma unroll
        for (int i = 0; i < 4; i++) {
            float4 p4;
            p4.x = s[i][0]; p4.y = s[i][1]; p4.z = s[i][2]; p4.w = s[i][3];
            *(float4*)(Ps + (ty * 4 + i) * PS_STR + tx * 4) = p4;
        }
        __syncthreads();

        #pragma unroll 4
        for (int c = 0; c < 64; c++) {
            float4 rv = *(const float4*)(Vs + c * VS_STR + tx * 4);
            #pragma unroll
            for (int i = 0; i < 4; i++) {
                float p = Ps[(ty * 4 + i) * PS_STR + c];
                acc[i][0] += p * rv.x;
                acc[i][1] += p * rv.y;
                acc[i][2] += p * rv.z;
                acc[i][3] += p * rv.w;
            }
        }
    }

    float* Og = O + base + (size_t)(qt * 64) * DD;
    #pragma unroll
    for (int i = 0; i < 4; i++) {
        float inv = 1.0f / l_i[i];
        int r = ty * 4 + i;
        float4 o;
        o.x = acc[i][0] * inv; o.y = acc[i][1] * inv;
        o.z = acc[i][2] * inv; o.w = acc[i][3] * inv;
        *(float4*)(Og + (size_t)r * DD + tx * 4) = o;
    }
}

// ============================================================
// Launch
// ============================================================
extern "C" void kernel_launch(void* const* d_in, const int* in_sizes, int n_in,
                              void* d_out, int out_size)
{
    const float* x  = (const float*)d_in[0];
    const float* Wq = (const float*)d_in[1];
    const float* Wk = (const float*)d_in[2];
    const float* Wv = (const float*)d_in[3];
    const float* Wo = (const float*)d_in[4];
    const float* bo = (const float*)d_in[5];
    float* out = (float*)d_out;

    float *qb, *kb, *vb, *ab;
    __nv_bfloat16 *xh, *xl, *wqh, *wql, *wkh, *wkl, *wvh, *wvl, *woh, *wol;
    cudaGetSymbolAddress((void**)&qb, g_q);
    cudaGetSymbolAddress((void**)&kb, g_k);
    cudaGetSymbolAddress((void**)&vb, g_v);
    cudaGetSymbolAddress((void**)&ab, g_att);
    cudaGetSymbolAddress((void**)&xh, g_xh);
    cudaGetSymbolAddress((void**)&xl, g_xl);
    cudaGetSymbolAddress((void**)&wqh, g_wqh);
    cudaGetSymbolAddress((void**)&wql, g_wql);
    cudaGetSymbolAddress((void**)&wkh, g_wkh);
    cudaGetSymbolAddress((void**)&wkl, g_wkl);
    cudaGetSymbolAddress((void**)&wvh, g_wvh);
    cudaGetSymbolAddress((void**)&wvl, g_wvl);
    cudaGetSymbolAddress((void**)&woh, g_woh);
    cudaGetSymbolAddress((void**)&wol, g_wol);

    // 1. split x to bf16 hi/lo
    const int n4 = MTOK * DD / 4;
    split_kernel<<<n4 / 256, 256>>>(x, xh, xl, n4);

    // 2. transpose+split weights
    dim3 tgrid(DD / 32, DD / 32), tblk(32, 8);
    transpose_split_kernel<<<tgrid, tblk>>>(Wq, wqh, wql);
    transpose_split_kernel<<<tgrid, tblk>>>(Wk, wkh, wkl);
    transpose_split_kernel<<<tgrid, tblk>>>(Wv, wvh, wvl);
    transpose_split_kernel<<<tgrid, tblk>>>(Wo, woh, wol);

    // 3. QKV projections on tensor cores (mma.sync)
    cudaFuncSetAttribute(gemm_mma_kernel,
                         cudaFuncAttributeMaxDynamicSharedMemorySize, GSMEM);
    dim3 ggrid(DD / 128, MTOK / 128);  // (8, 64)
    gemm_mma_kernel<<<ggrid, 256, GSMEM>>>(xh, xl, wqh, wql, nullptr, qb);
    gemm_mma_kernel<<<ggrid, 256, GSMEM>>>(xh, xl, wkh, wkl, nullptr, kb);
    gemm_mma_kernel<<<ggrid, 256, GSMEM>>>(xh, xl, wvh, wvl, nullptr, vb);

    // 4. flash attention (fp32)
    const int fa_smem = FA_SMEM_FLOATS * (int)sizeof(float);
    cudaFuncSetAttribute(flash_kernel,
                         cudaFuncAttributeMaxDynamicSharedMemorySize, fa_smem);
    flash_kernel<<<dim3(SS / 64, HH, BB), 256, fa_smem>>>(qb, kb, vb, ab);

    // 5. split attention output, output projection (+bias)
    split_kernel<<<n4 / 256, 256>>>(ab, xh, xl, n4);
    gemm_mma_kernel<<<ggrid, 256, GSMEM>>>(xh, xl, woh, wol, bo, out);
}

// round 4
// speedup vs baseline: 2.5087x; 1.6292x over previous
#include <cuda_runtime.h>
#include <cuda_bf16.h>
#include <math_constants.h>
#include <cstdint>

// Problem constants
#define BB 4
#define SS 2048
#define DD 1024
#define HH 16
#define HDIM 64
#define MTOK (BB * SS)   // 8192
#define GK DD            // GEMM K = 1024

typedef __nv_bfloat16 bf16;

// ---------------- scratch (__device__ globals; allocation-free rule) -------
__device__ bf16 g_xh[MTOK * DD], g_xl[MTOK * DD];
__device__ bf16 g_qh[MTOK * DD], g_ql[MTOK * DD];
__device__ bf16 g_kh[MTOK * DD], g_kl[MTOK * DD];
__device__ bf16 g_vh[MTOK * DD], g_vl[MTOK * DD];
__device__ bf16 g_wqh[DD * DD], g_wql[DD * DD];
__device__ bf16 g_wkh[DD * DD], g_wkl[DD * DD];
__device__ bf16 g_wvh[DD * DD], g_wvl[DD * DD];
__device__ bf16 g_woh[DD * DD], g_wol[DD * DD];

// ---------------- helpers (plain sm_90-era PTX only) ------------------------
__device__ __forceinline__ uint32_t smem_u32(const void* p) {
    uint32_t a;
    asm("{ .reg .u64 t; cvta.to.shared.u64 t, %1; cvt.u32.u64 %0, t; }"
        : "=r"(a) : "l"(p));
    return a;
}
__device__ __forceinline__ void ldsm_x4(uint32_t& r0, uint32_t& r1,
                                        uint32_t& r2, uint32_t& r3, uint32_t addr) {
    asm volatile("ldmatrix.sync.aligned.m8n8.x4.shared.b16 {%0,%1,%2,%3}, [%4];"
                 : "=r"(r0), "=r"(r1), "=r"(r2), "=r"(r3) : "r"(addr));
}
__device__ __forceinline__ void ldsm_x4_t(uint32_t& r0, uint32_t& r1,
                                          uint32_t& r2, uint32_t& r3, uint32_t addr) {
    asm volatile("ldmatrix.sync.aligned.m8n8.x4.trans.shared.b16 {%0,%1,%2,%3}, [%4];"
                 : "=r"(r0), "=r"(r1), "=r"(r2), "=r"(r3) : "r"(addr));
}
__device__ __forceinline__ void mma16816(float* c, const uint32_t* a,
                                         uint32_t b0, uint32_t b1) {
    asm volatile(
        "mma.sync.aligned.m16n8k16.row.col.f32.bf16.bf16.f32 "
        "{%0,%1,%2,%3}, {%4,%5,%6,%7}, {%8,%9}, {%0,%1,%2,%3};"
        : "+f"(c[0]), "+f"(c[1]), "+f"(c[2]), "+f"(c[3])
        : "r"(a[0]), "r"(a[1]), "r"(a[2]), "r"(a[3]), "r"(b0), "r"(b1));
}
#define CP_ASYNC16(saddr, gaddr) \
    asm volatile("cp.async.cg.shared.global [%0], [%1], 16;" :: "r"(saddr), "l"(gaddr))
#define CP_COMMIT() asm volatile("cp.async.commit_group;" ::: "memory")
#define CP_WAIT(n)  asm volatile("cp.async.wait_group %0;" :: "n"(n) : "memory")

__device__ __forceinline__ uint32_t pack2bf(float a, float b) {
    __nv_bfloat162 t = __floats2bfloat162_rn(a, b);   // .x = a (low), .y = b (high)
    return *reinterpret_cast<uint32_t*>(&t);
}
// split two fp32 into packed hi / packed residual-lo
__device__ __forceinline__ void split2(float a, float b, uint32_t& hi, uint32_t& lo) {
    bf16 ha = __float2bfloat16(a), hb = __float2bfloat16(b);
    hi = pack2bf(__bfloat162float(ha), __bfloat162float(hb));
    lo = pack2bf(a - __bfloat162float(ha), b - __bfloat162float(hb));
}

// ============================================================
// split: fp32 -> bf16 hi + bf16 lo (residual)   [for input x]
// ============================================================
__global__ __launch_bounds__(256) void split_kernel(
    const float* __restrict__ in, bf16* __restrict__ hi,
    bf16* __restrict__ lo, int n4)
{
    int i = blockIdx.x * blockDim.x + threadIdx.x;
    if (i >= n4) return;
    float4 v = reinterpret_cast<const float4*>(in)[i];
    uint32_t h0, l0, h1, l1;
    split2(v.x, v.y, h0, l0);
    split2(v.z, v.w, h1, l1);
    uint2 hh, ll;
    hh.x = h0; hh.y = h1;
    ll.x = l0; ll.y = l1;
    reinterpret_cast<uint2*>(hi)[i] = hh;
    reinterpret_cast<uint2*>(lo)[i] = ll;
}

// ============================================================
// transpose + split: W[K,N] fp32 -> Wt_hi/Wt_lo[N,K] bf16
// ============================================================
__global__ __launch_bounds__(256) void transpose_split_kernel(
    const float* __restrict__ W, bf16* __restrict__ Th, bf16* __restrict__ Tl)
{
    __shared__ float t[32][33];
    const int bx = blockIdx.x, by = blockIdx.y;
    const int x = threadIdx.x, y = threadIdx.y;  // 32 x 8
    #pragma unroll
    for (int i = 0; i < 4; i++)
        t[y + 8 * i][x] = W[(size_t)(by * 32 + y + 8 * i) * DD + bx * 32 + x];
    __syncthreads();
    #pragma unroll
    for (int i = 0; i < 4; i++) {
        float v = t[x][y + 8 * i];
        bf16 h = __float2bfloat16(v);
        bf16 l = __float2bfloat16(v - __bfloat162float(h));
        size_t off = (size_t)(bx * 32 + y + 8 * i) * DD + by * 32 + x;
        Th[off] = h;
        Tl[off] = l;
    }
}

// ============================================================
// bf16x3 GEMM on mma.sync (validated R3), now with optional
// split-bf16 epilogue + exact power-of-2 scale.
// ============================================================
#define CHK 32
#define ASTRB 80
#define TILEB (128 * ASTRB)
#define STAGEB (4 * TILEB)
#define GSMEM (2 * STAGEB)

__global__ __launch_bounds__(256, 1) void gemm_mma_kernel(
    const bf16* __restrict__ Ah, const bf16* __restrict__ Al,
    const bf16* __restrict__ Bh, const bf16* __restrict__ Bl,
    const float* __restrict__ bias, float* __restrict__ Cf,
    bf16* __restrict__ Ch, bf16* __restrict__ Cl, float scale)
{
    extern __shared__ char dsm[];
    const uint32_t sbase = smem_u32(dsm);

    const int tid = threadIdx.x;
    const int lane = tid & 31;
    const int wid = tid >> 5;
    const int warp_m = wid & 3;
    const int warp_n = wid >> 2;
    const int br = blockIdx.y, bc = blockIdx.x;

    const bf16* gsrc[4] = {
        Ah + (size_t)(br * 128) * GK, Al + (size_t)(br * 128) * GK,
        Bh + (size_t)(bc * 128) * GK, Bl + (size_t)(bc * 128) * GK
    };

    auto load_stage = [&](int k0, int st) {
        const uint32_t s0 = sbase + st * STAGEB;
        #pragma unroll
        for (int p = 0; p < 8; p++) {
            int idx = tid + p * 256;
            int t   = idx >> 9;
            int rem = idx & 511;
            int row = rem >> 2;
            int ch  = rem & 3;
            uint32_t sa = s0 + t * TILEB + row * ASTRB + ch * 16;
            const bf16* g = gsrc[t] + (size_t)row * GK + k0 + ch * 8;
            CP_ASYNC16(sa, g);
        }
        CP_COMMIT();
    };

    float acc[2][8][4];
    #pragma unroll
    for (int mt = 0; mt < 2; mt++)
        #pragma unroll
        for (int nt = 0; nt < 8; nt++)
            #pragma unroll
            for (int j = 0; j < 4; j++) acc[mt][nt][j] = 0.f;

    load_stage(0, 0);

    const int NC = GK / CHK;
    for (int c = 0; c < NC; c++) {
        if (c + 1 < NC) {
            load_stage((c + 1) * CHK, (c + 1) & 1);
            CP_WAIT(1);
        } else {
            CP_WAIT(0);
        }
        __syncthreads();

        const uint32_t s0  = sbase + (c & 1) * STAGEB;
        const uint32_t sAh = s0, sAl = s0 + TILEB;
        const uint32_t sBh = s0 + 2 * TILEB, sBl = s0 + 3 * TILEB;
        const int lrow = lane & 15;
        const int lsel = (lane >> 4) * 16;

        #pragma unroll
        for (int kk = 0; kk < 2; kk++) {
            const int lcol = lsel + kk * 32;
            uint32_t ah[2][4], al[2][4], bh[4][4], bl[4][4];
            #pragma unroll
            for (int mt = 0; mt < 2; mt++) {
                uint32_t off = (uint32_t)(warp_m * 32 + mt * 16 + lrow) * ASTRB + lcol;
                ldsm_x4(ah[mt][0], ah[mt][1], ah[mt][2], ah[mt][3], sAh + off);
                ldsm_x4(al[mt][0], al[mt][1], al[mt][2], al[mt][3], sAl + off);
            }
            #pragma unroll
            for (int ng = 0; ng < 4; ng++) {
                uint32_t off = (uint32_t)(warp_n * 64 + ng * 16 + lrow) * ASTRB + lcol;
                ldsm_x4(bh[ng][0], bh[ng][1], bh[ng][2], bh[ng][3], sBh + off);
                ldsm_x4(bl[ng][0], bl[ng][1], bl[ng][2], bl[ng][3], sBl + off);
            }
            #pragma unroll
            for (int mt = 0; mt < 2; mt++) {
                #pragma unroll
                for (int ng = 0; ng < 4; ng++) {
                    mma16816(acc[mt][2 * ng],     ah[mt], bh[ng][0], bh[ng][2]);
                    mma16816(acc[mt][2 * ng],     al[mt], bh[ng][0], bh[ng][2]);
                    mma16816(acc[mt][2 * ng],     ah[mt], bl[ng][0], bl[ng][2]);
                    mma16816(acc[mt][2 * ng + 1], ah[mt], bh[ng][1], bh[ng][3]);
                    mma16816(acc[mt][2 * ng + 1], al[mt], bh[ng][1], bh[ng][3]);
                    mma16816(acc[mt][2 * ng + 1], ah[mt], bl[ng][1], bl[ng][3]);
                }
            }
        }
        __syncthreads();
    }

    const int row0 = br * 128 + warp_m * 32;
    const int col0 = bc * 128 + warp_n * 64;
    const int qr = lane >> 2;
    const int qc = (lane & 3) * 2;
    #pragma unroll
    for (int mt = 0; mt < 2; mt++) {
        #pragma unroll
        for (int nt = 0; nt < 8; nt++) {
            int col = col0 + nt * 8 + qc;
            float b0 = 0.f, b1 = 0.f;
            if (bias) { b0 = bias[col]; b1 = bias[col + 1]; }
            float v0 = acc[mt][nt][0] * scale + b0;
            float v1 = acc[mt][nt][1] * scale + b1;
            float v2 = acc[mt][nt][2] * scale + b0;
            float v3 = acc[mt][nt][3] * scale + b1;
            size_t o0 = (size_t)(row0 + mt * 16 + qr) * DD + col;
            size_t o1 = (size_t)(row0 + mt * 16 + qr + 8) * DD + col;
            if (Cf) {
                float2 w0, w1;
                w0.x = v0; w0.y = v1; w1.x = v2; w1.y = v3;
                *(float2*)(Cf + o0) = w0;
                *(float2*)(Cf + o1) = w1;
            } else {
                uint32_t h0, l0, h1, l1;
                split2(v0, v1, h0, l0);
                split2(v2, v3, h1, l1);
                *(uint32_t*)(Ch + o0) = h0;
                *(uint32_t*)(Cl + o0) = l0;
                *(uint32_t*)(Ch + o1) = h1;
                *(uint32_t*)(Cl + o1) = l1;
            }
        }
    }
}

// ============================================================
// Flash attention (causal) on mma.sync, bf16x3 split precision.
// CTA: 128 threads / 4 warps; tile 64 q-rows x 64 kv; HD=64.
// Q pre-scaled by 0.125 in the Q-projection epilogue (exact).
// ============================================================
#define FSTR 144                  // 64 bf16 = 128B + 16B pad
#define FTILE (64 * FSTR)         // 9216 B
#define FSTAGEB (4 * FTILE)       // Kh,Kl,Vh,Vl
#define FSMEM (2 * FTILE + 2 * FSTAGEB)  // 92160 B

__global__ __launch_bounds__(128) void flash_mma_kernel(
    const bf16* __restrict__ Qh, const bf16* __restrict__ Ql,
    const bf16* __restrict__ Kh, const bf16* __restrict__ Kl,
    const bf16* __restrict__ Vh, const bf16* __restrict__ Vl,
    bf16* __restrict__ Oh, bf16* __restrict__ Ol)
{
    extern __shared__ char dsm[];
    const uint32_t sbase = smem_u32(dsm);

    const int tid = threadIdx.x;
    const int lane = tid & 31;
    const int w = tid >> 5;
    const int qt = blockIdx.x, h = blockIdx.y, b = blockIdx.z;

    const size_t base = ((size_t)b * SS) * DD + (size_t)h * HDIM;
    const bf16* gq[2] = {Qh + base + (size_t)(qt * 64) * DD,
                         Ql + base + (size_t)(qt * 64) * DD};

    // ---- load Q tiles (hi/lo), group with stage0 ----
    {
        #pragma unroll
        for (int p = 0; p < 8; p++) {
            int i = tid + p * 128;          // 0..1023
            int t = i >> 9;                 // tile
            int rem = i & 511;
            int row = rem >> 3;
            int ch = rem & 7;
            CP_ASYNC16(sbase + t * FTILE + row * FSTR + ch * 16,
                       gq[t] + (size_t)row * DD + ch * 8);
        }
    }

    const bf16* gkv[4] = {Kh + base, Kl + base, Vh + base, Vl + base};
    auto load_kv = [&](int kt, int st) {
        const uint32_t s0 = sbase + 2 * FTILE + st * FSTAGEB;
        const size_t roff = (size_t)(kt * 64) * DD;
        #pragma unroll
        for (int p = 0; p < 16; p++) {
            int i = tid + p * 128;          // 0..2047
            int t = i >> 9;
            int rem = i & 511;
            int row = rem >> 3;
            int ch = rem & 7;
            CP_ASYNC16(s0 + t * FTILE + row * FSTR + ch * 16,
                       gkv[t] + roff + (size_t)row * DD + ch * 8);
        }
        CP_COMMIT();
    };

    load_kv(0, 0);   // commits Q + stage0 together

    const int qr = lane >> 2;
    const int ql2 = (lane & 3) * 2;
    const int lrow = lane & 15;
    const int lhalf = (lane >> 4) * 16;   // byte offset

    float oacc[8][4];
    #pragma unroll
    for (int nt = 0; nt < 8; nt++)
        #pragma unroll
        for (int j = 0; j < 4; j++) oacc[nt][j] = 0.f;
    float m0 = -CUDART_INF_F, m1 = -CUDART_INF_F;
    float l0 = 0.f, l1 = 0.f;

    const int row_loc0 = w * 16 + qr;     // local q row (0..63)
    const int nk = qt + 1;

    for (int kt = 0; kt < nk; kt++) {
        if (kt + 1 < nk) {
            load_kv(kt + 1, (kt + 1) & 1);
            CP_WAIT(1);
        } else {
            CP_WAIT(0);
        }
        __syncthreads();

        const uint32_t s0  = sbase + 2 * FTILE + (kt & 1) * FSTAGEB;
        const uint32_t sQh = sbase, sQl = sbase + FTILE;
        const uint32_t sKh = s0,            sKl = s0 + FTILE;
        const uint32_t sVh = s0 + 2 * FTILE, sVl = s0 + 3 * FTILE;

        // ---- S = Q @ K^T (bf16x3) ----
        float sac[8][4];
        #pragma unroll
        for (int nt = 0; nt < 8; nt++)
            #pragma unroll
            for (int j = 0; j < 4; j++) sac[nt][j] = 0.f;

        #pragma unroll
        for (int kk = 0; kk < 4; kk++) {
            uint32_t aoff = (uint32_t)(w * 16 + lrow) * FSTR + lhalf + kk * 32;
            uint32_t qh_[4], ql_[4];
            ldsm_x4(qh_[0], qh_[1], qh_[2], qh_[3], sQh + aoff);
            ldsm_x4(ql_[0], ql_[1], ql_[2], ql_[3], sQl + aoff);
            #pragma unroll
            for (int ng = 0; ng < 4; ng++) {
                uint32_t boff = (uint32_t)(ng * 16 + lrow) * FSTR + lhalf + kk * 32;
                uint32_t kh_[4], kl_[4];
                ldsm_x4(kh_[0], kh_[1], kh_[2], kh_[3], sKh + boff);
                ldsm_x4(kl_[0], kl_[1], kl_[2], kl_[3], sKl + boff);
                mma16816(sac[2 * ng],     qh_, kh_[0], kh_[2]);
                mma16816(sac[2 * ng],     ql_, kh_[0], kh_[2]);
                mma16816(sac[2 * ng],     qh_, kl_[0], kl_[2]);
                mma16816(sac[2 * ng + 1], qh_, kh_[1], kh_[3]);
                mma16816(sac[2 * ng + 1], ql_, kh_[1], kh_[3]);
                mma16816(sac[2 * ng + 1], qh_, kl_[1], kl_[3]);
            }
        }

        // ---- causal mask on diagonal tile ----
        if (kt == qt) {
            #pragma unroll
            for (int nt = 0; nt < 8; nt++) {
                int c = nt * 8 + ql2;
                if (c > row_loc0)     sac[nt][0] = -CUDART_INF_F;
                if (c + 1 > row_loc0) sac[nt][1] = -CUDART_INF_F;
                if (c > row_loc0 + 8)     sac[nt][2] = -CUDART_INF_F;
                if (c + 1 > row_loc0 + 8) sac[nt][3] = -CUDART_INF_F;
            }
        }

        // ---- online softmax ----
        float mx0 = -CUDART_INF_F, mx1 = -CUDART_INF_F;
        #pragma unroll
        for (int nt = 0; nt < 8; nt++) {
            mx0 = fmaxf(mx0, fmaxf(sac[nt][0], sac[nt][1]));
            mx1 = fmaxf(mx1, fmaxf(sac[nt][2], sac[nt][3]));
        }
        mx0 = fmaxf(mx0, __shfl_xor_sync(0xffffffffu, mx0, 1));
        mx0 = fmaxf(mx0, __shfl_xor_sync(0xffffffffu, mx0, 2));
        mx1 = fmaxf(mx1, __shfl_xor_sync(0xffffffffu, mx1, 1));
        mx1 = fmaxf(mx1, __shfl_xor_sync(0xffffffffu, mx1, 2));

        float mn0 = fmaxf(m0, mx0), mn1 = fmaxf(m1, mx1);
        float cr0 = __expf(m0 - mn0), cr1 = __expf(m1 - mn1);
        m0 = mn0; m1 = mn1;

        float ls0 = 0.f, ls1 = 0.f;
        #pragma unroll
        for (int nt = 0; nt < 8; nt++) {
            float p0 = __expf(sac[nt][0] - m0);
            float p1 = __expf(sac[nt][1] - m0);
            float p2 = __expf(sac[nt][2] - m1);
            float p3 = __expf(sac[nt][3] - m1);
            sac[nt][0] = p0; sac[nt][1] = p1; sac[nt][2] = p2; sac[nt][3] = p3;
            ls0 += p0 + p1;
            ls1 += p2 + p3;
        }
        ls0 += __shfl_xor_sync(0xffffffffu, ls0, 1);
        ls0 += __shfl_xor_sync(0xffffffffu, ls0, 2);
        ls1 += __shfl_xor_sync(0xffffffffu, ls1, 1);
        ls1 += __shfl_xor_sync(0xffffffffu, ls1, 2);
        l0 = l0 * cr0 + ls0;
        l1 = l1 * cr1 + ls1;

        #pragma unroll
        for (int nt = 0; nt < 8; nt++) {
            oacc[nt][0] *= cr0; oacc[nt][1] *= cr0;
            oacc[nt][2] *= cr1; oacc[nt][3] *= cr1;
        }

        // ---- O += P @ V (bf16x3, P from registers) ----
        #pragma unroll
        for (int kk = 0; kk < 4; kk++) {
            uint32_t ph_[4], pl_[4];
            {
                uint32_t h0, lo0, h1, lo1, h2, lo2, h3, lo3;
                split2(sac[2 * kk][0],     sac[2 * kk][1],     h0, lo0);
                split2(sac[2 * kk][2],     sac[2 * kk][3],     h1, lo1);
                split2(sac[2 * kk + 1][0], sac[2 * kk + 1][1], h2, lo2);
                split2(sac[2 * kk + 1][2], sac[2 * kk + 1][3], h3, lo3);
                ph_[0] = h0; ph_[1] = h1; ph_[2] = h2; ph_[3] = h3;
                pl_[0] = lo0; pl_[1] = lo1; pl_[2] = lo2; pl_[3] = lo3;
            }
            #pragma unroll
            for (int ng = 0; ng < 4; ng++) {
                uint32_t voff = (uint32_t)(kk * 16 + lrow) * FSTR + ng * 32 + lhalf;
                uint32_t vh_[4], vl_[4];
                ldsm_x4_t(vh_[0], vh_[1], vh_[2], vh_[3], sVh + voff);
                ldsm_x4_t(vl_[0], vl_[1], vl_[2], vl_[3], sVl + voff);
                mma16816(oacc[2 * ng],     ph_, vh_[0], vh_[1]);
                mma16816(oacc[2 * ng],     pl_, vh_[0], vh_[1]);
                mma16816(oacc[2 * ng],     ph_, vl_[0], vl_[1]);
                mma16816(oacc[2 * ng + 1], ph_, vh_[2], vh_[3]);
                mma16816(oacc[2 * ng + 1], pl_, vh_[2], vh_[3]);
                mma16816(oacc[2 * ng + 1], ph_, vl_[2], vl_[3]);
            }
        }
        __syncthreads();
    }

    // ---- epilogue: normalize, split, store bf16 hi/lo ----
    const float inv0 = 1.0f / l0, inv1 = 1.0f / l1;
    const size_t orow0 = base + (size_t)(qt * 64 + w * 16 + qr) * DD;
    const size_t orow1 = orow0 + 8 * DD;
    #pragma unroll
    for (int nt = 0; nt < 8; nt++) {
        int d = nt * 8 + ql2;
        uint32_t h0, lo0, h1, lo1;
        split2(oacc[nt][0] * inv0, oacc[nt][1] * inv0, h0, lo0);
        split2(oacc[nt][2] * inv1, oacc[nt][3] * inv1, h1, lo1);
        *(uint32_t*)(Oh + orow0 + d) = h0;
        *(uint32_t*)(Ol + orow0 + d) = lo0;
        *(uint32_t*)(Oh + orow1 + d) = h1;
        *(uint32_t*)(Ol + orow1 + d) = lo1;
    }
}

// ============================================================
// Launch
// ============================================================
extern "C" void kernel_launch(void* const* d_in, const int* in_sizes, int n_in,
                              void* d_out, int out_size)
{
    const float* x  = (const float*)d_in[0];
    const float* Wq = (const float*)d_in[1];
    const float* Wk = (const float*)d_in[2];
    const float* Wv = (const float*)d_in[3];
    const float* Wo = (const float*)d_in[4];
    const float* bo = (const float*)d_in[5];
    float* out = (float*)d_out;

    bf16 *xh, *xl, *qh, *ql, *kh, *kl, *vh, *vl;
    bf16 *wqh, *wql, *wkh, *wkl, *wvh, *wvl, *woh, *wol;
    cudaGetSymbolAddress((void**)&xh, g_xh);
    cudaGetSymbolAddress((void**)&xl, g_xl);
    cudaGetSymbolAddress((void**)&qh, g_qh);
    cudaGetSymbolAddress((void**)&ql, g_ql);
    cudaGetSymbolAddress((void**)&kh, g_kh);
    cudaGetSymbolAddress((void**)&kl, g_kl);
    cudaGetSymbolAddress((void**)&vh, g_vh);
    cudaGetSymbolAddress((void**)&vl, g_vl);
    cudaGetSymbolAddress((void**)&wqh, g_wqh);
    cudaGetSymbolAddress((void**)&wql, g_wql);
    cudaGetSymbolAddress((void**)&wkh, g_wkh);
    cudaGetSymbolAddress((void**)&wkl, g_wkl);
    cudaGetSymbolAddress((void**)&wvh, g_wvh);
    cudaGetSymbolAddress((void**)&wvl, g_wvl);
    cudaGetSymbolAddress((void**)&woh, g_woh);
    cudaGetSymbolAddress((void**)&wol, g_wol);

    // 1. split x
    const int n4 = MTOK * DD / 4;
    split_kernel<<<n4 / 256, 256>>>(x, xh, xl, n4);

    // 2. transpose+split weights
    dim3 tgrid(DD / 32, DD / 32), tblk(32, 8);
    transpose_split_kernel<<<tgrid, tblk>>>(Wq, wqh, wql);
    transpose_split_kernel<<<tgrid, tblk>>>(Wk, wkh, wkl);
    transpose_split_kernel<<<tgrid, tblk>>>(Wv, wvh, wvl);
    transpose_split_kernel<<<tgrid, tblk>>>(Wo, woh, wol);

    // 3. QKV projections -> split bf16 output (Q pre-scaled 1/8, exact)
    cudaFuncSetAttribute(gemm_mma_kernel,
                         cudaFuncAttributeMaxDynamicSharedMemorySize, GSMEM);
    dim3 ggrid(DD / 128, MTOK / 128);
    gemm_mma_kernel<<<ggrid, 256, GSMEM>>>(xh, xl, wqh, wql, nullptr,
                                           nullptr, qh, ql, 0.125f);
    gemm_mma_kernel<<<ggrid, 256, GSMEM>>>(xh, xl, wkh, wkl, nullptr,
                                           nullptr, kh, kl, 1.0f);
    gemm_mma_kernel<<<ggrid, 256, GSMEM>>>(xh, xl, wvh, wvl, nullptr,
                                           nullptr, vh, vl, 1.0f);

    // 4. flash attention on tensor cores; writes hi/lo into xh/xl
    cudaFuncSetAttribute(flash_mma_kernel,
                         cudaFuncAttributeMaxDynamicSharedMemorySize, FSMEM);
    flash_mma_kernel<<<dim3(SS / 64, HH, BB), 128, FSMEM>>>(
        qh, ql, kh, kl, vh, vl, xh, xl);

    // 5. output projection (+bias), fp32 out
    gemm_mma_kernel<<<ggrid, 256, GSMEM>>>(xh, xl, woh, wol, bo,
                                           out, nullptr, nullptr, 1.0f);
}

// round 5
// speedup vs baseline: 2.6560x; 1.0587x over previous
#include <cuda_runtime.h>
#include <cuda_bf16.h>
#include <math_constants.h>
#include <cstdint>

// Problem constants
#define BB 4
#define SS 2048
#define DD 1024
#define HH 16
#define HDIM 64
#define MTOK (BB * SS)   // 8192
#define GK DD            // GEMM K = 1024

typedef __nv_bfloat16 bf16;

// ---------------- scratch (__device__ globals; allocation-free rule) -------
__device__ bf16 g_xh[MTOK * DD], g_xl[MTOK * DD];
__device__ bf16 g_qkvh[3 * MTOK * DD], g_qkvl[3 * MTOK * DD];   // Q|K|V segments
__device__ bf16 g_wqkvh[3 * DD * DD], g_wqkvl[3 * DD * DD];     // Wq|Wk|Wv (transposed)
__device__ bf16 g_woh[DD * DD], g_wol[DD * DD];

// ---------------- helpers (plain sm_90-era PTX only) ------------------------
__device__ __forceinline__ uint32_t smem_u32(const void* p) {
    uint32_t a;
    asm("{ .reg .u64 t; cvta.to.shared.u64 t, %1; cvt.u32.u64 %0, t; }"
        : "=r"(a) : "l"(p));
    return a;
}
__device__ __forceinline__ void ldsm_x4(uint32_t& r0, uint32_t& r1,
                                        uint32_t& r2, uint32_t& r3, uint32_t addr) {
    asm volatile("ldmatrix.sync.aligned.m8n8.x4.shared.b16 {%0,%1,%2,%3}, [%4];"
                 : "=r"(r0), "=r"(r1), "=r"(r2), "=r"(r3) : "r"(addr));
}
__device__ __forceinline__ void ldsm_x4_t(uint32_t& r0, uint32_t& r1,
                                          uint32_t& r2, uint32_t& r3, uint32_t addr) {
    asm volatile("ldmatrix.sync.aligned.m8n8.x4.trans.shared.b16 {%0,%1,%2,%3}, [%4];"
                 : "=r"(r0), "=r"(r1), "=r"(r2), "=r"(r3) : "r"(addr));
}
__device__ __forceinline__ void mma16816(float* c, const uint32_t* a,
                                         uint32_t b0, uint32_t b1) {
    asm volatile(
        "mma.sync.aligned.m16n8k16.row.col.f32.bf16.bf16.f32 "
        "{%0,%1,%2,%3}, {%4,%5,%6,%7}, {%8,%9}, {%0,%1,%2,%3};"
        : "+f"(c[0]), "+f"(c[1]), "+f"(c[2]), "+f"(c[3])
        : "r"(a[0]), "r"(a[1]), "r"(a[2]), "r"(a[3]), "r"(b0), "r"(b1));
}
#define CP_ASYNC16(saddr, gaddr) \
    asm volatile("cp.async.cg.shared.global [%0], [%1], 16;" :: "r"(saddr), "l"(gaddr))
#define CP_COMMIT() asm volatile("cp.async.commit_group;" ::: "memory")
#define CP_WAIT(n)  asm volatile("cp.async.wait_group %0;" :: "n"(n) : "memory")

__device__ __forceinline__ uint32_t pack2bf(float a, float b) {
    __nv_bfloat162 t = __floats2bfloat162_rn(a, b);
    return *reinterpret_cast<uint32_t*>(&t);
}
__device__ __forceinline__ void split2(float a, float b, uint32_t& hi, uint32_t& lo) {
    bf16 ha = __float2bfloat16(a), hb = __float2bfloat16(b);
    hi = pack2bf(__bfloat162float(ha), __bfloat162float(hb));
    lo = pack2bf(a - __bfloat162float(ha), b - __bfloat162float(hb));
}

// ============================================================
// split: fp32 -> bf16 hi + bf16 lo (residual)   [for input x]
// ============================================================
__global__ __launch_bounds__(256) void split_kernel(
    const float* __restrict__ in, bf16* __restrict__ hi,
    bf16* __restrict__ lo, int n4)
{
    int i = blockIdx.x * blockDim.x + threadIdx.x;
    if (i >= n4) return;
    float4 v = reinterpret_cast<const float4*>(in)[i];
    uint32_t h0, l0, h1, l1;
    split2(v.x, v.y, h0, l0);
    split2(v.z, v.w, h1, l1);
    uint2 hh, ll;
    hh.x = h0; hh.y = h1;
    ll.x = l0; ll.y = l1;
    reinterpret_cast<uint2*>(hi)[i] = hh;
    reinterpret_cast<uint2*>(lo)[i] = ll;
}

// ============================================================
// fused transpose + split of all 4 weights (z = which weight)
// W[K,N] fp32 -> Wt_hi/Wt_lo[N,K] bf16
// ============================================================
__global__ __launch_bounds__(256) void transpose_split4_kernel(
    const float* __restrict__ Wq, const float* __restrict__ Wk,
    const float* __restrict__ Wv, const float* __restrict__ Wo,
    bf16* __restrict__ Wqkvh, bf16* __restrict__ Wqkvl,
    bf16* __restrict__ Woh, bf16* __restrict__ Wol)
{
    __shared__ float t[32][33];
    const int z = blockIdx.z;
    const float* W = (z == 0) ? Wq : (z == 1) ? Wk : (z == 2) ? Wv : Wo;
    bf16* Th = (z < 3) ? Wqkvh + (size_t)z * DD * DD : Woh;
    bf16* Tl = (z < 3) ? Wqkvl + (size_t)z * DD * DD : Wol;

    const int bx = blockIdx.x, by = blockIdx.y;
    const int x = threadIdx.x, y = threadIdx.y;  // 32 x 8
    #pragma unroll
    for (int i = 0; i < 4; i++)
        t[y + 8 * i][x] = W[(size_t)(by * 32 + y + 8 * i) * DD + bx * 32 + x];
    __syncthreads();
    #pragma unroll
    for (int i = 0; i < 4; i++) {
        float v = t[x][y + 8 * i];
        bf16 h = __float2bfloat16(v);
        bf16 l = __float2bfloat16(v - __bfloat162float(h));
        size_t off = (size_t)(bx * 32 + y + 8 * i) * DD + by * 32 + x;
        Th[off] = h;
        Tl[off] = l;
    }
}

// ============================================================
// bf16x3 GEMM on mma.sync. A[M,1024] @ B[N,1024]^T.
// Fused-QKV mode (Cf==null): bc>>3 selects Q/K/V output segment,
// Q cols scaled by qscale. fp32 mode (Cf!=null): +bias, out fp32.
// 2 CTAs/SM via reg cap.
// ============================================================
#define CHK 32
#define ASTRB 80
#define TILEB (128 * ASTRB)
#define STAGEB (4 * TILEB)
#define GSMEM (2 * STAGEB)       // 81920 B

__global__ __launch_bounds__(256, 2) void gemm_mma_kernel(
    const bf16* __restrict__ Ah, const bf16* __restrict__ Al,
    const bf16* __restrict__ Bh, const bf16* __restrict__ Bl,
    const float* __restrict__ bias, float* __restrict__ Cf,
    bf16* __restrict__ Ch, bf16* __restrict__ Cl, float qscale)
{
    extern __shared__ char dsm[];
    const uint32_t sbase = smem_u32(dsm);

    const int tid = threadIdx.x;
    const int lane = tid & 31;
    const int wid = tid >> 5;
    const int warp_m = wid & 3;
    const int warp_n = wid >> 2;
    const int br = blockIdx.y, bc = blockIdx.x;

    const bf16* gsrc[4] = {
        Ah + (size_t)(br * 128) * GK, Al + (size_t)(br * 128) * GK,
        Bh + (size_t)(bc * 128) * GK, Bl + (size_t)(bc * 128) * GK
    };

    auto load_stage = [&](int k0, int st) {
        const uint32_t s0 = sbase + st * STAGEB;
        #pragma unroll
        for (int p = 0; p < 8; p++) {
            int idx = tid + p * 256;
            int t   = idx >> 9;
            int rem = idx & 511;
            int row = rem >> 2;
            int ch  = rem & 3;
            uint32_t sa = s0 + t * TILEB + row * ASTRB + ch * 16;
            const bf16* g = gsrc[t] + (size_t)row * GK + k0 + ch * 8;
            CP_ASYNC16(sa, g);
        }
        CP_COMMIT();
    };

    float acc[2][8][4];
    #pragma unroll
    for (int mt = 0; mt < 2; mt++)
        #pragma unroll
        for (int nt = 0; nt < 8; nt++)
            #pragma unroll
            for (int j = 0; j < 4; j++) acc[mt][nt][j] = 0.f;

    load_stage(0, 0);

    const int NC = GK / CHK;
    for (int c = 0; c < NC; c++) {
        if (c + 1 < NC) {
            load_stage((c + 1) * CHK, (c + 1) & 1);
            CP_WAIT(1);
        } else {
            CP_WAIT(0);
        }
        __syncthreads();

        const uint32_t s0  = sbase + (c & 1) * STAGEB;
        const uint32_t sAh = s0, sAl = s0 + TILEB;
        const uint32_t sBh = s0 + 2 * TILEB, sBl = s0 + 3 * TILEB;
        const int lrow = lane & 15;
        const int lsel = (lane >> 4) * 16;

        #pragma unroll
        for (int kk = 0; kk < 2; kk++) {
            const int lcol = lsel + kk * 32;
            uint32_t ah[2][4], al[2][4];
            #pragma unroll
            for (int mt = 0; mt < 2; mt++) {
                uint32_t off = (uint32_t)(warp_m * 32 + mt * 16 + lrow) * ASTRB + lcol;
                ldsm_x4(ah[mt][0], ah[mt][1], ah[mt][2], ah[mt][3], sAh + off);
                ldsm_x4(al[mt][0], al[mt][1], al[mt][2], al[mt][3], sAl + off);
            }
            // interleave B-frag load + consume (keeps live B regs to 8)
            #pragma unroll
            for (int ng = 0; ng < 4; ng++) {
                uint32_t off = (uint32_t)(warp_n * 64 + ng * 16 + lrow) * ASTRB + lcol;
                uint32_t bh[4], bl[4];
                ldsm_x4(bh[0], bh[1], bh[2], bh[3], sBh + off);
                ldsm_x4(bl[0], bl[1], bl[2], bl[3], sBl + off);
                #pragma unroll
                for (int mt = 0; mt < 2; mt++) {
                    mma16816(acc[mt][2 * ng],     ah[mt], bh[0], bh[2]);
                    mma16816(acc[mt][2 * ng],     al[mt], bh[0], bh[2]);
                    mma16816(acc[mt][2 * ng],     ah[mt], bl[0], bl[2]);
                    mma16816(acc[mt][2 * ng + 1], ah[mt], bh[1], bh[3]);
                    mma16816(acc[mt][2 * ng + 1], al[mt], bh[1], bh[3]);
                    mma16816(acc[mt][2 * ng + 1], ah[mt], bl[1], bl[3]);
                }
            }
        }
        __syncthreads();
    }

    const int row0 = br * 128 + warp_m * 32;
    const int col0 = (bc & 7) * 128 + warp_n * 64;   // col within DD
    const int qr = lane >> 2;
    const int qc = (lane & 3) * 2;

    if (Cf) {
        #pragma unroll
        for (int mt = 0; mt < 2; mt++) {
            #pragma unroll
            for (int nt = 0; nt < 8; nt++) {
                int col = col0 + nt * 8 + qc;
                float b0 = 0.f, b1 = 0.f;
                if (bias) { b0 = bias[col]; b1 = bias[col + 1]; }
                size_t o0 = (size_t)(row0 + mt * 16 + qr) * DD + col;
                size_t o1 = o0 + 8 * DD;
                float2 w0, w1;
                w0.x = acc[mt][nt][0] + b0; w0.y = acc[mt][nt][1] + b1;
                w1.x = acc[mt][nt][2] + b0; w1.y = acc[mt][nt][3] + b1;
                *(float2*)(Cf + o0) = w0;
                *(float2*)(Cf + o1) = w1;
            }
        }
    } else {
        const int sel = bc >> 3;                      // 0=Q 1=K 2=V
        const float scale = (sel == 0) ? qscale : 1.0f;
        bf16* Chs = Ch + (size_t)sel * MTOK * DD;
        bf16* Cls = Cl + (size_t)sel * MTOK * DD;
        #pragma unroll
        for (int mt = 0; mt < 2; mt++) {
            #pragma unroll
            for (int nt = 0; nt < 8; nt++) {
                int col = col0 + nt * 8 + qc;
                size_t o0 = (size_t)(row0 + mt * 16 + qr) * DD + col;
                size_t o1 = o0 + 8 * DD;
                uint32_t h0, l0, h1, l1;
                split2(acc[mt][nt][0] * scale, acc[mt][nt][1] * scale, h0, l0);
                split2(acc[mt][nt][2] * scale, acc[mt][nt][3] * scale, h1, l1);
                *(uint32_t*)(Chs + o0) = h0;
                *(uint32_t*)(Cls + o0) = l0;
                *(uint32_t*)(Chs + o1) = h1;
                *(uint32_t*)(Cls + o1) = l1;
            }
        }
    }
}

// ============================================================
// Flash attention (causal) on mma.sync, bf16x3, base-2 softmax.
// Q pre-scaled by 0.125*log2(e) in Q-projection epilogue.
// CTA: 128 threads / 4 warps; tile 64 q-rows x 64 kv.
// ============================================================
#define FSTR 144
#define FTILE (64 * FSTR)
#define FSTAGEB (4 * FTILE)
#define FSMEM (2 * FTILE + 2 * FSTAGEB)  // 92160 B

__global__ __launch_bounds__(128) void flash_mma_kernel(
    const bf16* __restrict__ Qh, const bf16* __restrict__ Ql,
    const bf16* __restrict__ Kh, const bf16* __restrict__ Kl,
    const bf16* __restrict__ Vh, const bf16* __restrict__ Vl,
    bf16* __restrict__ Oh, bf16* __restrict__ Ol)
{
    extern __shared__ char dsm[];
    const uint32_t sbase = smem_u32(dsm);

    const int tid = threadIdx.x;
    const int lane = tid & 31;
    const int w = tid >> 5;
    const int qt = blockIdx.x, h = blockIdx.y, b = blockIdx.z;

    const size_t base = ((size_t)b * SS) * DD + (size_t)h * HDIM;
    const bf16* gq[2] = {Qh + base + (size_t)(qt * 64) * DD,
                         Ql + base + (size_t)(qt * 64) * DD};

    {
        #pragma unroll
        for (int p = 0; p < 8; p++) {
            int i = tid + p * 128;
            int t = i >> 9;
            int rem = i & 511;
            int row = rem >> 3;
            int ch = rem & 7;
            CP_ASYNC16(sbase + t * FTILE + row * FSTR + ch * 16,
                       gq[t] + (size_t)row * DD + ch * 8);
        }
    }

    const bf16* gkv[4] = {Kh + base, Kl + base, Vh + base, Vl + base};
    auto load_kv = [&](int kt, int st) {
        const uint32_t s0 = sbase + 2 * FTILE + st * FSTAGEB;
        const size_t roff = (size_t)(kt * 64) * DD;
        #pragma unroll
        for (int p = 0; p < 16; p++) {
            int i = tid + p * 128;
            int t = i >> 9;
            int rem = i & 511;
            int row = rem >> 3;
            int ch = rem & 7;
            CP_ASYNC16(s0 + t * FTILE + row * FSTR + ch * 16,
                       gkv[t] + roff + (size_t)row * DD + ch * 8);
        }
        CP_COMMIT();
    };

    load_kv(0, 0);

    const int qr = lane >> 2;
    const int ql2 = (lane & 3) * 2;
    const int lrow = lane & 15;
    const int lhalf = (lane >> 4) * 16;

    float oacc[8][4];
    #pragma unroll
    for (int nt = 0; nt < 8; nt++)
        #pragma unroll
        for (int j = 0; j < 4; j++) oacc[nt][j] = 0.f;
    float m0 = -CUDART_INF_F, m1 = -CUDART_INF_F;
    float l0 = 0.f, l1 = 0.f;

    const int row_loc0 = w * 16 + qr;
    const int nk = qt + 1;

    for (int kt = 0; kt < nk; kt++) {
        if (kt + 1 < nk) {
            load_kv(kt + 1, (kt + 1) & 1);
            CP_WAIT(1);
        } else {
            CP_WAIT(0);
        }
        __syncthreads();

        const uint32_t s0  = sbase + 2 * FTILE + (kt & 1) * FSTAGEB;
        const uint32_t sQh = sbase, sQl = sbase + FTILE;
        const uint32_t sKh = s0,            sKl = s0 + FTILE;
        const uint32_t sVh = s0 + 2 * FTILE, sVl = s0 + 3 * FTILE;

        // ---- S = Q @ K^T (bf16x3), S in log2 units ----
        float sac[8][4];
        #pragma unroll
        for (int nt = 0; nt < 8; nt++)
            #pragma unroll
            for (int j = 0; j < 4; j++) sac[nt][j] = 0.f;

        #pragma unroll
        for (int kk = 0; kk < 4; kk++) {
            uint32_t aoff = (uint32_t)(w * 16 + lrow) * FSTR + lhalf + kk * 32;
            uint32_t qh_[4], ql_[4];
            ldsm_x4(qh_[0], qh_[1], qh_[2], qh_[3], sQh + aoff);
            ldsm_x4(ql_[0], ql_[1], ql_[2], ql_[3], sQl + aoff);
            #pragma unroll
            for (int ng = 0; ng < 4; ng++) {
                uint32_t boff = (uint32_t)(ng * 16 + lrow) * FSTR + lhalf + kk * 32;
                uint32_t kh_[4], kl_[4];
                ldsm_x4(kh_[0], kh_[1], kh_[2], kh_[3], sKh + boff);
                ldsm_x4(kl_[0], kl_[1], kl_[2], kl_[3], sKl + boff);
                mma16816(sac[2 * ng],     qh_, kh_[0], kh_[2]);
                mma16816(sac[2 * ng],     ql_, kh_[0], kh_[2]);
                mma16816(sac[2 * ng],     qh_, kl_[0], kl_[2]);
                mma16816(sac[2 * ng + 1], qh_, kh_[1], kh_[3]);
                mma16816(sac[2 * ng + 1], ql_, kh_[1], kh_[3]);
                mma16816(sac[2 * ng + 1], qh_, kl_[1], kl_[3]);
            }
        }

        if (kt == qt) {
            #pragma unroll
            for (int nt = 0; nt < 8; nt++) {
                int c = nt * 8 + ql2;
                if (c > row_loc0)     sac[nt][0] = -CUDART_INF_F;
                if (c + 1 > row_loc0) sac[nt][1] = -CUDART_INF_F;
                if (c > row_loc0 + 8)     sac[nt][2] = -CUDART_INF_F;
                if (c + 1 > row_loc0 + 8) sac[nt][3] = -CUDART_INF_F;
            }
        }

        // ---- online softmax (base 2) ----
        float mx0 = -CUDART_INF_F, mx1 = -CUDART_INF_F;
        #pragma unroll
        for (int nt = 0; nt < 8; nt++) {
            mx0 = fmaxf(mx0, fmaxf(sac[nt][0], sac[nt][1]));
            mx1 = fmaxf(mx1, fmaxf(sac[nt][2], sac[nt][3]));
        }
        mx0 = fmaxf(mx0, __shfl_xor_sync(0xffffffffu, mx0, 1));
        mx0 = fmaxf(mx0, __shfl_xor_sync(0xffffffffu, mx0, 2));
        mx1 = fmaxf(mx1, __shfl_xor_sync(0xffffffffu, mx1, 1));
        mx1 = fmaxf(mx1, __shfl_xor_sync(0xffffffffu, mx1, 2));

        float mn0 = fmaxf(m0, mx0), mn1 = fmaxf(m1, mx1);
        float cr0 = exp2f(m0 - mn0), cr1 = exp2f(m1 - mn1);
        m0 = mn0; m1 = mn1;

        float ls0 = 0.f, ls1 = 0.f;
        #pragma unroll
        for (int nt = 0; nt < 8; nt++) {
            float p0 = exp2f(sac[nt][0] - m0);
            float p1 = exp2f(sac[nt][1] - m0);
            float p2 = exp2f(sac[nt][2] - m1);
            float p3 = exp2f(sac[nt][3] - m1);
            sac[nt][0] = p0; sac[nt][1] = p1; sac[nt][2] = p2; sac[nt][3] = p3;
            ls0 += p0 + p1;
            ls1 += p2 + p3;
        }
        ls0 += __shfl_xor_sync(0xffffffffu, ls0, 1);
        ls0 += __shfl_xor_sync(0xffffffffu, ls0, 2);
        ls1 += __shfl_xor_sync(0xffffffffu, ls1, 1);
        ls1 += __shfl_xor_sync(0xffffffffu, ls1, 2);
        l0 = l0 * cr0 + ls0;
        l1 = l1 * cr1 + ls1;

        #pragma unroll
        for (int nt = 0; nt < 8; nt++) {
            oacc[nt][0] *= cr0; oacc[nt][1] *= cr0;
            oacc[nt][2] *= cr1; oacc[nt][3] *= cr1;
        }

        // ---- O += P @ V (bf16x3, P from registers) ----
        #pragma unroll
        for (int kk = 0; kk < 4; kk++) {
            uint32_t ph_[4], pl_[4];
            {
                uint32_t h0, lo0, h1, lo1, h2, lo2, h3, lo3;
                split2(sac[2 * kk][0],     sac[2 * kk][1],     h0, lo0);
                split2(sac[2 * kk][2],     sac[2 * kk][3],     h1, lo1);
                split2(sac[2 * kk + 1][0], sac[2 * kk + 1][1], h2, lo2);
                split2(sac[2 * kk + 1][2], sac[2 * kk + 1][3], h3, lo3);
                ph_[0] = h0; ph_[1] = h1; ph_[2] = h2; ph_[3] = h3;
                pl_[0] = lo0; pl_[1] = lo1; pl_[2] = lo2; pl_[3] = lo3;
            }
            #pragma unroll
            for (int ng = 0; ng < 4; ng++) {
                uint32_t voff = (uint32_t)(kk * 16 + lrow) * FSTR + ng * 32 + lhalf;
                uint32_t vh_[4], vl_[4];
                ldsm_x4_t(vh_[0], vh_[1], vh_[2], vh_[3], sVh + voff);
                ldsm_x4_t(vl_[0], vl_[1], vl_[2], vl_[3], sVl + voff);
                mma16816(oacc[2 * ng],     ph_, vh_[0], vh_[1]);
                mma16816(oacc[2 * ng],     pl_, vh_[0], vh_[1]);
                mma16816(oacc[2 * ng],     ph_, vl_[0], vl_[1]);
                mma16816(oacc[2 * ng + 1], ph_, vh_[2], vh_[3]);
                mma16816(oacc[2 * ng + 1], pl_, vh_[2], vh_[3]);
                mma16816(oacc[2 * ng + 1], ph_, vl_[2], vl_[3]);
            }
        }
        __syncthreads();
    }

    // ---- epilogue: normalize, split, store bf16 hi/lo ----
    const float inv0 = 1.0f / l0, inv1 = 1.0f / l1;
    const size_t orow0 = base + (size_t)(qt * 64 + w * 16 + qr) * DD;
    const size_t orow1 = orow0 + 8 * DD;
    #pragma unroll
    for (int nt = 0; nt < 8; nt++) {
        int d = nt * 8 + ql2;
        uint32_t h0, lo0, h1, lo1;
        split2(oacc[nt][0] * inv0, oacc[nt][1] * inv0, h0, lo0);
        split2(oacc[nt][2] * inv1, oacc[nt][3] * inv1, h1, lo1);
        *(uint32_t*)(Oh + orow0 + d) = h0;
        *(uint32_t*)(Ol + orow0 + d) = lo0;
        *(uint32_t*)(Oh + orow1 + d) = h1;
        *(uint32_t*)(Ol + orow1 + d) = lo1;
    }
}

// ============================================================
// Launch
// ============================================================
extern "C" void kernel_launch(void* const* d_in, const int* in_sizes, int n_in,
                              void* d_out, int out_size)
{
    const float* x  = (const float*)d_in[0];
    const float* Wq = (const float*)d_in[1];
    const float* Wk = (const float*)d_in[2];
    const float* Wv = (const float*)d_in[3];
    const float* Wo = (const float*)d_in[4];
    const float* bo = (const float*)d_in[5];
    float* out = (float*)d_out;

    bf16 *xh, *xl, *qkvh, *qkvl, *wqkvh, *wqkvl, *woh, *wol;
    cudaGetSymbolAddress((void**)&xh, g_xh);
    cudaGetSymbolAddress((void**)&xl, g_xl);
    cudaGetSymbolAddress((void**)&qkvh, g_qkvh);
    cudaGetSymbolAddress((void**)&qkvl, g_qkvl);
    cudaGetSymbolAddress((void**)&wqkvh, g_wqkvh);
    cudaGetSymbolAddress((void**)&wqkvl, g_wqkvl);
    cudaGetSymbolAddress((void**)&woh, g_woh);
    cudaGetSymbolAddress((void**)&wol, g_wol);

    // 1. split x
    const int n4 = MTOK * DD / 4;
    split_kernel<<<n4 / 256, 256>>>(x, xh, xl, n4);

    // 2. fused transpose+split of all 4 weights
    transpose_split4_kernel<<<dim3(DD / 32, DD / 32, 4), dim3(32, 8)>>>(
        Wq, Wk, Wv, Wo, wqkvh, wqkvl, woh, wol);

    // 3. fused QKV projection (single launch, N=3072)
    //    Q pre-scaled by 1/sqrt(64) * log2(e) for base-2 softmax
    const float qscale = 0.125f * 1.4426950408889634f;
    cudaFuncSetAttribute(gemm_mma_kernel,
                         cudaFuncAttributeMaxDynamicSharedMemorySize, GSMEM);
    gemm_mma_kernel<<<dim3(24, MTOK / 128), 256, GSMEM>>>(
        xh, xl, wqkvh, wqkvl, nullptr, nullptr, qkvh, qkvl, qscale);

    // 4. flash attention; writes hi/lo into xh/xl
    const size_t seg = (size_t)MTOK * DD;
    cudaFuncSetAttribute(flash_mma_kernel,
                         cudaFuncAttributeMaxDynamicSharedMemorySize, FSMEM);
    flash_mma_kernel<<<dim3(SS / 64, HH, BB), 128, FSMEM>>>(
        qkvh, qkvl, qkvh + seg, qkvl + seg, qkvh + 2 * seg, qkvl + 2 * seg,
        xh, xl);

    // 5. output projection (+bias), fp32 out
    gemm_mma_kernel<<<dim3(8, MTOK / 128), 256, GSMEM>>>(
        xh, xl, woh, wol, bo, out, nullptr, nullptr, 1.0f);
}

// round 6
// speedup vs baseline: 2.7814x; 1.0472x over previous
#include <cuda_runtime.h>
#include <cuda_bf16.h>
#include <math_constants.h>
#include <cstdint>

// Problem constants
#define BB 4
#define SS 2048
#define DD 1024
#define HH 16
#define HDIM 64
#define MTOK (BB * SS)   // 8192
#define GK DD            // GEMM K = 1024

typedef __nv_bfloat16 bf16;

// ---------------- scratch (__device__ globals; allocation-free rule) -------
__device__ bf16 g_xh[MTOK * DD], g_xl[MTOK * DD];
__device__ bf16 g_qkvh[3 * MTOK * DD], g_qkvl[3 * MTOK * DD];   // Q|K|V segments
__device__ bf16 g_wqkvh[3 * DD * DD], g_wqkvl[3 * DD * DD];     // Wq|Wk|Wv (transposed)
__device__ bf16 g_woh[DD * DD], g_wol[DD * DD];

// ---------------- helpers (plain sm_90-era PTX only) ------------------------
__device__ __forceinline__ uint32_t smem_u32(const void* p) {
    uint32_t a;
    asm("{ .reg .u64 t; cvta.to.shared.u64 t, %1; cvt.u32.u64 %0, t; }"
        : "=r"(a) : "l"(p));
    return a;
}
__device__ __forceinline__ void ldsm_x4(uint32_t& r0, uint32_t& r1,
                                        uint32_t& r2, uint32_t& r3, uint32_t addr) {
    asm volatile("ldmatrix.sync.aligned.m8n8.x4.shared.b16 {%0,%1,%2,%3}, [%4];"
                 : "=r"(r0), "=r"(r1), "=r"(r2), "=r"(r3) : "r"(addr));
}
__device__ __forceinline__ void ldsm_x4_t(uint32_t& r0, uint32_t& r1,
                                          uint32_t& r2, uint32_t& r3, uint32_t addr) {
    asm volatile("ldmatrix.sync.aligned.m8n8.x4.trans.shared.b16 {%0,%1,%2,%3}, [%4];"
                 : "=r"(r0), "=r"(r1), "=r"(r2), "=r"(r3) : "r"(addr));
}
__device__ __forceinline__ void mma16816(float* c, const uint32_t* a,
                                         uint32_t b0, uint32_t b1) {
    asm volatile(
        "mma.sync.aligned.m16n8k16.row.col.f32.bf16.bf16.f32 "
        "{%0,%1,%2,%3}, {%4,%5,%6,%7}, {%8,%9}, {%0,%1,%2,%3};"
        : "+f"(c[0]), "+f"(c[1]), "+f"(c[2]), "+f"(c[3])
        : "r"(a[0]), "r"(a[1]), "r"(a[2]), "r"(a[3]), "r"(b0), "r"(b1));
}
#define CP_ASYNC16(saddr, gaddr) \
    asm volatile("cp.async.cg.shared.global [%0], [%1], 16;" :: "r"(saddr), "l"(gaddr))
#define CP_COMMIT() asm volatile("cp.async.commit_group;" ::: "memory")
#define CP_WAIT(n)  asm volatile("cp.async.wait_group %0;" :: "n"(n) : "memory")

__device__ __forceinline__ uint32_t pack2bf(float a, float b) {
    __nv_bfloat162 t = __floats2bfloat162_rn(a, b);
    return *reinterpret_cast<uint32_t*>(&t);
}
__device__ __forceinline__ void split2(float a, float b, uint32_t& hi, uint32_t& lo) {
    bf16 ha = __float2bfloat16(a), hb = __float2bfloat16(b);
    hi = pack2bf(__bfloat162float(ha), __bfloat162float(hb));
    lo = pack2bf(a - __bfloat162float(ha), b - __bfloat162float(hb));
}

// ============================================================
// split: fp32 -> bf16 hi + bf16 lo (residual)   [for input x]
// ============================================================
__global__ __launch_bounds__(256) void split_kernel(
    const float* __restrict__ in, bf16* __restrict__ hi,
    bf16* __restrict__ lo, int n4)
{
    int i = blockIdx.x * blockDim.x + threadIdx.x;
    if (i >= n4) return;
    float4 v = reinterpret_cast<const float4*>(in)[i];
    uint32_t h0, l0, h1, l1;
    split2(v.x, v.y, h0, l0);
    split2(v.z, v.w, h1, l1);
    uint2 hh, ll;
    hh.x = h0; hh.y = h1;
    ll.x = l0; ll.y = l1;
    reinterpret_cast<uint2*>(hi)[i] = hh;
    reinterpret_cast<uint2*>(lo)[i] = ll;
}

// ============================================================
// fused transpose + split of all 4 weights (z = which weight)
// ============================================================
__global__ __launch_bounds__(256) void transpose_split4_kernel(
    const float* __restrict__ Wq, const float* __restrict__ Wk,
    const float* __restrict__ Wv, const float* __restrict__ Wo,
    bf16* __restrict__ Wqkvh, bf16* __restrict__ Wqkvl,
    bf16* __restrict__ Woh, bf16* __restrict__ Wol)
{
    __shared__ float t[32][33];
    const int z = blockIdx.z;
    const float* W = (z == 0) ? Wq : (z == 1) ? Wk : (z == 2) ? Wv : Wo;
    bf16* Th = (z < 3) ? Wqkvh + (size_t)z * DD * DD : Woh;
    bf16* Tl = (z < 3) ? Wqkvl + (size_t)z * DD * DD : Wol;

    const int bx = blockIdx.x, by = blockIdx.y;
    const int x = threadIdx.x, y = threadIdx.y;  // 32 x 8
    #pragma unroll
    for (int i = 0; i < 4; i++)
        t[y + 8 * i][x] = W[(size_t)(by * 32 + y + 8 * i) * DD + bx * 32 + x];
    __syncthreads();
    #pragma unroll
    for (int i = 0; i < 4; i++) {
        float v = t[x][y + 8 * i];
        bf16 h = __float2bfloat16(v);
        bf16 l = __float2bfloat16(v - __bfloat162float(h));
        size_t off = (size_t)(bx * 32 + y + 8 * i) * DD + by * 32 + x;
        Th[off] = h;
        Tl[off] = l;
    }
}

// ============================================================
// bf16x3 GEMM on mma.sync (unchanged from R5)
// ============================================================
#define CHK 32
#define ASTRB 80
#define TILEB (128 * ASTRB)
#define STAGEB (4 * TILEB)
#define GSMEM (2 * STAGEB)       // 81920 B

__global__ __launch_bounds__(256, 2) void gemm_mma_kernel(
    const bf16* __restrict__ Ah, const bf16* __restrict__ Al,
    const bf16* __restrict__ Bh, const bf16* __restrict__ Bl,
    const float* __restrict__ bias, float* __restrict__ Cf,
    bf16* __restrict__ Ch, bf16* __restrict__ Cl, float qscale)
{
    extern __shared__ char dsm[];
    const uint32_t sbase = smem_u32(dsm);

    const int tid = threadIdx.x;
    const int lane = tid & 31;
    const int wid = tid >> 5;
    const int warp_m = wid & 3;
    const int warp_n = wid >> 2;
    const int br = blockIdx.y, bc = blockIdx.x;

    const bf16* gsrc[4] = {
        Ah + (size_t)(br * 128) * GK, Al + (size_t)(br * 128) * GK,
        Bh + (size_t)(bc * 128) * GK, Bl + (size_t)(bc * 128) * GK
    };

    auto load_stage = [&](int k0, int st) {
        const uint32_t s0 = sbase + st * STAGEB;
        #pragma unroll
        for (int p = 0; p < 8; p++) {
            int idx = tid + p * 256;
            int t   = idx >> 9;
            int rem = idx & 511;
            int row = rem >> 2;
            int ch  = rem & 3;
            uint32_t sa = s0 + t * TILEB + row * ASTRB + ch * 16;
            const bf16* g = gsrc[t] + (size_t)row * GK + k0 + ch * 8;
            CP_ASYNC16(sa, g);
        }
        CP_COMMIT();
    };

    float acc[2][8][4];
    #pragma unroll
    for (int mt = 0; mt < 2; mt++)
        #pragma unroll
        for (int nt = 0; nt < 8; nt++)
            #pragma unroll
            for (int j = 0; j < 4; j++) acc[mt][nt][j] = 0.f;

    load_stage(0, 0);

    const int NC = GK / CHK;
    for (int c = 0; c < NC; c++) {
        if (c + 1 < NC) {
            load_stage((c + 1) * CHK, (c + 1) & 1);
            CP_WAIT(1);
        } else {
            CP_WAIT(0);
        }
        __syncthreads();

        const uint32_t s0  = sbase + (c & 1) * STAGEB;
        const uint32_t sAh = s0, sAl = s0 + TILEB;
        const uint32_t sBh = s0 + 2 * TILEB, sBl = s0 + 3 * TILEB;
        const int lrow = lane & 15;
        const int lsel = (lane >> 4) * 16;

        #pragma unroll
        for (int kk = 0; kk < 2; kk++) {
            const int lcol = lsel + kk * 32;
            uint32_t ah[2][4], al[2][4];
            #pragma unroll
            for (int mt = 0; mt < 2; mt++) {
                uint32_t off = (uint32_t)(warp_m * 32 + mt * 16 + lrow) * ASTRB + lcol;
                ldsm_x4(ah[mt][0], ah[mt][1], ah[mt][2], ah[mt][3], sAh + off);
                ldsm_x4(al[mt][0], al[mt][1], al[mt][2], al[mt][3], sAl + off);
            }
            #pragma unroll
            for (int ng = 0; ng < 4; ng++) {
                uint32_t off = (uint32_t)(warp_n * 64 + ng * 16 + lrow) * ASTRB + lcol;
                uint32_t bh[4], bl[4];
                ldsm_x4(bh[0], bh[1], bh[2], bh[3], sBh + off);
                ldsm_x4(bl[0], bl[1], bl[2], bl[3], sBl + off);
                #pragma unroll
                for (int mt = 0; mt < 2; mt++) {
                    mma16816(acc[mt][2 * ng],     ah[mt], bh[0], bh[2]);
                    mma16816(acc[mt][2 * ng],     al[mt], bh[0], bh[2]);
                    mma16816(acc[mt][2 * ng],     ah[mt], bl[0], bl[2]);
                    mma16816(acc[mt][2 * ng + 1], ah[mt], bh[1], bh[3]);
                    mma16816(acc[mt][2 * ng + 1], al[mt], bh[1], bh[3]);
                    mma16816(acc[mt][2 * ng + 1], ah[mt], bl[1], bl[3]);
                }
            }
        }
        __syncthreads();
    }

    const int row0 = br * 128 + warp_m * 32;
    const int col0 = (bc & 7) * 128 + warp_n * 64;
    const int qr = lane >> 2;
    const int qc = (lane & 3) * 2;

    if (Cf) {
        #pragma unroll
        for (int mt = 0; mt < 2; mt++) {
            #pragma unroll
            for (int nt = 0; nt < 8; nt++) {
                int col = col0 + nt * 8 + qc;
                float b0 = 0.f, b1 = 0.f;
                if (bias) { b0 = bias[col]; b1 = bias[col + 1]; }
                size_t o0 = (size_t)(row0 + mt * 16 + qr) * DD + col;
                size_t o1 = o0 + 8 * DD;
                float2 w0, w1;
                w0.x = acc[mt][nt][0] + b0; w0.y = acc[mt][nt][1] + b1;
                w1.x = acc[mt][nt][2] + b0; w1.y = acc[mt][nt][3] + b1;
                *(float2*)(Cf + o0) = w0;
                *(float2*)(Cf + o1) = w1;
            }
        }
    } else {
        const int sel = bc >> 3;
        const float scale = (sel == 0) ? qscale : 1.0f;
        bf16* Chs = Ch + (size_t)sel * MTOK * DD;
        bf16* Cls = Cl + (size_t)sel * MTOK * DD;
        #pragma unroll
        for (int mt = 0; mt < 2; mt++) {
            #pragma unroll
            for (int nt = 0; nt < 8; nt++) {
                int col = col0 + nt * 8 + qc;
                size_t o0 = (size_t)(row0 + mt * 16 + qr) * DD + col;
                size_t o1 = o0 + 8 * DD;
                uint32_t h0, l0, h1, l1;
                split2(acc[mt][nt][0] * scale, acc[mt][nt][1] * scale, h0, l0);
                split2(acc[mt][nt][2] * scale, acc[mt][nt][3] * scale, h1, l1);
                *(uint32_t*)(Chs + o0) = h0;
                *(uint32_t*)(Cls + o0) = l0;
                *(uint32_t*)(Chs + o1) = h1;
                *(uint32_t*)(Cls + o1) = l1;
            }
        }
    }
}

// ============================================================
// Flash attention (causal) on mma.sync, bf16x3, base-2 softmax.
// CTA: 256 threads / 8 warps; CTA tile 128 q-rows x 64 kv.
// Each warp owns 16 q-rows. Q pre-scaled by 0.125*log2(e).
// ============================================================
#define FSTR 144
#define FKTILE (64 * FSTR)            // 9216 B  (one 64-row kv tile)
#define FQTILE (128 * FSTR)           // 18432 B (128-row q tile)
#define FSTAGEB (4 * FKTILE)          // Kh,Kl,Vh,Vl = 36864 B
#define FSMEM (2 * FQTILE + 2 * FSTAGEB)  // 110592 B

__global__ __launch_bounds__(256, 2) void flash_mma_kernel(
    const bf16* __restrict__ Qh, const bf16* __restrict__ Ql,
    const bf16* __restrict__ Kh, const bf16* __restrict__ Kl,
    const bf16* __restrict__ Vh, const bf16* __restrict__ Vl,
    bf16* __restrict__ Oh, bf16* __restrict__ Ol)
{
    extern __shared__ char dsm[];
    const uint32_t sbase = smem_u32(dsm);

    const int tid = threadIdx.x;
    const int lane = tid & 31;
    const int w = tid >> 5;                 // 0..7
    const int qt = blockIdx.x, h = blockIdx.y, b = blockIdx.z;

    const size_t base = ((size_t)b * SS) * DD + (size_t)h * HDIM;
    const bf16* gq[2] = {Qh + base + (size_t)(qt * 128) * DD,
                         Ql + base + (size_t)(qt * 128) * DD};

    // ---- load Q (hi/lo, 128 rows), grouped with kv stage0 ----
    {
        #pragma unroll
        for (int p = 0; p < 8; p++) {
            int i = tid + p * 256;          // 0..2047
            int t = i >> 10;                // tile (1024 chunks each)
            int rem = i & 1023;
            int row = rem >> 3;
            int ch = rem & 7;
            CP_ASYNC16(sbase + t * FQTILE + row * FSTR + ch * 16,
                       gq[t] + (size_t)row * DD + ch * 8);
        }
    }

    const bf16* gkv[4] = {Kh + base, Kl + base, Vh + base, Vl + base};
    auto load_kv = [&](int kt, int st) {
        const uint32_t s0 = sbase + 2 * FQTILE + st * FSTAGEB;
        const size_t roff = (size_t)(kt * 64) * DD;
        #pragma unroll
        for (int p = 0; p < 8; p++) {
            int i = tid + p * 256;          // 0..2047
            int t = i >> 9;
            int rem = i & 511;
            int row = rem >> 3;
            int ch = rem & 7;
            CP_ASYNC16(s0 + t * FKTILE + row * FSTR + ch * 16,
                       gkv[t] + roff + (size_t)row * DD + ch * 8);
        }
        CP_COMMIT();
    };

    load_kv(0, 0);

    const int qr = lane >> 2;
    const int ql2 = (lane & 3) * 2;
    const int lrow = lane & 15;
    const int lhalf = (lane >> 4) * 16;

    float oacc[8][4];
    #pragma unroll
    for (int nt = 0; nt < 8; nt++)
        #pragma unroll
        for (int j = 0; j < 4; j++) oacc[nt][j] = 0.f;
    float m0 = -CUDART_INF_F, m1 = -CUDART_INF_F;
    float l0 = 0.f, l1 = 0.f;

    const int wrow = w * 16;                // warp's first q row in CTA tile
    const int row0g = qt * 128 + wrow;      // global
    const int nk = 2 * qt + 2;

    for (int kt = 0; kt < nk; kt++) {
        if (kt + 1 < nk) {
            load_kv(kt + 1, (kt + 1) & 1);
            CP_WAIT(1);
        } else {
            CP_WAIT(0);
        }
        __syncthreads();

        // warp-level early-out: kv tile entirely above this warp's rows
        if (kt * 64 <= row0g + 15) {
            const uint32_t s0  = sbase + 2 * FQTILE + (kt & 1) * FSTAGEB;
            const uint32_t sQh = sbase, sQl = sbase + FQTILE;
            const uint32_t sKh = s0,             sKl = s0 + FKTILE;
            const uint32_t sVh = s0 + 2 * FKTILE, sVl = s0 + 3 * FKTILE;

            // ---- S = Q @ K^T (bf16x3), log2 units ----
            float sac[8][4];
            #pragma unroll
            for (int nt = 0; nt < 8; nt++)
                #pragma unroll
                for (int j = 0; j < 4; j++) sac[nt][j] = 0.f;

            #pragma unroll
            for (int kk = 0; kk < 4; kk++) {
                uint32_t aoff = (uint32_t)(wrow + lrow) * FSTR + lhalf + kk * 32;
                uint32_t qh_[4], ql_[4];
                ldsm_x4(qh_[0], qh_[1], qh_[2], qh_[3], sQh + aoff);
                ldsm_x4(ql_[0], ql_[1], ql_[2], ql_[3], sQl + aoff);
                #pragma unroll
                for (int ng = 0; ng < 4; ng++) {
                    uint32_t boff = (uint32_t)(ng * 16 + lrow) * FSTR + lhalf + kk * 32;
                    uint32_t kh_[4], kl_[4];
                    ldsm_x4(kh_[0], kh_[1], kh_[2], kh_[3], sKh + boff);
                    ldsm_x4(kl_[0], kl_[1], kl_[2], kl_[3], sKl + boff);
                    mma16816(sac[2 * ng],     qh_, kh_[0], kh_[2]);
                    mma16816(sac[2 * ng],     ql_, kh_[0], kh_[2]);
                    mma16816(sac[2 * ng],     qh_, kl_[0], kl_[2]);
                    mma16816(sac[2 * ng + 1], qh_, kh_[1], kh_[3]);
                    mma16816(sac[2 * ng + 1], ql_, kh_[1], kh_[3]);
                    mma16816(sac[2 * ng + 1], qh_, kl_[1], kl_[3]);
                }
            }

            // ---- causal mask when tile straddles this warp's diagonal ----
            if (kt * 64 + 63 > row0g) {
                const int r0 = row0g + qr, r1 = r0 + 8;
                #pragma unroll
                for (int nt = 0; nt < 8; nt++) {
                    int c = kt * 64 + nt * 8 + ql2;
                    if (c > r0)     sac[nt][0] = -CUDART_INF_F;
                    if (c + 1 > r0) sac[nt][1] = -CUDART_INF_F;
                    if (c > r1)     sac[nt][2] = -CUDART_INF_F;
                    if (c + 1 > r1) sac[nt][3] = -CUDART_INF_F;
                }
            }

            // ---- online softmax (base 2) ----
            float mx0 = -CUDART_INF_F, mx1 = -CUDART_INF_F;
            #pragma unroll
            for (int nt = 0; nt < 8; nt++) {
                mx0 = fmaxf(mx0, fmaxf(sac[nt][0], sac[nt][1]));
                mx1 = fmaxf(mx1, fmaxf(sac[nt][2], sac[nt][3]));
            }
            mx0 = fmaxf(mx0, __shfl_xor_sync(0xffffffffu, mx0, 1));
            mx0 = fmaxf(mx0, __shfl_xor_sync(0xffffffffu, mx0, 2));
            mx1 = fmaxf(mx1, __shfl_xor_sync(0xffffffffu, mx1, 1));
            mx1 = fmaxf(mx1, __shfl_xor_sync(0xffffffffu, mx1, 2));

            float mn0 = fmaxf(m0, mx0), mn1 = fmaxf(m1, mx1);
            float cr0 = exp2f(m0 - mn0), cr1 = exp2f(m1 - mn1);
            m0 = mn0; m1 = mn1;

            float ls0 = 0.f, ls1 = 0.f;
            #pragma unroll
            for (int nt = 0; nt < 8; nt++) {
                float p0 = exp2f(sac[nt][0] - m0);
                float p1 = exp2f(sac[nt][1] - m0);
                float p2 = exp2f(sac[nt][2] - m1);
                float p3 = exp2f(sac[nt][3] - m1);
                sac[nt][0] = p0; sac[nt][1] = p1; sac[nt][2] = p2; sac[nt][3] = p3;
                ls0 += p0 + p1;
                ls1 += p2 + p3;
            }
            ls0 += __shfl_xor_sync(0xffffffffu, ls0, 1);
            ls0 += __shfl_xor_sync(0xffffffffu, ls0, 2);
            ls1 += __shfl_xor_sync(0xffffffffu, ls1, 1);
            ls1 += __shfl_xor_sync(0xffffffffu, ls1, 2);
            l0 = l0 * cr0 + ls0;
            l1 = l1 * cr1 + ls1;

            #pragma unroll
            for (int nt = 0; nt < 8; nt++) {
                oacc[nt][0] *= cr0; oacc[nt][1] *= cr0;
                oacc[nt][2] *= cr1; oacc[nt][3] *= cr1;
            }

            // ---- O += P @ V (bf16x3, P from registers) ----
            #pragma unroll
            for (int kk = 0; kk < 4; kk++) {
                uint32_t ph_[4], pl_[4];
                {
                    uint32_t h0, lo0, h1, lo1, h2, lo2, h3, lo3;
                    split2(sac[2 * kk][0],     sac[2 * kk][1],     h0, lo0);
                    split2(sac[2 * kk][2],     sac[2 * kk][3],     h1, lo1);
                    split2(sac[2 * kk + 1][0], sac[2 * kk + 1][1], h2, lo2);
                    split2(sac[2 * kk + 1][2], sac[2 * kk + 1][3], h3, lo3);
                    ph_[0] = h0; ph_[1] = h1; ph_[2] = h2; ph_[3] = h3;
                    pl_[0] = lo0; pl_[1] = lo1; pl_[2] = lo2; pl_[3] = lo3;
                }
                #pragma unroll
                for (int ng = 0; ng < 4; ng++) {
                    uint32_t voff = (uint32_t)(kk * 16 + lrow) * FSTR + ng * 32 + lhalf;
                    uint32_t vh_[4], vl_[4];
                    ldsm_x4_t(vh_[0], vh_[1], vh_[2], vh_[3], sVh + voff);
                    ldsm_x4_t(vl_[0], vl_[1], vl_[2], vl_[3], sVl + voff);
                    mma16816(oacc[2 * ng],     ph_, vh_[0], vh_[1]);
                    mma16816(oacc[2 * ng],     pl_, vh_[0], vh_[1]);
                    mma16816(oacc[2 * ng],     ph_, vl_[0], vl_[1]);
                    mma16816(oacc[2 * ng + 1], ph_, vh_[2], vh_[3]);
                    mma16816(oacc[2 * ng + 1], pl_, vh_[2], vh_[3]);
                    mma16816(oacc[2 * ng + 1], ph_, vl_[2], vl_[3]);
                }
            }
        }
        __syncthreads();
    }

    // ---- epilogue: normalize, split, store bf16 hi/lo ----
    const float inv0 = 1.0f / l0, inv1 = 1.0f / l1;
    const size_t orow0 = base + (size_t)(qt * 128 + wrow + qr) * DD;
    const size_t orow1 = orow0 + 8 * DD;
    #pragma unroll
    for (int nt = 0; nt < 8; nt++) {
        int d = nt * 8 + ql2;
        uint32_t h0, lo0, h1, lo1;
        split2(oacc[nt][0] * inv0, oacc[nt][1] * inv0, h0, lo0);
        split2(oacc[nt][2] * inv1, oacc[nt][3] * inv1, h1, lo1);
        *(uint32_t*)(Oh + orow0 + d) = h0;
        *(uint32_t*)(Ol + orow0 + d) = lo0;
        *(uint32_t*)(Oh + orow1 + d) = h1;
        *(uint32_t*)(Ol + orow1 + d) = lo1;
    }
}

// ============================================================
// Launch
// ============================================================
extern "C" void kernel_launch(void* const* d_in, const int* in_sizes, int n_in,
                              void* d_out, int out_size)
{
    const float* x  = (const float*)d_in[0];
    const float* Wq = (const float*)d_in[1];
    const float* Wk = (const float*)d_in[2];
    const float* Wv = (const float*)d_in[3];
    const float* Wo = (const float*)d_in[4];
    const float* bo = (const float*)d_in[5];
    float* out = (float*)d_out;

    bf16 *xh, *xl, *qkvh, *qkvl, *wqkvh, *wqkvl, *woh, *wol;
    cudaGetSymbolAddress((void**)&xh, g_xh);
    cudaGetSymbolAddress((void**)&xl, g_xl);
    cudaGetSymbolAddress((void**)&qkvh, g_qkvh);
    cudaGetSymbolAddress((void**)&qkvl, g_qkvl);
    cudaGetSymbolAddress((void**)&wqkvh, g_wqkvh);
    cudaGetSymbolAddress((void**)&wqkvl, g_wqkvl);
    cudaGetSymbolAddress((void**)&woh, g_woh);
    cudaGetSymbolAddress((void**)&wol, g_wol);

    // 1. split x
    const int n4 = MTOK * DD / 4;
    split_kernel<<<n4 / 256, 256>>>(x, xh, xl, n4);

    // 2. fused transpose+split of all 4 weights
    transpose_split4_kernel<<<dim3(DD / 32, DD / 32, 4), dim3(32, 8)>>>(
        Wq, Wk, Wv, Wo, wqkvh, wqkvl, woh, wol);

    // 3. fused QKV projection (single launch, N=3072)
    const float qscale = 0.125f * 1.4426950408889634f;
    cudaFuncSetAttribute(gemm_mma_kernel,
                         cudaFuncAttributeMaxDynamicSharedMemorySize, GSMEM);
    gemm_mma_kernel<<<dim3(24, MTOK / 128), 256, GSMEM>>>(
        xh, xl, wqkvh, wqkvl, nullptr, nullptr, qkvh, qkvl, qscale);

    // 4. flash attention (128-row CTA tiles, 8 warps); writes hi/lo into xh/xl
    const size_t seg = (size_t)MTOK * DD;
    cudaFuncSetAttribute(flash_mma_kernel,
                         cudaFuncAttributeMaxDynamicSharedMemorySize, FSMEM);
    flash_mma_kernel<<<dim3(SS / 128, HH, BB), 256, FSMEM>>>(
        qkvh, qkvl, qkvh + seg, qkvl + seg, qkvh + 2 * seg, qkvl + 2 * seg,
        xh, xl);

    // 5. output projection (+bias), fp32 out
    gemm_mma_kernel<<<dim3(8, MTOK / 128), 256, GSMEM>>>(
        xh, xl, woh, wol, bo, out, nullptr, nullptr, 1.0f);
}

// round 7
// speedup vs baseline: 3.0992x; 1.1143x over previous
#include <cuda_runtime.h>
#include <cuda_bf16.h>
#include <math_constants.h>
#include <cstdint>

// Problem constants
#define BB 4
#define SS 2048
#define DD 1024
#define HH 16
#define HDIM 64
#define MTOK (BB * SS)   // 8192
#define GK DD            // GEMM K = 1024

typedef __nv_bfloat16 bf16;

// ---------------- scratch (__device__ globals; allocation-free rule) -------
__device__ bf16 g_xh[MTOK * DD], g_xl[MTOK * DD];
__device__ bf16 g_qkvh[3 * MTOK * DD], g_qkvl[3 * MTOK * DD];   // Q|K|V segments
__device__ bf16 g_wqkvh[3 * DD * DD], g_wqkvl[3 * DD * DD];     // Wq|Wk|Wv (transposed)
__device__ bf16 g_woh[DD * DD], g_wol[DD * DD];

// ---------------- helpers (plain sm_90-era PTX only) ------------------------
__device__ __forceinline__ uint32_t smem_u32(const void* p) {
    uint32_t a;
    asm("{ .reg .u64 t; cvta.to.shared.u64 t, %1; cvt.u32.u64 %0, t; }"
        : "=r"(a) : "l"(p));
    return a;
}
__device__ __forceinline__ void ldsm_x4(uint32_t& r0, uint32_t& r1,
                                        uint32_t& r2, uint32_t& r3, uint32_t addr) {
    asm volatile("ldmatrix.sync.aligned.m8n8.x4.shared.b16 {%0,%1,%2,%3}, [%4];"
                 : "=r"(r0), "=r"(r1), "=r"(r2), "=r"(r3) : "r"(addr));
}
__device__ __forceinline__ void ldsm_x4_t(uint32_t& r0, uint32_t& r1,
                                          uint32_t& r2, uint32_t& r3, uint32_t addr) {
    asm volatile("ldmatrix.sync.aligned.m8n8.x4.trans.shared.b16 {%0,%1,%2,%3}, [%4];"
                 : "=r"(r0), "=r"(r1), "=r"(r2), "=r"(r3) : "r"(addr));
}
__device__ __forceinline__ void mma16816(float* c, const uint32_t* a,
                                         uint32_t b0, uint32_t b1) {
    asm volatile(
        "mma.sync.aligned.m16n8k16.row.col.f32.bf16.bf16.f32 "
        "{%0,%1,%2,%3}, {%4,%5,%6,%7}, {%8,%9}, {%0,%1,%2,%3};"
        : "+f"(c[0]), "+f"(c[1]), "+f"(c[2]), "+f"(c[3])
        : "r"(a[0]), "r"(a[1]), "r"(a[2]), "r"(a[3]), "r"(b0), "r"(b1));
}
#define CP_ASYNC16(saddr, gaddr) \
    asm volatile("cp.async.cg.shared.global [%0], [%1], 16;" :: "r"(saddr), "l"(gaddr))
#define CP_COMMIT() asm volatile("cp.async.commit_group;" ::: "memory")
#define CP_WAIT(n)  asm volatile("cp.async.wait_group %0;" :: "n"(n) : "memory")

// SW64 swizzle: permutes 16B chunks within the 128B bank period
#define SW64(off) ((off) ^ (((off) >> 3) & 0x30))

__device__ __forceinline__ uint32_t pack2bf(float a, float b) {
    __nv_bfloat162 t = __floats2bfloat162_rn(a, b);
    return *reinterpret_cast<uint32_t*>(&t);
}
__device__ __forceinline__ void split2(float a, float b, uint32_t& hi, uint32_t& lo) {
    bf16 ha = __float2bfloat16(a), hb = __float2bfloat16(b);
    hi = pack2bf(__bfloat162float(ha), __bfloat162float(hb));
    lo = pack2bf(a - __bfloat162float(ha), b - __bfloat162float(hb));
}

// ============================================================
// split: fp32 -> bf16 hi + bf16 lo (residual)   [for input x]
// ============================================================
__global__ __launch_bounds__(256) void split_kernel(
    const float* __restrict__ in, bf16* __restrict__ hi,
    bf16* __restrict__ lo, int n4)
{
    int i = blockIdx.x * blockDim.x + threadIdx.x;
    if (i >= n4) return;
    float4 v = reinterpret_cast<const float4*>(in)[i];
    uint32_t h0, l0, h1, l1;
    split2(v.x, v.y, h0, l0);
    split2(v.z, v.w, h1, l1);
    uint2 hh, ll;
    hh.x = h0; hh.y = h1;
    ll.x = l0; ll.y = l1;
    reinterpret_cast<uint2*>(hi)[i] = hh;
    reinterpret_cast<uint2*>(lo)[i] = ll;
}

// ============================================================
// fused transpose + split of all 4 weights (z = which weight)
// ============================================================
__global__ __launch_bounds__(256) void transpose_split4_kernel(
    const float* __restrict__ Wq, const float* __restrict__ Wk,
    const float* __restrict__ Wv, const float* __restrict__ Wo,
    bf16* __restrict__ Wqkvh, bf16* __restrict__ Wqkvl,
    bf16* __restrict__ Woh, bf16* __restrict__ Wol)
{
    __shared__ float t[32][33];
    const int z = blockIdx.z;
    const float* W = (z == 0) ? Wq : (z == 1) ? Wk : (z == 2) ? Wv : Wo;
    bf16* Th = (z < 3) ? Wqkvh + (size_t)z * DD * DD : Woh;
    bf16* Tl = (z < 3) ? Wqkvl + (size_t)z * DD * DD : Wol;

    const int bx = blockIdx.x, by = blockIdx.y;
    const int x = threadIdx.x, y = threadIdx.y;  // 32 x 8
    #pragma unroll
    for (int i = 0; i < 4; i++)
        t[y + 8 * i][x] = W[(size_t)(by * 32 + y + 8 * i) * DD + bx * 32 + x];
    __syncthreads();
    #pragma unroll
    for (int i = 0; i < 4; i++) {
        float v = t[x][y + 8 * i];
        bf16 h = __float2bfloat16(v);
        bf16 l = __float2bfloat16(v - __bfloat162float(h));
        size_t off = (size_t)(bx * 32 + y + 8 * i) * DD + by * 32 + x;
        Th[off] = h;
        Tl[off] = l;
    }
}

// ============================================================
// bf16x3 GEMM on mma.sync. 3-stage cp.async pipeline, SW64
// swizzled unpadded 64B rows, ONE barrier per K-chunk.
// ============================================================
#define CHK 32
#define GTILE 8192               // 128 rows x 64 B
#define GSTAGE (4 * GTILE)       // Ah, Al, Bh, Bl = 32768 B
#define GSMEM (3 * GSTAGE)       // 98304 B

__global__ __launch_bounds__(256, 2) void gemm_mma_kernel(
    const bf16* __restrict__ Ah, const bf16* __restrict__ Al,
    const bf16* __restrict__ Bh, const bf16* __restrict__ Bl,
    const float* __restrict__ bias, float* __restrict__ Cf,
    bf16* __restrict__ Ch, bf16* __restrict__ Cl, float qscale)
{
    extern __shared__ __align__(1024) char dsm[];
    const uint32_t sbase = smem_u32(dsm);

    const int tid = threadIdx.x;
    const int lane = tid & 31;
    const int wid = tid >> 5;
    const int warp_m = wid & 3;
    const int warp_n = wid >> 2;
    const int br = blockIdx.y, bc = blockIdx.x;

    const bf16* gsrc[4] = {
        Ah + (size_t)(br * 128) * GK, Al + (size_t)(br * 128) * GK,
        Bh + (size_t)(bc * 128) * GK, Bl + (size_t)(bc * 128) * GK
    };

    auto load_stage = [&](int k0, int st) {
        const uint32_t s0 = sbase + st * GSTAGE;
        #pragma unroll
        for (int p = 0; p < 8; p++) {
            int idx = tid + p * 256;
            int t   = idx >> 9;
            int rem = idx & 511;
            int row = rem >> 2;
            int ch  = rem & 3;
            uint32_t sa = s0 + t * GTILE + SW64((uint32_t)(row * 64 + ch * 16));
            const bf16* g = gsrc[t] + (size_t)row * GK + k0 + ch * 8;
            CP_ASYNC16(sa, g);
        }
        CP_COMMIT();
    };

    float acc[2][8][4];
    #pragma unroll
    for (int mt = 0; mt < 2; mt++)
        #pragma unroll
        for (int nt = 0; nt < 8; nt++)
            #pragma unroll
            for (int j = 0; j < 4; j++) acc[mt][nt][j] = 0.f;

    const int NC = GK / CHK;   // 32
    load_stage(0, 0);
    load_stage(CHK, 1);

    const int lrow = lane & 15;
    const int lsel = (lane >> 4) * 16;

    int st = 0;                 // stage index of chunk c (mod 3)
    for (int c = 0; c < NC; c++) {
        if (c + 1 < NC) { CP_WAIT(1); } else { CP_WAIT(0); }
        __syncthreads();
        if (c + 2 < NC) {
            int nst = st + 2; if (nst >= 3) nst -= 3;
            load_stage((c + 2) * CHK, nst);
        }

        const uint32_t s0  = sbase + st * GSTAGE;
        const uint32_t sAh = s0, sAl = s0 + GTILE;
        const uint32_t sBh = s0 + 2 * GTILE, sBl = s0 + 3 * GTILE;

        #pragma unroll
        for (int kk = 0; kk < 2; kk++) {
            const int lcol = lsel + kk * 32;
            uint32_t ah[2][4], al[2][4];
            #pragma unroll
            for (int mt = 0; mt < 2; mt++) {
                uint32_t off = SW64((uint32_t)((warp_m * 32 + mt * 16 + lrow) * 64 + lcol));
                ldsm_x4(ah[mt][0], ah[mt][1], ah[mt][2], ah[mt][3], sAh + off);
                ldsm_x4(al[mt][0], al[mt][1], al[mt][2], al[mt][3], sAl + off);
            }
            #pragma unroll
            for (int ng = 0; ng < 4; ng++) {
                uint32_t off = SW64((uint32_t)((warp_n * 64 + ng * 16 + lrow) * 64 + lcol));
                uint32_t bh[4], bl[4];
                ldsm_x4(bh[0], bh[1], bh[2], bh[3], sBh + off);
                ldsm_x4(bl[0], bl[1], bl[2], bl[3], sBl + off);
                #pragma unroll
                for (int mt = 0; mt < 2; mt++) {
                    mma16816(acc[mt][2 * ng],     ah[mt], bh[0], bh[2]);
                    mma16816(acc[mt][2 * ng],     al[mt], bh[0], bh[2]);
                    mma16816(acc[mt][2 * ng],     ah[mt], bl[0], bl[2]);
                    mma16816(acc[mt][2 * ng + 1], ah[mt], bh[1], bh[3]);
                    mma16816(acc[mt][2 * ng + 1], al[mt], bh[1], bh[3]);
                    mma16816(acc[mt][2 * ng + 1], ah[mt], bl[1], bl[3]);
                }
            }
        }
        if (++st == 3) st = 0;
    }

    const int row0 = br * 128 + warp_m * 32;
    const int col0 = (bc & 7) * 128 + warp_n * 64;
    const int qr = lane >> 2;
    const int qc = (lane & 3) * 2;

    if (Cf) {
        #pragma unroll
        for (int mt = 0; mt < 2; mt++) {
            #pragma unroll
            for (int nt = 0; nt < 8; nt++) {
                int col = col0 + nt * 8 + qc;
                float b0 = 0.f, b1 = 0.f;
                if (bias) { b0 = bias[col]; b1 = bias[col + 1]; }
                size_t o0 = (size_t)(row0 + mt * 16 + qr) * DD + col;
                size_t o1 = o0 + 8 * DD;
                float2 w0, w1;
                w0.x = acc[mt][nt][0] + b0; w0.y = acc[mt][nt][1] + b1;
                w1.x = acc[mt][nt][2] + b0; w1.y = acc[mt][nt][3] + b1;
                *(float2*)(Cf + o0) = w0;
                *(float2*)(Cf + o1) = w1;
            }
        }
    } else {
        const int sel = bc >> 3;
        const float scale = (sel == 0) ? qscale : 1.0f;
        bf16* Chs = Ch + (size_t)sel * MTOK * DD;
        bf16* Cls = Cl + (size_t)sel * MTOK * DD;
        #pragma unroll
        for (int mt = 0; mt < 2; mt++) {
            #pragma unroll
            for (int nt = 0; nt < 8; nt++) {
                int col = col0 + nt * 8 + qc;
                size_t o0 = (size_t)(row0 + mt * 16 + qr) * DD + col;
                size_t o1 = o0 + 8 * DD;
                uint32_t h0, l0, h1, l1;
                split2(acc[mt][nt][0] * scale, acc[mt][nt][1] * scale, h0, l0);
                split2(acc[mt][nt][2] * scale, acc[mt][nt][3] * scale, h1, l1);
                *(uint32_t*)(Chs + o0) = h0;
                *(uint32_t*)(Cls + o0) = l0;
                *(uint32_t*)(Chs + o1) = h1;
                *(uint32_t*)(Cls + o1) = l1;
            }
        }
    }
}

// ============================================================
// Flash attention (causal) on mma.sync, bf16x3, base-2 softmax.
// CTA: 256 threads / 8 warps; CTA tile 128 q-rows x 64 kv.
// ONE barrier per kv tile. Q pre-scaled by 0.125*log2(e).
// ============================================================
#define FSTR 144
#define FKTILE (64 * FSTR)            // 9216 B
#define FQTILE (128 * FSTR)           // 18432 B
#define FSTAGEB (4 * FKTILE)          // 36864 B
#define FSMEM (2 * FQTILE + 2 * FSTAGEB)  // 110592 B

__global__ __launch_bounds__(256, 2) void flash_mma_kernel(
    const bf16* __restrict__ Qh, const bf16* __restrict__ Ql,
    const bf16* __restrict__ Kh, const bf16* __restrict__ Kl,
    const bf16* __restrict__ Vh, const bf16* __restrict__ Vl,
    bf16* __restrict__ Oh, bf16* __restrict__ Ol)
{
    extern __shared__ __align__(1024) char dsm[];
    const uint32_t sbase = smem_u32(dsm);

    const int tid = threadIdx.x;
    const int lane = tid & 31;
    const int w = tid >> 5;                 // 0..7
    const int qt = blockIdx.x, h = blockIdx.y, b = blockIdx.z;

    const size_t base = ((size_t)b * SS) * DD + (size_t)h * HDIM;
    const bf16* gq[2] = {Qh + base + (size_t)(qt * 128) * DD,
                         Ql + base + (size_t)(qt * 128) * DD};

    // ---- load Q (hi/lo, 128 rows), grouped with kv stage0 ----
    {
        #pragma unroll
        for (int p = 0; p < 8; p++) {
            int i = tid + p * 256;
            int t = i >> 10;
            int rem = i & 1023;
            int row = rem >> 3;
            int ch = rem & 7;
            CP_ASYNC16(sbase + t * FQTILE + row * FSTR + ch * 16,
                       gq[t] + (size_t)row * DD + ch * 8);
        }
    }

    const bf16* gkv[4] = {Kh + base, Kl + base, Vh + base, Vl + base};
    auto load_kv = [&](int kt, int st) {
        const uint32_t s0 = sbase + 2 * FQTILE + st * FSTAGEB;
        const size_t roff = (size_t)(kt * 64) * DD;
        #pragma unroll
        for (int p = 0; p < 8; p++) {
            int i = tid + p * 256;
            int t = i >> 9;
            int rem = i & 511;
            int row = rem >> 3;
            int ch = rem & 7;
            CP_ASYNC16(s0 + t * FKTILE + row * FSTR + ch * 16,
                       gkv[t] + roff + (size_t)row * DD + ch * 8);
        }
        CP_COMMIT();
    };

    load_kv(0, 0);

    const int qr = lane >> 2;
    const int ql2 = (lane & 3) * 2;
    const int lrow = lane & 15;
    const int lhalf = (lane >> 4) * 16;

    float oacc[8][4];
    #pragma unroll
    for (int nt = 0; nt < 8; nt++)
        #pragma unroll
        for (int j = 0; j < 4; j++) oacc[nt][j] = 0.f;
    float m0 = -CUDART_INF_F, m1 = -CUDART_INF_F;
    float l0 = 0.f, l1 = 0.f;

    const int wrow = w * 16;
    const int row0g = qt * 128 + wrow;
    const int nk = 2 * qt + 2;

    for (int kt = 0; kt < nk; kt++) {
        CP_WAIT(0);
        __syncthreads();
        if (kt + 1 < nk) load_kv(kt + 1, (kt + 1) & 1);

        // warp-level early-out: kv tile entirely above this warp's rows
        if (kt * 64 <= row0g + 15) {
            const uint32_t s0  = sbase + 2 * FQTILE + (kt & 1) * FSTAGEB;
            const uint32_t sQh = sbase, sQl = sbase + FQTILE;
            const uint32_t sKh = s0,             sKl = s0 + FKTILE;
            const uint32_t sVh = s0 + 2 * FKTILE, sVl = s0 + 3 * FKTILE;

            // ---- S = Q @ K^T (bf16x3), log2 units ----
            float sac[8][4];
            #pragma unroll
            for (int nt = 0; nt < 8; nt++)
                #pragma unroll
                for (int j = 0; j < 4; j++) sac[nt][j] = 0.f;

            #pragma unroll
            for (int kk = 0; kk < 4; kk++) {
                uint32_t aoff = (uint32_t)(wrow + lrow) * FSTR + lhalf + kk * 32;
                uint32_t qh_[4], ql_[4];
                ldsm_x4(qh_[0], qh_[1], qh_[2], qh_[3], sQh + aoff);
                ldsm_x4(ql_[0], ql_[1], ql_[2], ql_[3], sQl + aoff);
                #pragma unroll
                for (int ng = 0; ng < 4; ng++) {
                    uint32_t boff = (uint32_t)(ng * 16 + lrow) * FSTR + lhalf + kk * 32;
                    uint32_t kh_[4], kl_[4];
                    ldsm_x4(kh_[0], kh_[1], kh_[2], kh_[3], sKh + boff);
                    ldsm_x4(kl_[0], kl_[1], kl_[2], kl_[3], sKl + boff);
                    mma16816(sac[2 * ng],     qh_, kh_[0], kh_[2]);
                    mma16816(sac[2 * ng],     ql_, kh_[0], kh_[2]);
                    mma16816(sac[2 * ng],     qh_, kl_[0], kl_[2]);
                    mma16816(sac[2 * ng + 1], qh_, kh_[1], kh_[3]);
                    mma16816(sac[2 * ng + 1], ql_, kh_[1], kh_[3]);
                    mma16816(sac[2 * ng + 1], qh_, kl_[1], kl_[3]);
                }
            }

            // ---- causal mask when tile straddles this warp's diagonal ----
            if (kt * 64 + 63 > row0g) {
                const int r0 = row0g + qr, r1 = r0 + 8;
                #pragma unroll
                for (int nt = 0; nt < 8; nt++) {
                    int c = kt * 64 + nt * 8 + ql2;
                    if (c > r0)     sac[nt][0] = -CUDART_INF_F;
                    if (c + 1 > r0) sac[nt][1] = -CUDART_INF_F;
                    if (c > r1)     sac[nt][2] = -CUDART_INF_F;
                    if (c + 1 > r1) sac[nt][3] = -CUDART_INF_F;
                }
            }

            // ---- online softmax (base 2) ----
            float mx0 = -CUDART_INF_F, mx1 = -CUDART_INF_F;
            #pragma unroll
            for (int nt = 0; nt < 8; nt++) {
                mx0 = fmaxf(mx0, fmaxf(sac[nt][0], sac[nt][1]));
                mx1 = fmaxf(mx1, fmaxf(sac[nt][2], sac[nt][3]));
            }
            mx0 = fmaxf(mx0, __shfl_xor_sync(0xffffffffu, mx0, 1));
            mx0 = fmaxf(mx0, __shfl_xor_sync(0xffffffffu, mx0, 2));
            mx1 = fmaxf(mx1, __shfl_xor_sync(0xffffffffu, mx1, 1));
            mx1 = fmaxf(mx1, __shfl_xor_sync(0xffffffffu, mx1, 2));

            float mn0 = fmaxf(m0, mx0), mn1 = fmaxf(m1, mx1);
            float cr0 = exp2f(m0 - mn0), cr1 = exp2f(m1 - mn1);
            m0 = mn0; m1 = mn1;

            float ls0 = 0.f, ls1 = 0.f;
            #pragma unroll
            for (int nt = 0; nt < 8; nt++) {
                float p0 = exp2f(sac[nt][0] - m0);
                float p1 = exp2f(sac[nt][1] - m0);
                float p2 = exp2f(sac[nt][2] - m1);
                float p3 = exp2f(sac[nt][3] - m1);
                sac[nt][0] = p0; sac[nt][1] = p1; sac[nt][2] = p2; sac[nt][3] = p3;
                ls0 += p0 + p1;
                ls1 += p2 + p3;
            }
            ls0 += __shfl_xor_sync(0xffffffffu, ls0, 1);
            ls0 += __shfl_xor_sync(0xffffffffu, ls0, 2);
            ls1 += __shfl_xor_sync(0xffffffffu, ls1, 1);
            ls1 += __shfl_xor_sync(0xffffffffu, ls1, 2);
            l0 = l0 * cr0 + ls0;
            l1 = l1 * cr1 + ls1;

            #pragma unroll
            for (int nt = 0; nt < 8; nt++) {
                oacc[nt][0] *= cr0; oacc[nt][1] *= cr0;
                oacc[nt][2] *= cr1; oacc[nt][3] *= cr1;
            }

            // ---- O += P @ V (bf16x3, P from registers) ----
            #pragma unroll
            for (int kk = 0; kk < 4; kk++) {
                uint32_t ph_[4], pl_[4];
                {
                    uint32_t h0, lo0, h1, lo1, h2, lo2, h3, lo3;
                    split2(sac[2 * kk][0],     sac[2 * kk][1],     h0, lo0);
                    split2(sac[2 * kk][2],     sac[2 * kk][3],     h1, lo1);
                    split2(sac[2 * kk + 1][0], sac[2 * kk + 1][1], h2, lo2);
                    split2(sac[2 * kk + 1][2], sac[2 * kk + 1][3], h3, lo3);
                    ph_[0] = h0; ph_[1] = h1; ph_[2] = h2; ph_[3] = h3;
                    pl_[0] = lo0; pl_[1] = lo1; pl_[2] = lo2; pl_[3] = lo3;
                }
                #pragma unroll
                for (int ng = 0; ng < 4; ng++) {
                    uint32_t voff = (uint32_t)(kk * 16 + lrow) * FSTR + ng * 32 + lhalf;
                    uint32_t vh_[4], vl_[4];
                    ldsm_x4_t(vh_[0], vh_[1], vh_[2], vh_[3], sVh + voff);
                    ldsm_x4_t(vl_[0], vl_[1], vl_[2], vl_[3], sVl + voff);
                    mma16816(oacc[2 * ng],     ph_, vh_[0], vh_[1]);
                    mma16816(oacc[2 * ng],     pl_, vh_[0], vh_[1]);
                    mma16816(oacc[2 * ng],     ph_, vl_[0], vl_[1]);
                    mma16816(oacc[2 * ng + 1], ph_, vh_[2], vh_[3]);
                    mma16816(oacc[2 * ng + 1], pl_, vh_[2], vh_[3]);
                    mma16816(oacc[2 * ng + 1], ph_, vl_[2], vl_[3]);
                }
            }
        }
    }

    // ---- epilogue: normalize, split, store bf16 hi/lo ----
    const float inv0 = 1.0f / l0, inv1 = 1.0f / l1;
    const size_t orow0 = base + (size_t)(qt * 128 + wrow + qr) * DD;
    const size_t orow1 = orow0 + 8 * DD;
    #pragma unroll
    for (int nt = 0; nt < 8; nt++) {
        int d = nt * 8 + ql2;
        uint32_t h0, lo0, h1, lo1;
        split2(oacc[nt][0] * inv0, oacc[nt][1] * inv0, h0, lo0);
        split2(oacc[nt][2] * inv1, oacc[nt][3] * inv1, h1, lo1);
        *(uint32_t*)(Oh + orow0 + d) = h0;
        *(uint32_t*)(Ol + orow0 + d) = lo0;
        *(uint32_t*)(Oh + orow1 + d) = h1;
        *(uint32_t*)(Ol + orow1 + d) = lo1;
    }
}

// ============================================================
// Launch
// ============================================================
extern "C" void kernel_launch(void* const* d_in, const int* in_sizes, int n_in,
                              void* d_out, int out_size)
{
    const float* x  = (const float*)d_in[0];
    const float* Wq = (const float*)d_in[1];
    const float* Wk = (const float*)d_in[2];
    const float* Wv = (const float*)d_in[3];
    const float* Wo = (const float*)d_in[4];
    const float* bo = (const float*)d_in[5];
    float* out = (float*)d_out;

    bf16 *xh, *xl, *qkvh, *qkvl, *wqkvh, *wqkvl, *woh, *wol;
    cudaGetSymbolAddress((void**)&xh, g_xh);
    cudaGetSymbolAddress((void**)&xl, g_xl);
    cudaGetSymbolAddress((void**)&qkvh, g_qkvh);
    cudaGetSymbolAddress((void**)&qkvl, g_qkvl);
    cudaGetSymbolAddress((void**)&wqkvh, g_wqkvh);
    cudaGetSymbolAddress((void**)&wqkvl, g_wqkvl);
    cudaGetSymbolAddress((void**)&woh, g_woh);
    cudaGetSymbolAddress((void**)&wol, g_wol);

    // 1. split x
    const int n4 = MTOK * DD / 4;
    split_kernel<<<n4 / 256, 256>>>(x, xh, xl, n4);

    // 2. fused transpose+split of all 4 weights
    transpose_split4_kernel<<<dim3(DD / 32, DD / 32, 4), dim3(32, 8)>>>(
        Wq, Wk, Wv, Wo, wqkvh, wqkvl, woh, wol);

    // 3. fused QKV projection (single launch, N=3072)
    const float qscale = 0.125f * 1.4426950408889634f;
    cudaFuncSetAttribute(gemm_mma_kernel,
                         cudaFuncAttributeMaxDynamicSharedMemorySize, GSMEM);
    gemm_mma_kernel<<<dim3(24, MTOK / 128), 256, GSMEM>>>(
        xh, xl, wqkvh, wqkvl, nullptr, nullptr, qkvh, qkvl, qscale);

    // 4. flash attention (128-row CTA tiles, 8 warps); writes hi/lo into xh/xl
    const size_t seg = (size_t)MTOK * DD;
    cudaFuncSetAttribute(flash_mma_kernel,
                         cudaFuncAttributeMaxDynamicSharedMemorySize, FSMEM);
    flash_mma_kernel<<<dim3(SS / 128, HH, BB), 256, FSMEM>>>(
        qkvh, qkvl, qkvh + seg, qkvl + seg, qkvh + 2 * seg, qkvl + 2 * seg,
        xh, xl);

    // 5. output projection (+bias), fp32 out
    gemm_mma_kernel<<<dim3(8, MTOK / 128), 256, GSMEM>>>(
        xh, xl, woh, wol, bo, out, nullptr, nullptr, 1.0f);
}

// round 8
// speedup vs baseline: 3.1010x; 1.0006x over previous
#include <cuda_runtime.h>
#include <cuda_bf16.h>
#include <math_constants.h>
#include <cstdint>

// Problem constants
#define BB 4
#define SS 2048
#define DD 1024
#define HH 16
#define HDIM 64
#define MTOK (BB * SS)   // 8192
#define GK DD            // GEMM K = 1024

typedef __nv_bfloat16 bf16;

// ---------------- scratch (__device__ globals; allocation-free rule) -------
__device__ bf16 g_xh[MTOK * DD], g_xl[MTOK * DD];
__device__ bf16 g_qkvh[3 * MTOK * DD], g_qkvl[3 * MTOK * DD];   // Q|K|V segments
__device__ bf16 g_wqkvh[3 * DD * DD], g_wqkvl[3 * DD * DD];     // Wq|Wk|Wv (transposed)
__device__ bf16 g_woh[DD * DD], g_wol[DD * DD];

// ---------------- helpers (plain sm_90-era PTX only) ------------------------
__device__ __forceinline__ uint32_t smem_u32(const void* p) {
    uint32_t a;
    asm("{ .reg .u64 t; cvta.to.shared.u64 t, %1; cvt.u32.u64 %0, t; }"
        : "=r"(a) : "l"(p));
    return a;
}
__device__ __forceinline__ void ldsm_x4(uint32_t& r0, uint32_t& r1,
                                        uint32_t& r2, uint32_t& r3, uint32_t addr) {
    asm volatile("ldmatrix.sync.aligned.m8n8.x4.shared.b16 {%0,%1,%2,%3}, [%4];"
                 : "=r"(r0), "=r"(r1), "=r"(r2), "=r"(r3) : "r"(addr));
}
__device__ __forceinline__ void ldsm_x4_t(uint32_t& r0, uint32_t& r1,
                                          uint32_t& r2, uint32_t& r3, uint32_t addr) {
    asm volatile("ldmatrix.sync.aligned.m8n8.x4.trans.shared.b16 {%0,%1,%2,%3}, [%4];"
                 : "=r"(r0), "=r"(r1), "=r"(r2), "=r"(r3) : "r"(addr));
}
__device__ __forceinline__ void mma16816(float* c, const uint32_t* a,
                                         uint32_t b0, uint32_t b1) {
    asm volatile(
        "mma.sync.aligned.m16n8k16.row.col.f32.bf16.bf16.f32 "
        "{%0,%1,%2,%3}, {%4,%5,%6,%7}, {%8,%9}, {%0,%1,%2,%3};"
        : "+f"(c[0]), "+f"(c[1]), "+f"(c[2]), "+f"(c[3])
        : "r"(a[0]), "r"(a[1]), "r"(a[2]), "r"(a[3]), "r"(b0), "r"(b1));
}
#define CP_ASYNC16(saddr, gaddr) \
    asm volatile("cp.async.cg.shared.global [%0], [%1], 16;" :: "r"(saddr), "l"(gaddr))
#define CP_COMMIT() asm volatile("cp.async.commit_group;" ::: "memory")
#define CP_WAIT(n)  asm volatile("cp.async.wait_group %0;" :: "n"(n) : "memory")

// SW64 swizzle: permutes 16B chunks within the 128B bank period
#define SW64(off) ((off) ^ (((off) >> 3) & 0x30))

__device__ __forceinline__ uint32_t pack2bf(float a, float b) {
    __nv_bfloat162 t = __floats2bfloat162_rn(a, b);
    return *reinterpret_cast<uint32_t*>(&t);
}
__device__ __forceinline__ void split2(float a, float b, uint32_t& hi, uint32_t& lo) {
    bf16 ha = __float2bfloat16(a), hb = __float2bfloat16(b);
    hi = pack2bf(__bfloat162float(ha), __bfloat162float(hb));
    lo = pack2bf(a - __bfloat162float(ha), b - __bfloat162float(hb));
}

// ============================================================
// split: fp32 -> bf16 hi + bf16 lo (residual)   [for input x]
// ============================================================
__global__ __launch_bounds__(256) void split_kernel(
    const float* __restrict__ in, bf16* __restrict__ hi,
    bf16* __restrict__ lo, int n4)
{
    int i = blockIdx.x * blockDim.x + threadIdx.x;
    if (i >= n4) return;
    float4 v = reinterpret_cast<const float4*>(in)[i];
    uint32_t h0, l0, h1, l1;
    split2(v.x, v.y, h0, l0);
    split2(v.z, v.w, h1, l1);
    uint2 hh, ll;
    hh.x = h0; hh.y = h1;
    ll.x = l0; ll.y = l1;
    reinterpret_cast<uint2*>(hi)[i] = hh;
    reinterpret_cast<uint2*>(lo)[i] = ll;
}

// ============================================================
// fused transpose + split of all 4 weights (z = which weight)
// ============================================================
__global__ __launch_bounds__(256) void transpose_split4_kernel(
    const float* __restrict__ Wq, const float* __restrict__ Wk,
    const float* __restrict__ Wv, const float* __restrict__ Wo,
    bf16* __restrict__ Wqkvh, bf16* __restrict__ Wqkvl,
    bf16* __restrict__ Woh, bf16* __restrict__ Wol)
{
    __shared__ float t[32][33];
    const int z = blockIdx.z;
    const float* W = (z == 0) ? Wq : (z == 1) ? Wk : (z == 2) ? Wv : Wo;
    bf16* Th = (z < 3) ? Wqkvh + (size_t)z * DD * DD : Woh;
    bf16* Tl = (z < 3) ? Wqkvl + (size_t)z * DD * DD : Wol;

    const int bx = blockIdx.x, by = blockIdx.y;
    const int x = threadIdx.x, y = threadIdx.y;  // 32 x 8
    #pragma unroll
    for (int i = 0; i < 4; i++)
        t[y + 8 * i][x] = W[(size_t)(by * 32 + y + 8 * i) * DD + bx * 32 + x];
    __syncthreads();
    #pragma unroll
    for (int i = 0; i < 4; i++) {
        float v = t[x][y + 8 * i];
        bf16 h = __float2bfloat16(v);
        bf16 l = __float2bfloat16(v - __bfloat162float(h));
        size_t off = (size_t)(bx * 32 + y + 8 * i) * DD + by * 32 + x;
        Th[off] = h;
        Tl[off] = l;
    }
}

// ============================================================
// bf16x3 GEMM on mma.sync. 3-stage cp.async pipeline, SW64
// swizzled unpadded 64B rows, ONE barrier per K-chunk.
// ============================================================
#define CHK 32
#define GTILE 8192               // 128 rows x 64 B
#define GSTAGE (4 * GTILE)       // Ah, Al, Bh, Bl = 32768 B
#define GSMEM (3 * GSTAGE)       // 98304 B

__global__ __launch_bounds__(256, 2) void gemm_mma_kernel(
    const bf16* __restrict__ Ah, const bf16* __restrict__ Al,
    const bf16* __restrict__ Bh, const bf16* __restrict__ Bl,
    const float* __restrict__ bias, float* __restrict__ Cf,
    bf16* __restrict__ Ch, bf16* __restrict__ Cl, float qscale)
{
    extern __shared__ __align__(1024) char dsm[];
    const uint32_t sbase = smem_u32(dsm);

    const int tid = threadIdx.x;
    const int lane = tid & 31;
    const int wid = tid >> 5;
    const int warp_m = wid & 3;
    const int warp_n = wid >> 2;
    const int br = blockIdx.y, bc = blockIdx.x;

    const bf16* gsrc[4] = {
        Ah + (size_t)(br * 128) * GK, Al + (size_t)(br * 128) * GK,
        Bh + (size_t)(bc * 128) * GK, Bl + (size_t)(bc * 128) * GK
    };

    auto load_stage = [&](int k0, int st) {
        const uint32_t s0 = sbase + st * GSTAGE;
        #pragma unroll
        for (int p = 0; p < 8; p++) {
            int idx = tid + p * 256;
            int t   = idx >> 9;
            int rem = idx & 511;
            int row = rem >> 2;
            int ch  = rem & 3;
            uint32_t sa = s0 + t * GTILE + SW64((uint32_t)(row * 64 + ch * 16));
            const bf16* g = gsrc[t] + (size_t)row * GK + k0 + ch * 8;
            CP_ASYNC16(sa, g);
        }
        CP_COMMIT();
    };

    float acc[2][8][4];
    #pragma unroll
    for (int mt = 0; mt < 2; mt++)
        #pragma unroll
        for (int nt = 0; nt < 8; nt++)
            #pragma unroll
            for (int j = 0; j < 4; j++) acc[mt][nt][j] = 0.f;

    const int NC = GK / CHK;   // 32
    load_stage(0, 0);
    load_stage(CHK, 1);

    const int lrow = lane & 15;
    const int lsel = (lane >> 4) * 16;

    int st = 0;                 // stage index of chunk c (mod 3)
    for (int c = 0; c < NC; c++) {
        if (c + 1 < NC) { CP_WAIT(1); } else { CP_WAIT(0); }
        __syncthreads();
        if (c + 2 < NC) {
            int nst = st + 2; if (nst >= 3) nst -= 3;
            load_stage((c + 2) * CHK, nst);
        }

        const uint32_t s0  = sbase + st * GSTAGE;
        const uint32_t sAh = s0, sAl = s0 + GTILE;
        const uint32_t sBh = s0 + 2 * GTILE, sBl = s0 + 3 * GTILE;

        #pragma unroll
        for (int kk = 0; kk < 2; kk++) {
            const int lcol = lsel + kk * 32;
            uint32_t ah[2][4], al[2][4];
            #pragma unroll
            for (int mt = 0; mt < 2; mt++) {
                uint32_t off = SW64((uint32_t)((warp_m * 32 + mt * 16 + lrow) * 64 + lcol));
                ldsm_x4(ah[mt][0], ah[mt][1], ah[mt][2], ah[mt][3], sAh + off);
                ldsm_x4(al[mt][0], al[mt][1], al[mt][2], al[mt][3], sAl + off);
            }
            #pragma unroll
            for (int ng = 0; ng < 4; ng++) {
                uint32_t off = SW64((uint32_t)((warp_n * 64 + ng * 16 + lrow) * 64 + lcol));
                uint32_t bh[4], bl[4];
                ldsm_x4(bh[0], bh[1], bh[2], bh[3], sBh + off);
                ldsm_x4(bl[0], bl[1], bl[2], bl[3], sBl + off);
                #pragma unroll
                for (int mt = 0; mt < 2; mt++) {
                    mma16816(acc[mt][2 * ng],     ah[mt], bh[0], bh[2]);
                    mma16816(acc[mt][2 * ng],     al[mt], bh[0], bh[2]);
                    mma16816(acc[mt][2 * ng],     ah[mt], bl[0], bl[2]);
                    mma16816(acc[mt][2 * ng + 1], ah[mt], bh[1], bh[3]);
                    mma16816(acc[mt][2 * ng + 1], al[mt], bh[1], bh[3]);
                    mma16816(acc[mt][2 * ng + 1], ah[mt], bl[1], bl[3]);
                }
            }
        }
        if (++st == 3) st = 0;
    }

    const int row0 = br * 128 + warp_m * 32;
    const int col0 = (bc & 7) * 128 + warp_n * 64;
    const int qr = lane >> 2;
    const int qc = (lane & 3) * 2;

    if (Cf) {
        #pragma unroll
        for (int mt = 0; mt < 2; mt++) {
            #pragma unroll
            for (int nt = 0; nt < 8; nt++) {
                int col = col0 + nt * 8 + qc;
                float b0 = 0.f, b1 = 0.f;
                if (bias) { b0 = bias[col]; b1 = bias[col + 1]; }
                size_t o0 = (size_t)(row0 + mt * 16 + qr) * DD + col;
                size_t o1 = o0 + 8 * DD;
                float2 w0, w1;
                w0.x = acc[mt][nt][0] + b0; w0.y = acc[mt][nt][1] + b1;
                w1.x = acc[mt][nt][2] + b0; w1.y = acc[mt][nt][3] + b1;
                *(float2*)(Cf + o0) = w0;
                *(float2*)(Cf + o1) = w1;
            }
        }
    } else {
        const int sel = bc >> 3;
        const float scale = (sel == 0) ? qscale : 1.0f;
        bf16* Chs = Ch + (size_t)sel * MTOK * DD;
        bf16* Cls = Cl + (size_t)sel * MTOK * DD;
        #pragma unroll
        for (int mt = 0; mt < 2; mt++) {
            #pragma unroll
            for (int nt = 0; nt < 8; nt++) {
                int col = col0 + nt * 8 + qc;
                size_t o0 = (size_t)(row0 + mt * 16 + qr) * DD + col;
                size_t o1 = o0 + 8 * DD;
                uint32_t h0, l0, h1, l1;
                split2(acc[mt][nt][0] * scale, acc[mt][nt][1] * scale, h0, l0);
                split2(acc[mt][nt][2] * scale, acc[mt][nt][3] * scale, h1, l1);
                *(uint32_t*)(Chs + o0) = h0;
                *(uint32_t*)(Cls + o0) = l0;
                *(uint32_t*)(Chs + o1) = h1;
                *(uint32_t*)(Cls + o1) = l1;
            }
        }
    }
}

// ============================================================
// Flash attention (causal) on mma.sync, bf16x3, base-2 softmax.
// CTA: 256 threads / 8 warps; CTA tile 128 q-rows x 64 kv.
// ONE barrier per kv tile. Q pre-scaled by 0.125*log2(e).
// ============================================================
#define FSTR 144
#define FKTILE (64 * FSTR)            // 9216 B
#define FQTILE (128 * FSTR)           // 18432 B
#define FSTAGEB (4 * FKTILE)          // 36864 B
#define FSMEM (2 * FQTILE + 2 * FSTAGEB)  // 110592 B

__global__ __launch_bounds__(256, 2) void flash_mma_kernel(
    const bf16* __restrict__ Qh, const bf16* __restrict__ Ql,
    const bf16* __restrict__ Kh, const bf16* __restrict__ Kl,
    const bf16* __restrict__ Vh, const bf16* __restrict__ Vl,
    bf16* __restrict__ Oh, bf16* __restrict__ Ol)
{
    extern __shared__ __align__(1024) char dsm[];
    const uint32_t sbase = smem_u32(dsm);

    const int tid = threadIdx.x;
    const int lane = tid & 31;
    const int w = tid >> 5;                 // 0..7
    const int qt = blockIdx.x, h = blockIdx.y, b = blockIdx.z;

    const size_t base = ((size_t)b * SS) * DD + (size_t)h * HDIM;
    const bf16* gq[2] = {Qh + base + (size_t)(qt * 128) * DD,
                         Ql + base + (size_t)(qt * 128) * DD};

    // ---- load Q (hi/lo, 128 rows), grouped with kv stage0 ----
    {
        #pragma unroll
        for (int p = 0; p < 8; p++) {
            int i = tid + p * 256;
            int t = i >> 10;
            int rem = i & 1023;
            int row = rem >> 3;
            int ch = rem & 7;
            CP_ASYNC16(sbase + t * FQTILE + row * FSTR + ch * 16,
                       gq[t] + (size_t)row * DD + ch * 8);
        }
    }

    const bf16* gkv[4] = {Kh + base, Kl + base, Vh + base, Vl + base};
    auto load_kv = [&](int kt, int st) {
        const uint32_t s0 = sbase + 2 * FQTILE + st * FSTAGEB;
        const size_t roff = (size_t)(kt * 64) * DD;
        #pragma unroll
        for (int p = 0; p < 8; p++) {
            int i = tid + p * 256;
            int t = i >> 9;
            int rem = i & 511;
            int row = rem >> 3;
            int ch = rem & 7;
            CP_ASYNC16(s0 + t * FKTILE + row * FSTR + ch * 16,
                       gkv[t] + roff + (size_t)row * DD + ch * 8);
        }
        CP_COMMIT();
    };

    load_kv(0, 0);

    const int qr = lane >> 2;
    const int ql2 = (lane & 3) * 2;
    const int lrow = lane & 15;
    const int lhalf = (lane >> 4) * 16;

    float oacc[8][4];
    #pragma unroll
    for (int nt = 0; nt < 8; nt++)
        #pragma unroll
        for (int j = 0; j < 4; j++) oacc[nt][j] = 0.f;
    float m0 = -CUDART_INF_F, m1 = -CUDART_INF_F;
    float l0 = 0.f, l1 = 0.f;

    const int wrow = w * 16;
    const int row0g = qt * 128 + wrow;
    const int nk = 2 * qt + 2;

    for (int kt = 0; kt < nk; kt++) {
        CP_WAIT(0);
        __syncthreads();
        if (kt + 1 < nk) load_kv(kt + 1, (kt + 1) & 1);

        // warp-level early-out: kv tile entirely above this warp's rows
        if (kt * 64 <= row0g + 15) {
            const uint32_t s0  = sbase + 2 * FQTILE + (kt & 1) * FSTAGEB;
            const uint32_t sQh = sbase, sQl = sbase + FQTILE;
            const uint32_t sKh = s0,             sKl = s0 + FKTILE;
            const uint32_t sVh = s0 + 2 * FKTILE, sVl = s0 + 3 * FKTILE;

            // ---- S = Q @ K^T (bf16x3), log2 units ----
            float sac[8][4];
            #pragma unroll
            for (int nt = 0; nt < 8; nt++)
                #pragma unroll
                for (int j = 0; j < 4; j++) sac[nt][j] = 0.f;

            #pragma unroll
            for (int kk = 0; kk < 4; kk++) {
                uint32_t aoff = (uint32_t)(wrow + lrow) * FSTR + lhalf + kk * 32;
                uint32_t qh_[4], ql_[4];
                ldsm_x4(qh_[0], qh_[1], qh_[2], qh_[3], sQh + aoff);
                ldsm_x4(ql_[0], ql_[1], ql_[2], ql_[3], sQl + aoff);
                #pragma unroll
                for (int ng = 0; ng < 4; ng++) {
                    uint32_t boff = (uint32_t)(ng * 16 + lrow) * FSTR + lhalf + kk * 32;
                    uint32_t kh_[4], kl_[4];
                    ldsm_x4(kh_[0], kh_[1], kh_[2], kh_[3], sKh + boff);
                    ldsm_x4(kl_[0], kl_[1], kl_[2], kl_[3], sKl + boff);
                    mma16816(sac[2 * ng],     qh_, kh_[0], kh_[2]);
                    mma16816(sac[2 * ng],     ql_, kh_[0], kh_[2]);
                    mma16816(sac[2 * ng],     qh_, kl_[0], kl_[2]);
                    mma16816(sac[2 * ng + 1], qh_, kh_[1], kh_[3]);
                    mma16816(sac[2 * ng + 1], ql_, kh_[1], kh_[3]);
                    mma16816(sac[2 * ng + 1], qh_, kl_[1], kl_[3]);
                }
            }

            // ---- causal mask when tile straddles this warp's diagonal ----
            if (kt * 64 + 63 > row0g) {
                const int r0 = row0g + qr, r1 = r0 + 8;
                #pragma unroll
                for (int nt = 0; nt < 8; nt++) {
                    int c = kt * 64 + nt * 8 + ql2;
                    if (c > r0)     sac[nt][0] = -CUDART_INF_F;
                    if (c + 1 > r0) sac[nt][1] = -CUDART_INF_F;
                    if (c > r1)     sac[nt][2] = -CUDART_INF_F;
                    if (c + 1 > r1) sac[nt][3] = -CUDART_INF_F;
                }
            }

            // ---- online softmax (base 2) ----
            float mx0 = -CUDART_INF_F, mx1 = -CUDART_INF_F;
            #pragma unroll
            for (int nt = 0; nt < 8; nt++) {
                mx0 = fmaxf(mx0, fmaxf(sac[nt][0], sac[nt][1]));
                mx1 = fmaxf(mx1, fmaxf(sac[nt][2], sac[nt][3]));
            }
            mx0 = fmaxf(mx0, __shfl_xor_sync(0xffffffffu, mx0, 1));
            mx0 = fmaxf(mx0, __shfl_xor_sync(0xffffffffu, mx0, 2));
            mx1 = fmaxf(mx1, __shfl_xor_sync(0xffffffffu, mx1, 1));
            mx1 = fmaxf(mx1, __shfl_xor_sync(0xffffffffu, mx1, 2));

            float mn0 = fmaxf(m0, mx0), mn1 = fmaxf(m1, mx1);
            float cr0 = exp2f(m0 - mn0), cr1 = exp2f(m1 - mn1);
            m0 = mn0; m1 = mn1;

            float ls0 = 0.f, ls1 = 0.f;
            #pragma unroll
            for (int nt = 0; nt < 8; nt++) {
                float p0 = exp2f(sac[nt][0] - m0);
                float p1 = exp2f(sac[nt][1] - m0);
                float p2 = exp2f(sac[nt][2] - m1);
                float p3 = exp2f(sac[nt][3] - m1);
                sac[nt][0] = p0; sac[nt][1] = p1; sac[nt][2] = p2; sac[nt][3] = p3;
                ls0 += p0 + p1;
                ls1 += p2 + p3;
            }
            ls0 += __shfl_xor_sync(0xffffffffu, ls0, 1);
            ls0 += __shfl_xor_sync(0xffffffffu, ls0, 2);
            ls1 += __shfl_xor_sync(0xffffffffu, ls1, 1);
            ls1 += __shfl_xor_sync(0xffffffffu, ls1, 2);
            l0 = l0 * cr0 + ls0;
            l1 = l1 * cr1 + ls1;

            #pragma unroll
            for (int nt = 0; nt < 8; nt++) {
                oacc[nt][0] *= cr0; oacc[nt][1] *= cr0;
                oacc[nt][2] *= cr1; oacc[nt][3] *= cr1;
            }

            // ---- O += P @ V (bf16x3, P from registers) ----
            #pragma unroll
            for (int kk = 0; kk < 4; kk++) {
                uint32_t ph_[4], pl_[4];
                {
                    uint32_t h0, lo0, h1, lo1, h2, lo2, h3, lo3;
                    split2(sac[2 * kk][0],     sac[2 * kk][1],     h0, lo0);
                    split2(sac[2 * kk][2],     sac[2 * kk][3],     h1, lo1);
                    split2(sac[2 * kk + 1][0], sac[2 * kk + 1][1], h2, lo2);
                    split2(sac[2 * kk + 1][2], sac[2 * kk + 1][3], h3, lo3);
                    ph_[0] = h0; ph_[1] = h1; ph_[2] = h2; ph_[3] = h3;
                    pl_[0] = lo0; pl_[1] = lo1; pl_[2] = lo2; pl_[3] = lo3;
                }
                #pragma unroll
                for (int ng = 0; ng < 4; ng++) {
                    uint32_t voff = (uint32_t)(kk * 16 + lrow) * FSTR + ng * 32 + lhalf;
                    uint32_t vh_[4], vl_[4];
                    ldsm_x4_t(vh_[0], vh_[1], vh_[2], vh_[3], sVh + voff);
                    ldsm_x4_t(vl_[0], vl_[1], vl_[2], vl_[3], sVl + voff);
                    mma16816(oacc[2 * ng],     ph_, vh_[0], vh_[1]);
                    mma16816(oacc[2 * ng],     pl_, vh_[0], vh_[1]);
                    mma16816(oacc[2 * ng],     ph_, vl_[0], vl_[1]);
                    mma16816(oacc[2 * ng + 1], ph_, vh_[2], vh_[3]);
                    mma16816(oacc[2 * ng + 1], pl_, vh_[2], vh_[3]);
                    mma16816(oacc[2 * ng + 1], ph_, vl_[2], vl_[3]);
                }
            }
        }
    }

    // ---- epilogue: normalize, split, store bf16 hi/lo ----
    const float inv0 = 1.0f / l0, inv1 = 1.0f / l1;
    const size_t orow0 = base + (size_t)(qt * 128 + wrow + qr) * DD;
    const size_t orow1 = orow0 + 8 * DD;
    #pragma unroll
    for (int nt = 0; nt < 8; nt++) {
        int d = nt * 8 + ql2;
        uint32_t h0, lo0, h1, lo1;
        split2(oacc[nt][0] * inv0, oacc[nt][1] * inv0, h0, lo0);
        split2(oacc[nt][2] * inv1, oacc[nt][3] * inv1, h1, lo1);
        *(uint32_t*)(Oh + orow0 + d) = h0;
        *(uint32_t*)(Ol + orow0 + d) = lo0;
        *(uint32_t*)(Oh + orow1 + d) = h1;
        *(uint32_t*)(Ol + orow1 + d) = lo1;
    }
}

// ============================================================
// Launch
// ============================================================
extern "C" void kernel_launch(void* const* d_in, const int* in_sizes, int n_in,
                              void* d_out, int out_size)
{
    const float* x  = (const float*)d_in[0];
    const float* Wq = (const float*)d_in[1];
    const float* Wk = (const float*)d_in[2];
    const float* Wv = (const float*)d_in[3];
    const float* Wo = (const float*)d_in[4];
    const float* bo = (const float*)d_in[5];
    float* out = (float*)d_out;

    bf16 *xh, *xl, *qkvh, *qkvl, *wqkvh, *wqkvl, *woh, *wol;
    cudaGetSymbolAddress((void**)&xh, g_xh);
    cudaGetSymbolAddress((void**)&xl, g_xl);
    cudaGetSymbolAddress((void**)&qkvh, g_qkvh);
    cudaGetSymbolAddress((void**)&qkvl, g_qkvl);
    cudaGetSymbolAddress((void**)&wqkvh, g_wqkvh);
    cudaGetSymbolAddress((void**)&wqkvl, g_wqkvl);
    cudaGetSymbolAddress((void**)&woh, g_woh);
    cudaGetSymbolAddress((void**)&wol, g_wol);

    // 1. split x
    const int n4 = MTOK * DD / 4;
    split_kernel<<<n4 / 256, 256>>>(x, xh, xl, n4);

    // 2. fused transpose+split of all 4 weights
    transpose_split4_kernel<<<dim3(DD / 32, DD / 32, 4), dim3(32, 8)>>>(
        Wq, Wk, Wv, Wo, wqkvh, wqkvl, woh, wol);

    // 3. fused QKV projection (single launch, N=3072)
    const float qscale = 0.125f * 1.4426950408889634f;
    cudaFuncSetAttribute(gemm_mma_kernel,
                         cudaFuncAttributeMaxDynamicSharedMemorySize, GSMEM);
    gemm_mma_kernel<<<dim3(24, MTOK / 128), 256, GSMEM>>>(
        xh, xl, wqkvh, wqkvl, nullptr, nullptr, qkvh, qkvl, qscale);

    // 4. flash attention (128-row CTA tiles, 8 warps); writes hi/lo into xh/xl
    const size_t seg = (size_t)MTOK * DD;
    cudaFuncSetAttribute(flash_mma_kernel,
                         cudaFuncAttributeMaxDynamicSharedMemorySize, FSMEM);
    flash_mma_kernel<<<dim3(SS / 128, HH, BB), 256, FSMEM>>>(
        qkvh, qkvl, qkvh + seg, qkvl + seg, qkvh + 2 * seg, qkvl + 2 * seg,
        xh, xl);

    // 5. output projection (+bias), fp32 out
    gemm_mma_kernel<<<dim3(8, MTOK / 128), 256, GSMEM>>>(
        xh, xl, woh, wol, bo, out, nullptr, nullptr, 1.0f);
}

// round 9
// speedup vs baseline: 4.3997x; 1.4188x over previous
#include <cuda_runtime.h>
#include <cuda_fp16.h>
#include <math_constants.h>
#include <cstdint>

// Problem constants
#define BB 4
#define SS 2048
#define DD 1024
#define HH 16
#define HDIM 64
#define MTOK (BB * SS)   // 8192
#define GK DD            // GEMM K = 1024

typedef __half fp16;

// ---------------- scratch (__device__ globals; allocation-free rule) -------
__device__ fp16 g_xh[MTOK * DD], g_xl[MTOK * DD];       // x split; reused for attn out
__device__ fp16 g_qkvh[3 * MTOK * DD], g_qkvl[3 * MTOK * DD];
__device__ fp16 g_wqkvh[3 * DD * DD];                   // Wq|Wk|Wv transposed, fp16 hi
__device__ fp16 g_woh[DD * DD];

// ---------------- helpers (plain sm_90-era PTX only) ------------------------
__device__ __forceinline__ uint32_t smem_u32(const void* p) {
    uint32_t a;
    asm("{ .reg .u64 t; cvta.to.shared.u64 t, %1; cvt.u32.u64 %0, t; }"
        : "=r"(a) : "l"(p));
    return a;
}
__device__ __forceinline__ void ldsm_x4(uint32_t& r0, uint32_t& r1,
                                        uint32_t& r2, uint32_t& r3, uint32_t addr) {
    asm volatile("ldmatrix.sync.aligned.m8n8.x4.shared.b16 {%0,%1,%2,%3}, [%4];"
                 : "=r"(r0), "=r"(r1), "=r"(r2), "=r"(r3) : "r"(addr));
}
__device__ __forceinline__ void ldsm_x4_t(uint32_t& r0, uint32_t& r1,
                                          uint32_t& r2, uint32_t& r3, uint32_t addr) {
    asm volatile("ldmatrix.sync.aligned.m8n8.x4.trans.shared.b16 {%0,%1,%2,%3}, [%4];"
                 : "=r"(r0), "=r"(r1), "=r"(r2), "=r"(r3) : "r"(addr));
}
__device__ __forceinline__ void mma16816(float* c, const uint32_t* a,
                                         uint32_t b0, uint32_t b1) {
    asm volatile(
        "mma.sync.aligned.m16n8k16.row.col.f32.f16.f16.f32 "
        "{%0,%1,%2,%3}, {%4,%5,%6,%7}, {%8,%9}, {%0,%1,%2,%3};"
        : "+f"(c[0]), "+f"(c[1]), "+f"(c[2]), "+f"(c[3])
        : "r"(a[0]), "r"(a[1]), "r"(a[2]), "r"(a[3]), "r"(b0), "r"(b1));
}
#define CP_ASYNC16(saddr, gaddr) \
    asm volatile("cp.async.cg.shared.global [%0], [%1], 16;" :: "r"(saddr), "l"(gaddr))
#define CP_COMMIT() asm volatile("cp.async.commit_group;" ::: "memory")
#define CP_WAIT(n)  asm volatile("cp.async.wait_group %0;" :: "n"(n) : "memory")

// SW64 swizzle: permutes 16B chunks within the 128B bank period
#define SW64(off) ((off) ^ (((off) >> 3) & 0x30))

// split two fp32 into packed fp16 hi / packed fp16 residual-lo
__device__ __forceinline__ void split2h(float a, float b, uint32_t& hi, uint32_t& lo) {
    __half ha = __float2half_rn(a), hb = __float2half_rn(b);
    __half2 hh = __halves2half2(ha, hb);
    hi = *reinterpret_cast<uint32_t*>(&hh);
    __half2 ll = __floats2half2_rn(a - __half2float(ha), b - __half2float(hb));
    lo = *reinterpret_cast<uint32_t*>(&ll);
}

// ============================================================
// split: fp32 -> fp16 hi + fp16 lo (residual)   [for input x]
// ============================================================
__global__ __launch_bounds__(256) void split_kernel(
    const float* __restrict__ in, fp16* __restrict__ hi,
    fp16* __restrict__ lo, int n4)
{
    int i = blockIdx.x * blockDim.x + threadIdx.x;
    if (i >= n4) return;
    float4 v = reinterpret_cast<const float4*>(in)[i];
    uint32_t h0, l0, h1, l1;
    split2h(v.x, v.y, h0, l0);
    split2h(v.z, v.w, h1, l1);
    uint2 hh, ll;
    hh.x = h0; hh.y = h1;
    ll.x = l0; ll.y = l1;
    reinterpret_cast<uint2*>(hi)[i] = hh;
    reinterpret_cast<uint2*>(lo)[i] = ll;
}

// ============================================================
// fused transpose of all 4 weights -> fp16 hi only
// ============================================================
__global__ __launch_bounds__(256) void transpose_split4_kernel(
    const float* __restrict__ Wq, const float* __restrict__ Wk,
    const float* __restrict__ Wv, const float* __restrict__ Wo,
    fp16* __restrict__ Wqkvh, fp16* __restrict__ Woh)
{
    __shared__ float t[32][33];
    const int z = blockIdx.z;
    const float* W = (z == 0) ? Wq : (z == 1) ? Wk : (z == 2) ? Wv : Wo;
    fp16* Th = (z < 3) ? Wqkvh + (size_t)z * DD * DD : Woh;

    const int bx = blockIdx.x, by = blockIdx.y;
    const int x = threadIdx.x, y = threadIdx.y;  // 32 x 8
    #pragma unroll
    for (int i = 0; i < 4; i++)
        t[y + 8 * i][x] = W[(size_t)(by * 32 + y + 8 * i) * DD + bx * 32 + x];
    __syncthreads();
    #pragma unroll
    for (int i = 0; i < 4; i++) {
        float v = t[x][y + 8 * i];
        Th[(size_t)(bx * 32 + y + 8 * i) * DD + by * 32 + x] = __float2half_rn(v);
    }
}

// ============================================================
// fp16x2 GEMM on mma.sync: C = (Ah+Al)[M,K] @ Bh[N,K]^T.
// 4-stage cp.async pipeline, SW64 swizzle, 1 barrier/chunk.
// ============================================================
#define CHK 32
#define GTILE 8192               // 128 rows x 64 B
#define GSTAGE (3 * GTILE)       // Ah, Al, Bh = 24576 B
#define GSMEM (4 * GSTAGE)       // 98304 B

__global__ __launch_bounds__(256, 2) void gemm_mma_kernel(
    const fp16* __restrict__ Ah, const fp16* __restrict__ Al,
    const fp16* __restrict__ Bh,
    const float* __restrict__ bias, float* __restrict__ Cf,
    fp16* __restrict__ Ch, fp16* __restrict__ Cl, float qscale)
{
    extern __shared__ __align__(1024) char dsm[];
    const uint32_t sbase = smem_u32(dsm);

    const int tid = threadIdx.x;
    const int lane = tid & 31;
    const int wid = tid >> 5;
    const int warp_m = wid & 3;
    const int warp_n = wid >> 2;
    const int br = blockIdx.y, bc = blockIdx.x;

    const fp16* gsrc[3] = {
        Ah + (size_t)(br * 128) * GK, Al + (size_t)(br * 128) * GK,
        Bh + (size_t)(bc * 128) * GK
    };

    auto load_stage = [&](int k0, int st) {
        const uint32_t s0 = sbase + st * GSTAGE;
        #pragma unroll
        for (int p = 0; p < 6; p++) {
            int idx = tid + p * 256;        // 0..1535
            int t   = idx >> 9;
            int rem = idx & 511;
            int row = rem >> 2;
            int ch  = rem & 3;
            uint32_t sa = s0 + t * GTILE + SW64((uint32_t)(row * 64 + ch * 16));
            const fp16* g = gsrc[t] + (size_t)row * GK + k0 + ch * 8;
            CP_ASYNC16(sa, g);
        }
        CP_COMMIT();
    };

    float acc[2][8][4];
    #pragma unroll
    for (int mt = 0; mt < 2; mt++)
        #pragma unroll
        for (int nt = 0; nt < 8; nt++)
            #pragma unroll
            for (int j = 0; j < 4; j++) acc[mt][nt][j] = 0.f;

    const int NC = GK / CHK;   // 32
    load_stage(0, 0);
    load_stage(CHK, 1);
    load_stage(2 * CHK, 2);

    const int lrow = lane & 15;
    const int lsel = (lane >> 4) * 16;

    int st = 0;
    for (int c = 0; c < NC; c++) {
        if (c <= NC - 3)      { CP_WAIT(2); }
        else if (c == NC - 2) { CP_WAIT(1); }
        else                  { CP_WAIT(0); }
        __syncthreads();
        if (c + 3 < NC) load_stage((c + 3) * CHK, (c + 3) & 3);

        const uint32_t s0  = sbase + st * GSTAGE;
        const uint32_t sAh = s0, sAl = s0 + GTILE, sBh = s0 + 2 * GTILE;

        #pragma unroll
        for (int kk = 0; kk < 2; kk++) {
            const int lcol = lsel + kk * 32;
            uint32_t ah[2][4], al[2][4];
            #pragma unroll
            for (int mt = 0; mt < 2; mt++) {
                uint32_t off = SW64((uint32_t)((warp_m * 32 + mt * 16 + lrow) * 64 + lcol));
                ldsm_x4(ah[mt][0], ah[mt][1], ah[mt][2], ah[mt][3], sAh + off);
                ldsm_x4(al[mt][0], al[mt][1], al[mt][2], al[mt][3], sAl + off);
            }
            #pragma unroll
            for (int ng = 0; ng < 4; ng++) {
                uint32_t off = SW64((uint32_t)((warp_n * 64 + ng * 16 + lrow) * 64 + lcol));
                uint32_t bh[4];
                ldsm_x4(bh[0], bh[1], bh[2], bh[3], sBh + off);
                #pragma unroll
                for (int mt = 0; mt < 2; mt++) {
                    mma16816(acc[mt][2 * ng],     ah[mt], bh[0], bh[2]);
                    mma16816(acc[mt][2 * ng],     al[mt], bh[0], bh[2]);
                    mma16816(acc[mt][2 * ng + 1], ah[mt], bh[1], bh[3]);
                    mma16816(acc[mt][2 * ng + 1], al[mt], bh[1], bh[3]);
                }
            }
        }
        if (++st == 4) st = 0;
    }

    const int row0 = br * 128 + warp_m * 32;
    const int col0 = (bc & 7) * 128 + warp_n * 64;
    const int qr = lane >> 2;
    const int qc = (lane & 3) * 2;

    if (Cf) {
        #pragma unroll
        for (int mt = 0; mt < 2; mt++) {
            #pragma unroll
            for (int nt = 0; nt < 8; nt++) {
                int col = col0 + nt * 8 + qc;
                float b0 = 0.f, b1 = 0.f;
                if (bias) { b0 = bias[col]; b1 = bias[col + 1]; }
                size_t o0 = (size_t)(row0 + mt * 16 + qr) * DD + col;
                size_t o1 = o0 + 8 * DD;
                float2 w0, w1;
                w0.x = acc[mt][nt][0] + b0; w0.y = acc[mt][nt][1] + b1;
                w1.x = acc[mt][nt][2] + b0; w1.y = acc[mt][nt][3] + b1;
                *(float2*)(Cf + o0) = w0;
                *(float2*)(Cf + o1) = w1;
            }
        }
    } else {
        const int sel = bc >> 3;                 // 0=Q 1=K 2=V
        const float scale = (sel == 0) ? qscale : 1.0f;
        fp16* Chs = Ch + (size_t)sel * MTOK * DD;
        fp16* Cls = Cl + (size_t)sel * MTOK * DD;
        #pragma unroll
        for (int mt = 0; mt < 2; mt++) {
            #pragma unroll
            for (int nt = 0; nt < 8; nt++) {
                int col = col0 + nt * 8 + qc;
                size_t o0 = (size_t)(row0 + mt * 16 + qr) * DD + col;
                size_t o1 = o0 + 8 * DD;
                uint32_t h0, l0, h1, l1;
                split2h(acc[mt][nt][0] * scale, acc[mt][nt][1] * scale, h0, l0);
                split2h(acc[mt][nt][2] * scale, acc[mt][nt][3] * scale, h1, l1);
                *(uint32_t*)(Chs + o0) = h0;
                *(uint32_t*)(Cls + o0) = l0;
                *(uint32_t*)(Chs + o1) = h1;
                *(uint32_t*)(Cls + o1) = l1;
            }
        }
    }
}

// ============================================================
// Flash attention (causal) on mma.sync, fp16x2, base-2 softmax.
// CTA: 256 threads / 8 warps; tile 128 q-rows x 64 kv.
// K, V single-stream fp16; Q, P hi+lo. qt reversed for tail pack.
// ============================================================
#define FSTR 144
#define FKTILE (64 * FSTR)            // 9216 B
#define FQTILE (128 * FSTR)           // 18432 B
#define FSTAGEB (2 * FKTILE)          // Kh, Vh = 18432 B
#define FSMEM (2 * FQTILE + 2 * FSTAGEB)  // 73728 B

__global__ __launch_bounds__(256, 2) void flash_mma_kernel(
    const fp16* __restrict__ Qh, const fp16* __restrict__ Ql,
    const fp16* __restrict__ Kh, const fp16* __restrict__ Vh,
    fp16* __restrict__ Oh, fp16* __restrict__ Ol)
{
    extern __shared__ __align__(1024) char dsm[];
    const uint32_t sbase = smem_u32(dsm);

    const int tid = threadIdx.x;
    const int lane = tid & 31;
    const int w = tid >> 5;                 // 0..7
    const int qt = (int)gridDim.x - 1 - (int)blockIdx.x;   // big tiles first
    const int h = blockIdx.y, b = blockIdx.z;

    const size_t base = ((size_t)b * SS) * DD + (size_t)h * HDIM;
    const fp16* gq[2] = {Qh + base + (size_t)(qt * 128) * DD,
                         Ql + base + (size_t)(qt * 128) * DD};

    // ---- load Q (hi/lo, 128 rows), grouped with kv stage0 ----
    {
        #pragma unroll
        for (int p = 0; p < 8; p++) {
            int i = tid + p * 256;
            int t = i >> 10;
            int rem = i & 1023;
            int row = rem >> 3;
            int ch = rem & 7;
            CP_ASYNC16(sbase + t * FQTILE + row * FSTR + ch * 16,
                       gq[t] + (size_t)row * DD + ch * 8);
        }
    }

    const fp16* gkv[2] = {Kh + base, Vh + base};
    auto load_kv = [&](int kt, int st) {
        const uint32_t s0 = sbase + 2 * FQTILE + st * FSTAGEB;
        const size_t roff = (size_t)(kt * 64) * DD;
        #pragma unroll
        for (int p = 0; p < 4; p++) {
            int i = tid + p * 256;          // 0..1023
            int t = i >> 9;
            int rem = i & 511;
            int row = rem >> 3;
            int ch = rem & 7;
            CP_ASYNC16(s0 + t * FKTILE + row * FSTR + ch * 16,
                       gkv[t] + roff + (size_t)row * DD + ch * 8);
        }
        CP_COMMIT();
    };

    load_kv(0, 0);

    const int qr = lane >> 2;
    const int ql2 = (lane & 3) * 2;
    const int lrow = lane & 15;
    const int lhalf = (lane >> 4) * 16;

    float oacc[8][4];
    #pragma unroll
    for (int nt = 0; nt < 8; nt++)
        #pragma unroll
        for (int j = 0; j < 4; j++) oacc[nt][j] = 0.f;
    float m0 = -CUDART_INF_F, m1 = -CUDART_INF_F;
    float l0 = 0.f, l1 = 0.f;

    const int wrow = w * 16;
    const int row0g = qt * 128 + wrow;
    const int nk = 2 * qt + 2;

    for (int kt = 0; kt < nk; kt++) {
        CP_WAIT(0);
        __syncthreads();
        if (kt + 1 < nk) load_kv(kt + 1, (kt + 1) & 1);

        if (kt * 64 <= row0g + 15) {      // warp early-out
            const uint32_t s0  = sbase + 2 * FQTILE + (kt & 1) * FSTAGEB;
            const uint32_t sQh = sbase, sQl = sbase + FQTILE;
            const uint32_t sKh = s0, sVh = s0 + FKTILE;

            // ---- S = Q @ K^T (fp16x2: Qh·Kh + Ql·Kh), log2 units ----
            float sac[8][4];
            #pragma unroll
            for (int nt = 0; nt < 8; nt++)
                #pragma unroll
                for (int j = 0; j < 4; j++) sac[nt][j] = 0.f;

            #pragma unroll
            for (int kk = 0; kk < 4; kk++) {
                uint32_t aoff = (uint32_t)(wrow + lrow) * FSTR + lhalf + kk * 32;
                uint32_t qh_[4], ql_[4];
                ldsm_x4(qh_[0], qh_[1], qh_[2], qh_[3], sQh + aoff);
                ldsm_x4(ql_[0], ql_[1], ql_[2], ql_[3], sQl + aoff);
                #pragma unroll
                for (int ng = 0; ng < 4; ng++) {
                    uint32_t boff = (uint32_t)(ng * 16 + lrow) * FSTR + lhalf + kk * 32;
                    uint32_t kh_[4];
                    ldsm_x4(kh_[0], kh_[1], kh_[2], kh_[3], sKh + boff);
                    mma16816(sac[2 * ng],     qh_, kh_[0], kh_[2]);
                    mma16816(sac[2 * ng],     ql_, kh_[0], kh_[2]);
                    mma16816(sac[2 * ng + 1], qh_, kh_[1], kh_[3]);
                    mma16816(sac[2 * ng + 1], ql_, kh_[1], kh_[3]);
                }
            }

            // ---- causal mask when tile straddles this warp's diagonal ----
            if (kt * 64 + 63 > row0g) {
                const int r0 = row0g + qr, r1 = r0 + 8;
                #pragma unroll
                for (int nt = 0; nt < 8; nt++) {
                    int c = kt * 64 + nt * 8 + ql2;
                    if (c > r0)     sac[nt][0] = -CUDART_INF_F;
                    if (c + 1 > r0) sac[nt][1] = -CUDART_INF_F;
                    if (c > r1)     sac[nt][2] = -CUDART_INF_F;
                    if (c + 1 > r1) sac[nt][3] = -CUDART_INF_F;
                }
            }

            // ---- online softmax (base 2) ----
            float mx0 = -CUDART_INF_F, mx1 = -CUDART_INF_F;
            #pragma unroll
            for (int nt = 0; nt < 8; nt++) {
                mx0 = fmaxf(mx0, fmaxf(sac[nt][0], sac[nt][1]));
                mx1 = fmaxf(mx1, fmaxf(sac[nt][2], sac[nt][3]));
            }
            mx0 = fmaxf(mx0, __shfl_xor_sync(0xffffffffu, mx0, 1));
            mx0 = fmaxf(mx0, __shfl_xor_sync(0xffffffffu, mx0, 2));
            mx1 = fmaxf(mx1, __shfl_xor_sync(0xffffffffu, mx1, 1));
            mx1 = fmaxf(mx1, __shfl_xor_sync(0xffffffffu, mx1, 2));

            float mn0 = fmaxf(m0, mx0), mn1 = fmaxf(m1, mx1);
            float cr0 = exp2f(m0 - mn0), cr1 = exp2f(m1 - mn1);
            m0 = mn0; m1 = mn1;

            float ls0 = 0.f, ls1 = 0.f;
            #pragma unroll
            for (int nt = 0; nt < 8; nt++) {
                float p0 = exp2f(sac[nt][0] - m0);
                float p1 = exp2f(sac[nt][1] - m0);
                float p2 = exp2f(sac[nt][2] - m1);
                float p3 = exp2f(sac[nt][3] - m1);
                sac[nt][0] = p0; sac[nt][1] = p1; sac[nt][2] = p2; sac[nt][3] = p3;
                ls0 += p0 + p1;
                ls1 += p2 + p3;
            }
            ls0 += __shfl_xor_sync(0xffffffffu, ls0, 1);
            ls0 += __shfl_xor_sync(0xffffffffu, ls0, 2);
            ls1 += __shfl_xor_sync(0xffffffffu, ls1, 1);
            ls1 += __shfl_xor_sync(0xffffffffu, ls1, 2);
            l0 = l0 * cr0 + ls0;
            l1 = l1 * cr1 + ls1;

            #pragma unroll
            for (int nt = 0; nt < 8; nt++) {
                oacc[nt][0] *= cr0; oacc[nt][1] *= cr0;
                oacc[nt][2] *= cr1; oacc[nt][3] *= cr1;
            }

            // ---- O += P @ V (fp16x2: Ph·Vh + Pl·Vh) ----
            #pragma unroll
            for (int kk = 0; kk < 4; kk++) {
                uint32_t ph_[4], pl_[4];
                {
                    uint32_t h0, lo0, h1, lo1, h2, lo2, h3, lo3;
                    split2h(sac[2 * kk][0],     sac[2 * kk][1],     h0, lo0);
                    split2h(sac[2 * kk][2],     sac[2 * kk][3],     h1, lo1);
                    split2h(sac[2 * kk + 1][0], sac[2 * kk + 1][1], h2, lo2);
                    split2h(sac[2 * kk + 1][2], sac[2 * kk + 1][3], h3, lo3);
                    ph_[0] = h0; ph_[1] = h1; ph_[2] = h2; ph_[3] = h3;
                    pl_[0] = lo0; pl_[1] = lo1; pl_[2] = lo2; pl_[3] = lo3;
                }
                #pragma unroll
                for (int ng = 0; ng < 4; ng++) {
                    uint32_t voff = (uint32_t)(kk * 16 + lrow) * FSTR + ng * 32 + lhalf;
                    uint32_t vh_[4];
                    ldsm_x4_t(vh_[0], vh_[1], vh_[2], vh_[3], sVh + voff);
                    mma16816(oacc[2 * ng],     ph_, vh_[0], vh_[1]);
                    mma16816(oacc[2 * ng],     pl_, vh_[0], vh_[1]);
                    mma16816(oacc[2 * ng + 1], ph_, vh_[2], vh_[3]);
                    mma16816(oacc[2 * ng + 1], pl_, vh_[2], vh_[3]);
                }
            }
        }
    }

    // ---- epilogue: normalize, split, store fp16 hi/lo ----
    const float inv0 = 1.0f / l0, inv1 = 1.0f / l1;
    const size_t orow0 = base + (size_t)(qt * 128 + wrow + qr) * DD;
    const size_t orow1 = orow0 + 8 * DD;
    #pragma unroll
    for (int nt = 0; nt < 8; nt++) {
        int d = nt * 8 + ql2;
        uint32_t h0, lo0, h1, lo1;
        split2h(oacc[nt][0] * inv0, oacc[nt][1] * inv0, h0, lo0);
        split2h(oacc[nt][2] * inv1, oacc[nt][3] * inv1, h1, lo1);
        *(uint32_t*)(Oh + orow0 + d) = h0;
        *(uint32_t*)(Ol + orow0 + d) = lo0;
        *(uint32_t*)(Oh + orow1 + d) = h1;
        *(uint32_t*)(Ol + orow1 + d) = lo1;
    }
}

// ============================================================
// Launch
// ============================================================
extern "C" void kernel_launch(void* const* d_in, const int* in_sizes, int n_in,
                              void* d_out, int out_size)
{
    const float* x  = (const float*)d_in[0];
    const float* Wq = (const float*)d_in[1];
    const float* Wk = (const float*)d_in[2];
    const float* Wv = (const float*)d_in[3];
    const float* Wo = (const float*)d_in[4];
    const float* bo = (const float*)d_in[5];
    float* out = (float*)d_out;

    fp16 *xh, *xl, *qkvh, *qkvl, *wqkvh, *woh;
    cudaGetSymbolAddress((void**)&xh, g_xh);
    cudaGetSymbolAddress((void**)&xl, g_xl);
    cudaGetSymbolAddress((void**)&qkvh, g_qkvh);
    cudaGetSymbolAddress((void**)&qkvl, g_qkvl);
    cudaGetSymbolAddress((void**)&wqkvh, g_wqkvh);
    cudaGetSymbolAddress((void**)&woh, g_woh);

    // 1. split x -> fp16 hi/lo
    const int n4 = MTOK * DD / 4;
    split_kernel<<<n4 / 256, 256>>>(x, xh, xl, n4);

    // 2. fused transpose of all 4 weights -> fp16 hi
    transpose_split4_kernel<<<dim3(DD / 32, DD / 32, 4), dim3(32, 8)>>>(
        Wq, Wk, Wv, Wo, wqkvh, woh);

    // 3. fused QKV projection (single launch, N=3072)
    const float qscale = 0.125f * 1.4426950408889634f;
    cudaFuncSetAttribute(gemm_mma_kernel,
                         cudaFuncAttributeMaxDynamicSharedMemorySize, GSMEM);
    gemm_mma_kernel<<<dim3(24, MTOK / 128), 256, GSMEM>>>(
        xh, xl, wqkvh, nullptr, nullptr, qkvh, qkvl, qscale);

    // 4. flash attention; writes hi/lo into xh/xl
    const size_t seg = (size_t)MTOK * DD;
    cudaFuncSetAttribute(flash_mma_kernel,
                         cudaFuncAttributeMaxDynamicSharedMemorySize, FSMEM);
    flash_mma_kernel<<<dim3(SS / 128, HH, BB), 256, FSMEM>>>(
        qkvh, qkvl, qkvh + seg, qkvh + 2 * seg,   // Qh, Ql, Kh, Vh
        xh, xl);

    // 5. output projection (+bias), fp32 out
    gemm_mma_kernel<<<dim3(8, MTOK / 128), 256, GSMEM>>>(
        xh, xl, woh, bo, out, nullptr, nullptr, 1.0f);
}

// round 10
// speedup vs baseline: 5.1532x; 1.1712x over previous
#include <cuda_runtime.h>
#include <cuda_fp16.h>
#include <math_constants.h>
#include <cstdint>

// Problem constants
#define BB 4
#define SS 2048
#define DD 1024
#define HH 16
#define HDIM 64
#define MTOK (BB * SS)   // 8192
#define GK DD            // GEMM K = 1024

typedef __half fp16;

// ---------------- scratch (__device__ globals; allocation-free rule) -------
__device__ fp16 g_xh[MTOK * DD], g_xl[MTOK * DD];       // x split; reused for attn out
__device__ fp16 g_qkvh[3 * MTOK * DD];                  // Q|K|V (hi only)
__device__ fp16 g_wqkvh[3 * DD * DD];                   // Wq|Wk|Wv transposed, fp16 hi
__device__ fp16 g_woh[DD * DD];

// ---------------- helpers (plain sm_90-era PTX only) ------------------------
__device__ __forceinline__ uint32_t smem_u32(const void* p) {
    uint32_t a;
    asm("{ .reg .u64 t; cvta.to.shared.u64 t, %1; cvt.u32.u64 %0, t; }"
        : "=r"(a) : "l"(p));
    return a;
}
__device__ __forceinline__ void ldsm_x4(uint32_t& r0, uint32_t& r1,
                                        uint32_t& r2, uint32_t& r3, uint32_t addr) {
    asm volatile("ldmatrix.sync.aligned.m8n8.x4.shared.b16 {%0,%1,%2,%3}, [%4];"
                 : "=r"(r0), "=r"(r1), "=r"(r2), "=r"(r3) : "r"(addr));
}
__device__ __forceinline__ void ldsm_x4_t(uint32_t& r0, uint32_t& r1,
                                          uint32_t& r2, uint32_t& r3, uint32_t addr) {
    asm volatile("ldmatrix.sync.aligned.m8n8.x4.trans.shared.b16 {%0,%1,%2,%3}, [%4];"
                 : "=r"(r0), "=r"(r1), "=r"(r2), "=r"(r3) : "r"(addr));
}
__device__ __forceinline__ void mma16816(float* c, const uint32_t* a,
                                         uint32_t b0, uint32_t b1) {
    asm volatile(
        "mma.sync.aligned.m16n8k16.row.col.f32.f16.f16.f32 "
        "{%0,%1,%2,%3}, {%4,%5,%6,%7}, {%8,%9}, {%0,%1,%2,%3};"
        : "+f"(c[0]), "+f"(c[1]), "+f"(c[2]), "+f"(c[3])
        : "r"(a[0]), "r"(a[1]), "r"(a[2]), "r"(a[3]), "r"(b0), "r"(b1));
}
#define CP_ASYNC16(saddr, gaddr) \
    asm volatile("cp.async.cg.shared.global [%0], [%1], 16;" :: "r"(saddr), "l"(gaddr))
#define CP_COMMIT() asm volatile("cp.async.commit_group;" ::: "memory")
#define CP_WAIT(n)  asm volatile("cp.async.wait_group %0;" :: "n"(n) : "memory")

// SW64 swizzle: permutes 16B chunks within the 128B bank period
#define SW64(off) ((off) ^ (((off) >> 3) & 0x30))

__device__ __forceinline__ uint32_t pack2h(float a, float b) {
    __half2 t = __floats2half2_rn(a, b);
    return *reinterpret_cast<uint32_t*>(&t);
}
// split two fp32 into packed fp16 hi / packed fp16 residual-lo
__device__ __forceinline__ void split2h(float a, float b, uint32_t& hi, uint32_t& lo) {
    __half ha = __float2half_rn(a), hb = __float2half_rn(b);
    __half2 hh = __halves2half2(ha, hb);
    hi = *reinterpret_cast<uint32_t*>(&hh);
    lo = pack2h(a - __half2float(ha), b - __half2float(hb));
}

// ============================================================
// split: fp32 -> fp16 hi + fp16 lo (residual)   [for input x]
// ============================================================
__global__ __launch_bounds__(256) void split_kernel(
    const float* __restrict__ in, fp16* __restrict__ hi,
    fp16* __restrict__ lo, int n4)
{
    int i = blockIdx.x * blockDim.x + threadIdx.x;
    if (i >= n4) return;
    float4 v = reinterpret_cast<const float4*>(in)[i];
    uint32_t h0, l0, h1, l1;
    split2h(v.x, v.y, h0, l0);
    split2h(v.z, v.w, h1, l1);
    uint2 hh, ll;
    hh.x = h0; hh.y = h1;
    ll.x = l0; ll.y = l1;
    reinterpret_cast<uint2*>(hi)[i] = hh;
    reinterpret_cast<uint2*>(lo)[i] = ll;
}

// ============================================================
// fused transpose of all 4 weights -> fp16 hi only
// ============================================================
__global__ __launch_bounds__(256) void transpose_split4_kernel(
    const float* __restrict__ Wq, const float* __restrict__ Wk,
    const float* __restrict__ Wv, const float* __restrict__ Wo,
    fp16* __restrict__ Wqkvh, fp16* __restrict__ Woh)
{
    __shared__ float t[32][33];
    const int z = blockIdx.z;
    const float* W = (z == 0) ? Wq : (z == 1) ? Wk : (z == 2) ? Wv : Wo;
    fp16* Th = (z < 3) ? Wqkvh + (size_t)z * DD * DD : Woh;

    const int bx = blockIdx.x, by = blockIdx.y;
    const int x = threadIdx.x, y = threadIdx.y;  // 32 x 8
    #pragma unroll
    for (int i = 0; i < 4; i++)
        t[y + 8 * i][x] = W[(size_t)(by * 32 + y + 8 * i) * DD + bx * 32 + x];
    __syncthreads();
    #pragma unroll
    for (int i = 0; i < 4; i++) {
        float v = t[x][y + 8 * i];
        Th[(size_t)(bx * 32 + y + 8 * i) * DD + by * 32 + x] = __float2half_rn(v);
    }
}

// ============================================================
// fp16x2 GEMM on mma.sync: C = (Ah+Al)[M,K] @ Bh[N,K]^T.
// 4-stage cp.async pipeline, SW64 swizzle, 1 barrier/chunk.
// QKV mode: hi-only fp16 outputs into Q|K|V segments.
// ============================================================
#define CHK 32
#define GTILE 8192               // 128 rows x 64 B
#define GSTAGE (3 * GTILE)       // Ah, Al, Bh = 24576 B
#define GSMEM (4 * GSTAGE)       // 98304 B

__global__ __launch_bounds__(256, 2) void gemm_mma_kernel(
    const fp16* __restrict__ Ah, const fp16* __restrict__ Al,
    const fp16* __restrict__ Bh,
    const float* __restrict__ bias, float* __restrict__ Cf,
    fp16* __restrict__ Ch, float qscale)
{
    extern __shared__ __align__(1024) char dsm[];
    const uint32_t sbase = smem_u32(dsm);

    const int tid = threadIdx.x;
    const int lane = tid & 31;
    const int wid = tid >> 5;
    const int warp_m = wid & 3;
    const int warp_n = wid >> 2;
    const int br = blockIdx.y, bc = blockIdx.x;

    const fp16* gsrc[3] = {
        Ah + (size_t)(br * 128) * GK, Al + (size_t)(br * 128) * GK,
        Bh + (size_t)(bc * 128) * GK
    };

    auto load_stage = [&](int k0, int st) {
        const uint32_t s0 = sbase + st * GSTAGE;
        #pragma unroll
        for (int p = 0; p < 6; p++) {
            int idx = tid + p * 256;        // 0..1535
            int t   = idx >> 9;
            int rem = idx & 511;
            int row = rem >> 2;
            int ch  = rem & 3;
            uint32_t sa = s0 + t * GTILE + SW64((uint32_t)(row * 64 + ch * 16));
            const fp16* g = gsrc[t] + (size_t)row * GK + k0 + ch * 8;
            CP_ASYNC16(sa, g);
        }
        CP_COMMIT();
    };

    float acc[2][8][4];
    #pragma unroll
    for (int mt = 0; mt < 2; mt++)
        #pragma unroll
        for (int nt = 0; nt < 8; nt++)
            #pragma unroll
            for (int j = 0; j < 4; j++) acc[mt][nt][j] = 0.f;

    const int NC = GK / CHK;   // 32
    load_stage(0, 0);
    load_stage(CHK, 1);
    load_stage(2 * CHK, 2);

    const int lrow = lane & 15;
    const int lsel = (lane >> 4) * 16;

    int st = 0;
    for (int c = 0; c < NC; c++) {
        if (c <= NC - 3)      { CP_WAIT(2); }
        else if (c == NC - 2) { CP_WAIT(1); }
        else                  { CP_WAIT(0); }
        __syncthreads();
        if (c + 3 < NC) load_stage((c + 3) * CHK, (c + 3) & 3);

        const uint32_t s0  = sbase + st * GSTAGE;
        const uint32_t sAh = s0, sAl = s0 + GTILE, sBh = s0 + 2 * GTILE;

        #pragma unroll
        for (int kk = 0; kk < 2; kk++) {
            const int lcol = lsel + kk * 32;
            uint32_t ah[2][4], al[2][4];
            #pragma unroll
            for (int mt = 0; mt < 2; mt++) {
                uint32_t off = SW64((uint32_t)((warp_m * 32 + mt * 16 + lrow) * 64 + lcol));
                ldsm_x4(ah[mt][0], ah[mt][1], ah[mt][2], ah[mt][3], sAh + off);
                ldsm_x4(al[mt][0], al[mt][1], al[mt][2], al[mt][3], sAl + off);
            }
            #pragma unroll
            for (int ng = 0; ng < 4; ng++) {
                uint32_t off = SW64((uint32_t)((warp_n * 64 + ng * 16 + lrow) * 64 + lcol));
                uint32_t bh[4];
                ldsm_x4(bh[0], bh[1], bh[2], bh[3], sBh + off);
                #pragma unroll
                for (int mt = 0; mt < 2; mt++) {
                    mma16816(acc[mt][2 * ng],     ah[mt], bh[0], bh[2]);
                    mma16816(acc[mt][2 * ng],     al[mt], bh[0], bh[2]);
                    mma16816(acc[mt][2 * ng + 1], ah[mt], bh[1], bh[3]);
                    mma16816(acc[mt][2 * ng + 1], al[mt], bh[1], bh[3]);
                }
            }
        }
        if (++st == 4) st = 0;
    }

    const int row0 = br * 128 + warp_m * 32;
    const int col0 = (bc & 7) * 128 + warp_n * 64;
    const int qr = lane >> 2;
    const int qc = (lane & 3) * 2;

    if (Cf) {
        #pragma unroll
        for (int mt = 0; mt < 2; mt++) {
            #pragma unroll
            for (int nt = 0; nt < 8; nt++) {
                int col = col0 + nt * 8 + qc;
                float b0 = 0.f, b1 = 0.f;
                if (bias) { b0 = bias[col]; b1 = bias[col + 1]; }
                size_t o0 = (size_t)(row0 + mt * 16 + qr) * DD + col;
                size_t o1 = o0 + 8 * DD;
                float2 w0, w1;
                w0.x = acc[mt][nt][0] + b0; w0.y = acc[mt][nt][1] + b1;
                w1.x = acc[mt][nt][2] + b0; w1.y = acc[mt][nt][3] + b1;
                *(float2*)(Cf + o0) = w0;
                *(float2*)(Cf + o1) = w1;
            }
        }
    } else {
        const int sel = bc >> 3;                 // 0=Q 1=K 2=V
        const float scale = (sel == 0) ? qscale : 1.0f;
        fp16* Chs = Ch + (size_t)sel * MTOK * DD;
        #pragma unroll
        for (int mt = 0; mt < 2; mt++) {
            #pragma unroll
            for (int nt = 0; nt < 8; nt++) {
                int col = col0 + nt * 8 + qc;
                size_t o0 = (size_t)(row0 + mt * 16 + qr) * DD + col;
                size_t o1 = o0 + 8 * DD;
                *(uint32_t*)(Chs + o0) = pack2h(acc[mt][nt][0] * scale,
                                                acc[mt][nt][1] * scale);
                *(uint32_t*)(Chs + o1) = pack2h(acc[mt][nt][2] * scale,
                                                acc[mt][nt][3] * scale);
            }
        }
    }
}

// ============================================================
// Flash attention (causal) on mma.sync, fp16 single-stream
// Q/K/P/V, base-2 softmax, fp32 accumulators. O out hi+lo.
// CTA: 256 threads / 8 warps; tile 128 q-rows x 64 kv.
// ============================================================
#define FSTR 144
#define FKTILE (64 * FSTR)            // 9216 B
#define FQTILE (128 * FSTR)           // 18432 B
#define FSTAGEB (2 * FKTILE)          // Kh, Vh = 18432 B
#define FSMEM (FQTILE + 2 * FSTAGEB)  // 55296 B

__global__ __launch_bounds__(256, 2) void flash_mma_kernel(
    const fp16* __restrict__ Qh,
    const fp16* __restrict__ Kh, const fp16* __restrict__ Vh,
    fp16* __restrict__ Oh, fp16* __restrict__ Ol)
{
    extern __shared__ __align__(1024) char dsm[];
    const uint32_t sbase = smem_u32(dsm);

    const int tid = threadIdx.x;
    const int lane = tid & 31;
    const int w = tid >> 5;                 // 0..7
    const int qt = (int)gridDim.x - 1 - (int)blockIdx.x;   // big tiles first
    const int h = blockIdx.y, b = blockIdx.z;

    const size_t base = ((size_t)b * SS) * DD + (size_t)h * HDIM;
    const fp16* gq = Qh + base + (size_t)(qt * 128) * DD;

    // ---- load Q (hi, 128 rows), grouped with kv stage0 ----
    {
        #pragma unroll
        for (int p = 0; p < 4; p++) {
            int i = tid + p * 256;          // 0..1023
            int row = i >> 3;
            int ch = i & 7;
            CP_ASYNC16(sbase + row * FSTR + ch * 16,
                       gq + (size_t)row * DD + ch * 8);
        }
    }

    const fp16* gkv[2] = {Kh + base, Vh + base};
    auto load_kv = [&](int kt, int st) {
        const uint32_t s0 = sbase + FQTILE + st * FSTAGEB;
        const size_t roff = (size_t)(kt * 64) * DD;
        #pragma unroll
        for (int p = 0; p < 4; p++) {
            int i = tid + p * 256;          // 0..1023
            int t = i >> 9;
            int rem = i & 511;
            int row = rem >> 3;
            int ch = rem & 7;
            CP_ASYNC16(s0 + t * FKTILE + row * FSTR + ch * 16,
                       gkv[t] + roff + (size_t)row * DD + ch * 8);
        }
        CP_COMMIT();
    };

    load_kv(0, 0);

    const int qr = lane >> 2;
    const int ql2 = (lane & 3) * 2;
    const int lrow = lane & 15;
    const int lhalf = (lane >> 4) * 16;

    float oacc[8][4];
    #pragma unroll
    for (int nt = 0; nt < 8; nt++)
        #pragma unroll
        for (int j = 0; j < 4; j++) oacc[nt][j] = 0.f;
    float m0 = -CUDART_INF_F, m1 = -CUDART_INF_F;
    float l0 = 0.f, l1 = 0.f;

    const int wrow = w * 16;
    const int row0g = qt * 128 + wrow;
    const int nk = 2 * qt + 2;

    for (int kt = 0; kt < nk; kt++) {
        CP_WAIT(0);
        __syncthreads();
        if (kt + 1 < nk) load_kv(kt + 1, (kt + 1) & 1);

        if (kt * 64 <= row0g + 15) {      // warp early-out
            const uint32_t s0  = sbase + FQTILE + (kt & 1) * FSTAGEB;
            const uint32_t sQh = sbase;
            const uint32_t sKh = s0, sVh = s0 + FKTILE;

            // ---- S = Qh @ Kh^T, log2 units ----
            float sac[8][4];
            #pragma unroll
            for (int nt = 0; nt < 8; nt++)
                #pragma unroll
                for (int j = 0; j < 4; j++) sac[nt][j] = 0.f;

            #pragma unroll
            for (int kk = 0; kk < 4; kk++) {
                uint32_t aoff = (uint32_t)(wrow + lrow) * FSTR + lhalf + kk * 32;
                uint32_t qh_[4];
                ldsm_x4(qh_[0], qh_[1], qh_[2], qh_[3], sQh + aoff);
                #pragma unroll
                for (int ng = 0; ng < 4; ng++) {
                    uint32_t boff = (uint32_t)(ng * 16 + lrow) * FSTR + lhalf + kk * 32;
                    uint32_t kh_[4];
                    ldsm_x4(kh_[0], kh_[1], kh_[2], kh_[3], sKh + boff);
                    mma16816(sac[2 * ng],     qh_, kh_[0], kh_[2]);
                    mma16816(sac[2 * ng + 1], qh_, kh_[1], kh_[3]);
                }
            }

            // ---- causal mask when tile straddles this warp's diagonal ----
            if (kt * 64 + 63 > row0g) {
                const int r0 = row0g + qr, r1 = r0 + 8;
                #pragma unroll
                for (int nt = 0; nt < 8; nt++) {
                    int c = kt * 64 + nt * 8 + ql2;
                    if (c > r0)     sac[nt][0] = -CUDART_INF_F;
                    if (c + 1 > r0) sac[nt][1] = -CUDART_INF_F;
                    if (c > r1)     sac[nt][2] = -CUDART_INF_F;
                    if (c + 1 > r1) sac[nt][3] = -CUDART_INF_F;
                }
            }

            // ---- online softmax (base 2) ----
            float mx0 = -CUDART_INF_F, mx1 = -CUDART_INF_F;
            #pragma unroll
            for (int nt = 0; nt < 8; nt++) {
                mx0 = fmaxf(mx0, fmaxf(sac[nt][0], sac[nt][1]));
                mx1 = fmaxf(mx1, fmaxf(sac[nt][2], sac[nt][3]));
            }
            mx0 = fmaxf(mx0, __shfl_xor_sync(0xffffffffu, mx0, 1));
            mx0 = fmaxf(mx0, __shfl_xor_sync(0xffffffffu, mx0, 2));
            mx1 = fmaxf(mx1, __shfl_xor_sync(0xffffffffu, mx1, 1));
            mx1 = fmaxf(mx1, __shfl_xor_sync(0xffffffffu, mx1, 2));

            float mn0 = fmaxf(m0, mx0), mn1 = fmaxf(m1, mx1);
            float cr0 = exp2f(m0 - mn0), cr1 = exp2f(m1 - mn1);
            m0 = mn0; m1 = mn1;

            float ls0 = 0.f, ls1 = 0.f;
            #pragma unroll
            for (int nt = 0; nt < 8; nt++) {
                float p0 = exp2f(sac[nt][0] - m0);
                float p1 = exp2f(sac[nt][1] - m0);
                float p2 = exp2f(sac[nt][2] - m1);
                float p3 = exp2f(sac[nt][3] - m1);
                sac[nt][0] = p0; sac[nt][1] = p1; sac[nt][2] = p2; sac[nt][3] = p3;
                ls0 += p0 + p1;
                ls1 += p2 + p3;
            }
            ls0 += __shfl_xor_sync(0xffffffffu, ls0, 1);
            ls0 += __shfl_xor_sync(0xffffffffu, ls0, 2);
            ls1 += __shfl_xor_sync(0xffffffffu, ls1, 1);
            ls1 += __shfl_xor_sync(0xffffffffu, ls1, 2);
            l0 = l0 * cr0 + ls0;
            l1 = l1 * cr1 + ls1;

            #pragma unroll
            for (int nt = 0; nt < 8; nt++) {
                oacc[nt][0] *= cr0; oacc[nt][1] *= cr0;
                oacc[nt][2] *= cr1; oacc[nt][3] *= cr1;
            }

            // ---- O += Ph @ Vh ----
            #pragma unroll
            for (int kk = 0; kk < 4; kk++) {
                uint32_t ph_[4];
                ph_[0] = pack2h(sac[2 * kk][0],     sac[2 * kk][1]);
                ph_[1] = pack2h(sac[2 * kk][2],     sac[2 * kk][3]);
                ph_[2] = pack2h(sac[2 * kk + 1][0], sac[2 * kk + 1][1]);
                ph_[3] = pack2h(sac[2 * kk + 1][2], sac[2 * kk + 1][3]);
                #pragma unroll
                for (int ng = 0; ng < 4; ng++) {
                    uint32_t voff = (uint32_t)(kk * 16 + lrow) * FSTR + ng * 32 + lhalf;
                    uint32_t vh_[4];
                    ldsm_x4_t(vh_[0], vh_[1], vh_[2], vh_[3], sVh + voff);
                    mma16816(oacc[2 * ng],     ph_, vh_[0], vh_[1]);
                    mma16816(oacc[2 * ng + 1], ph_, vh_[2], vh_[3]);
                }
            }
        }
    }

    // ---- epilogue: normalize, split, store fp16 hi/lo ----
    const float inv0 = 1.0f / l0, inv1 = 1.0f / l1;
    const size_t orow0 = base + (size_t)(qt * 128 + wrow + qr) * DD;
    const size_t orow1 = orow0 + 8 * DD;
    #pragma unroll
    for (int nt = 0; nt < 8; nt++) {
        int d = nt * 8 + ql2;
        uint32_t h0, lo0, h1, lo1;
        split2h(oacc[nt][0] * inv0, oacc[nt][1] * inv0, h0, lo0);
        split2h(oacc[nt][2] * inv1, oacc[nt][3] * inv1, h1, lo1);
        *(uint32_t*)(Oh + orow0 + d) = h0;
        *(uint32_t*)(Ol + orow0 + d) = lo0;
        *(uint32_t*)(Oh + orow1 + d) = h1;
        *(uint32_t*)(Ol + orow1 + d) = lo1;
    }
}

// ============================================================
// Launch
// ============================================================
extern "C" void kernel_launch(void* const* d_in, const int* in_sizes, int n_in,
                              void* d_out, int out_size)
{
    const float* x  = (const float*)d_in[0];
    const float* Wq = (const float*)d_in[1];
    const float* Wk = (const float*)d_in[2];
    const float* Wv = (const float*)d_in[3];
    const float* Wo = (const float*)d_in[4];
    const float* bo = (const float*)d_in[5];
    float* out = (float*)d_out;

    fp16 *xh, *xl, *qkvh, *wqkvh, *woh;
    cudaGetSymbolAddress((void**)&xh, g_xh);
    cudaGetSymbolAddress((void**)&xl, g_xl);
    cudaGetSymbolAddress((void**)&qkvh, g_qkvh);
    cudaGetSymbolAddress((void**)&wqkvh, g_wqkvh);
    cudaGetSymbolAddress((void**)&woh, g_woh);

    // 1. split x -> fp16 hi/lo
    const int n4 = MTOK * DD / 4;
    split_kernel<<<n4 / 256, 256>>>(x, xh, xl, n4);

    // 2. fused transpose of all 4 weights -> fp16 hi
    transpose_split4_kernel<<<dim3(DD / 32, DD / 32, 4), dim3(32, 8)>>>(
        Wq, Wk, Wv, Wo, wqkvh, woh);

    // 3. fused QKV projection (single launch, N=3072), hi-only outputs
    const float qscale = 0.125f * 1.4426950408889634f;
    cudaFuncSetAttribute(gemm_mma_kernel,
                         cudaFuncAttributeMaxDynamicSharedMemorySize, GSMEM);
    gemm_mma_kernel<<<dim3(24, MTOK / 128), 256, GSMEM>>>(
        xh, xl, wqkvh, nullptr, nullptr, qkvh, qscale);

    // 4. flash attention (single-stream Q/K/V); writes hi/lo into xh/xl
    const size_t seg = (size_t)MTOK * DD;
    cudaFuncSetAttribute(flash_mma_kernel,
                         cudaFuncAttributeMaxDynamicSharedMemorySize, FSMEM);
    flash_mma_kernel<<<dim3(SS / 128, HH, BB), 256, FSMEM>>>(
        qkvh, qkvh + seg, qkvh + 2 * seg, xh, xl);

    // 5. output projection (+bias), fp32 out
    gemm_mma_kernel<<<dim3(8, MTOK / 128), 256, GSMEM>>>(
        xh, xl, woh, bo, out, nullptr, 1.0f);
}

// round 11
// speedup vs baseline: 7.4327x; 1.4424x over previous
#include <cuda_runtime.h>
#include <cuda_fp16.h>
#include <math_constants.h>
#include <cstdint>

// Problem constants
#define BB 4
#define SS 2048
#define DD 1024
#define HH 16
#define HDIM 64
#define MTOK (BB * SS)   // 8192
#define GK DD            // GEMM K = 1024

typedef __half fp16;

// ---------------- scratch (__device__ globals; allocation-free rule) -------
__device__ fp16 g_xh[MTOK * DD];                        // x fp16; reused for attn out
__device__ fp16 g_qkvh[3 * MTOK * DD];                  // Q|K|V (fp16)
__device__ fp16 g_wqkvh[3 * DD * DD];                   // Wq|Wk|Wv transposed, fp16
__device__ fp16 g_woh[DD * DD];

// ---------------- helpers (plain sm_90-era PTX only) ------------------------
__device__ __forceinline__ uint32_t smem_u32(const void* p) {
    uint32_t a;
    asm("{ .reg .u64 t; cvta.to.shared.u64 t, %1; cvt.u32.u64 %0, t; }"
        : "=r"(a) : "l"(p));
    return a;
}
__device__ __forceinline__ void ldsm_x4(uint32_t& r0, uint32_t& r1,
                                        uint32_t& r2, uint32_t& r3, uint32_t addr) {
    asm volatile("ldmatrix.sync.aligned.m8n8.x4.shared.b16 {%0,%1,%2,%3}, [%4];"
                 : "=r"(r0), "=r"(r1), "=r"(r2), "=r"(r3) : "r"(addr));
}
__device__ __forceinline__ void ldsm_x4_t(uint32_t& r0, uint32_t& r1,
                                          uint32_t& r2, uint32_t& r3, uint32_t addr) {
    asm volatile("ldmatrix.sync.aligned.m8n8.x4.trans.shared.b16 {%0,%1,%2,%3}, [%4];"
                 : "=r"(r0), "=r"(r1), "=r"(r2), "=r"(r3) : "r"(addr));
}
__device__ __forceinline__ void mma16816(float* c, const uint32_t* a,
                                         uint32_t b0, uint32_t b1) {
    asm volatile(
        "mma.sync.aligned.m16n8k16.row.col.f32.f16.f16.f32 "
        "{%0,%1,%2,%3}, {%4,%5,%6,%7}, {%8,%9}, {%0,%1,%2,%3};"
        : "+f"(c[0]), "+f"(c[1]), "+f"(c[2]), "+f"(c[3])
        : "r"(a[0]), "r"(a[1]), "r"(a[2]), "r"(a[3]), "r"(b0), "r"(b1));
}
#define CP_ASYNC16(saddr, gaddr) \
    asm volatile("cp.async.cg.shared.global [%0], [%1], 16;" :: "r"(saddr), "l"(gaddr))
#define CP_COMMIT() asm volatile("cp.async.commit_group;" ::: "memory")
#define CP_WAIT(n)  asm volatile("cp.async.wait_group %0;" :: "n"(n) : "memory")

// SW64 swizzle: permutes 16B chunks within the 128B bank period
#define SW64(off) ((off) ^ (((off) >> 3) & 0x30))

__device__ __forceinline__ uint32_t pack2h(float a, float b) {
    __half2 t = __floats2half2_rn(a, b);
    return *reinterpret_cast<uint32_t*>(&t);
}

// ============================================================
// convert: fp32 -> fp16 (x)
// ============================================================
__global__ __launch_bounds__(256) void convert_kernel(
    const float* __restrict__ in, fp16* __restrict__ hi, int n4)
{
    int i = blockIdx.x * blockDim.x + threadIdx.x;
    if (i >= n4) return;
    float4 v = reinterpret_cast<const float4*>(in)[i];
    uint2 hh;
    hh.x = pack2h(v.x, v.y);
    hh.y = pack2h(v.z, v.w);
    reinterpret_cast<uint2*>(hi)[i] = hh;
}

// ============================================================
// fused transpose of all 4 weights -> fp16
// ============================================================
__global__ __launch_bounds__(256) void transpose4_kernel(
    const float* __restrict__ Wq, const float* __restrict__ Wk,
    const float* __restrict__ Wv, const float* __restrict__ Wo,
    fp16* __restrict__ Wqkvh, fp16* __restrict__ Woh)
{
    __shared__ float t[32][33];
    const int z = blockIdx.z;
    const float* W = (z == 0) ? Wq : (z == 1) ? Wk : (z == 2) ? Wv : Wo;
    fp16* Th = (z < 3) ? Wqkvh + (size_t)z * DD * DD : Woh;

    const int bx = blockIdx.x, by = blockIdx.y;
    const int x = threadIdx.x, y = threadIdx.y;  // 32 x 8
    #pragma unroll
    for (int i = 0; i < 4; i++)
        t[y + 8 * i][x] = W[(size_t)(by * 32 + y + 8 * i) * DD + bx * 32 + x];
    __syncthreads();
    #pragma unroll
    for (int i = 0; i < 4; i++) {
        float v = t[x][y + 8 * i];
        Th[(size_t)(bx * 32 + y + 8 * i) * DD + by * 32 + x] = __float2half_rn(v);
    }
}

// ============================================================
// fp16 GEMM on mma.sync: C = Ah[M,K] @ Bh[N,K]^T.
// 4-stage cp.async pipeline, SW64 swizzle, 1 barrier/chunk.
// QKV mode (Cf==null): fp16 outputs into Q|K|V segments, Q scaled.
// fp32 mode: +bias, fp32 out.
// ============================================================
#define CHK 32
#define GTILE 8192               // 128 rows x 64 B
#define GSTAGE (2 * GTILE)       // Ah, Bh = 16384 B
#define GSMEM (4 * GSTAGE)       // 65536 B

__global__ __launch_bounds__(256, 2) void gemm_mma_kernel(
    const fp16* __restrict__ Ah, const fp16* __restrict__ Bh,
    const float* __restrict__ bias, float* __restrict__ Cf,
    fp16* __restrict__ Ch, float qscale)
{
    extern __shared__ __align__(1024) char dsm[];
    const uint32_t sbase = smem_u32(dsm);

    const int tid = threadIdx.x;
    const int lane = tid & 31;
    const int wid = tid >> 5;
    const int warp_m = wid & 3;
    const int warp_n = wid >> 2;
    const int br = blockIdx.y, bc = blockIdx.x;

    const fp16* gsrc[2] = {
        Ah + (size_t)(br * 128) * GK,
        Bh + (size_t)(bc * 128) * GK
    };

    auto load_stage = [&](int k0, int st) {
        const uint32_t s0 = sbase + st * GSTAGE;
        #pragma unroll
        for (int p = 0; p < 4; p++) {
            int idx = tid + p * 256;        // 0..1023
            int t   = idx >> 9;
            int rem = idx & 511;
            int row = rem >> 2;
            int ch  = rem & 3;
            uint32_t sa = s0 + t * GTILE + SW64((uint32_t)(row * 64 + ch * 16));
            const fp16* g = gsrc[t] + (size_t)row * GK + k0 + ch * 8;
            CP_ASYNC16(sa, g);
        }
        CP_COMMIT();
    };

    float acc[2][8][4];
    #pragma unroll
    for (int mt = 0; mt < 2; mt++)
        #pragma unroll
        for (int nt = 0; nt < 8; nt++)
            #pragma unroll
            for (int j = 0; j < 4; j++) acc[mt][nt][j] = 0.f;

    const int NC = GK / CHK;   // 32
    load_stage(0, 0);
    load_stage(CHK, 1);
    load_stage(2 * CHK, 2);

    const int lrow = lane & 15;
    const int lsel = (lane >> 4) * 16;

    int st = 0;
    for (int c = 0; c < NC; c++) {
        if (c <= NC - 3)      { CP_WAIT(2); }
        else if (c == NC - 2) { CP_WAIT(1); }
        else                  { CP_WAIT(0); }
        __syncthreads();
        if (c + 3 < NC) load_stage((c + 3) * CHK, (c + 3) & 3);

        const uint32_t s0  = sbase + st * GSTAGE;
        const uint32_t sAh = s0, sBh = s0 + GTILE;

        #pragma unroll
        for (int kk = 0; kk < 2; kk++) {
            const int lcol = lsel + kk * 32;
            uint32_t ah[2][4];
            #pragma unroll
            for (int mt = 0; mt < 2; mt++) {
                uint32_t off = SW64((uint32_t)((warp_m * 32 + mt * 16 + lrow) * 64 + lcol));
                ldsm_x4(ah[mt][0], ah[mt][1], ah[mt][2], ah[mt][3], sAh + off);
            }
            #pragma unroll
            for (int ng = 0; ng < 4; ng++) {
                uint32_t off = SW64((uint32_t)((warp_n * 64 + ng * 16 + lrow) * 64 + lcol));
                uint32_t bh[4];
                ldsm_x4(bh[0], bh[1], bh[2], bh[3], sBh + off);
                #pragma unroll
                for (int mt = 0; mt < 2; mt++) {
                    mma16816(acc[mt][2 * ng],     ah[mt], bh[0], bh[2]);
                    mma16816(acc[mt][2 * ng + 1], ah[mt], bh[1], bh[3]);
                }
            }
        }
        if (++st == 4) st = 0;
    }

    const int row0 = br * 128 + warp_m * 32;
    const int col0 = (bc & 7) * 128 + warp_n * 64;
    const int qr = lane >> 2;
    const int qc = (lane & 3) * 2;

    if (Cf) {
        #pragma unroll
        for (int mt = 0; mt < 2; mt++) {
            #pragma unroll
            for (int nt = 0; nt < 8; nt++) {
                int col = col0 + nt * 8 + qc;
                float b0 = 0.f, b1 = 0.f;
                if (bias) { b0 = bias[col]; b1 = bias[col + 1]; }
                size_t o0 = (size_t)(row0 + mt * 16 + qr) * DD + col;
                size_t o1 = o0 + 8 * DD;
                float2 w0, w1;
                w0.x = acc[mt][nt][0] + b0; w0.y = acc[mt][nt][1] + b1;
                w1.x = acc[mt][nt][2] + b0; w1.y = acc[mt][nt][3] + b1;
                *(float2*)(Cf + o0) = w0;
                *(float2*)(Cf + o1) = w1;
            }
        }
    } else {
        const int sel = bc >> 3;                 // 0=Q 1=K 2=V
        const float scale = (sel == 0) ? qscale : 1.0f;
        fp16* Chs = Ch + (size_t)sel * MTOK * DD;
        #pragma unroll
        for (int mt = 0; mt < 2; mt++) {
            #pragma unroll
            for (int nt = 0; nt < 8; nt++) {
                int col = col0 + nt * 8 + qc;
                size_t o0 = (size_t)(row0 + mt * 16 + qr) * DD + col;
                size_t o1 = o0 + 8 * DD;
                *(uint32_t*)(Chs + o0) = pack2h(acc[mt][nt][0] * scale,
                                                acc[mt][nt][1] * scale);
                *(uint32_t*)(Chs + o1) = pack2h(acc[mt][nt][2] * scale,
                                                acc[mt][nt][3] * scale);
            }
        }
    }
}

// ============================================================
// Flash attention (causal) on mma.sync, fp16 single-stream,
// base-2 softmax, fp32 accumulators. O out fp16.
// CTA: 256 threads / 8 warps; tile 128 q-rows x 64 kv.
// ============================================================
#define FSTR 144
#define FKTILE (64 * FSTR)            // 9216 B
#define FQTILE (128 * FSTR)           // 18432 B
#define FSTAGEB (2 * FKTILE)          // Kh, Vh = 18432 B
#define FSMEM (FQTILE + 2 * FSTAGEB)  // 55296 B

__global__ __launch_bounds__(256, 2) void flash_mma_kernel(
    const fp16* __restrict__ Qh,
    const fp16* __restrict__ Kh, const fp16* __restrict__ Vh,
    fp16* __restrict__ Oh)
{
    extern __shared__ __align__(1024) char dsm[];
    const uint32_t sbase = smem_u32(dsm);

    const int tid = threadIdx.x;
    const int lane = tid & 31;
    const int w = tid >> 5;                 // 0..7
    const int qt = (int)gridDim.x - 1 - (int)blockIdx.x;   // big tiles first
    const int h = blockIdx.y, b = blockIdx.z;

    const size_t base = ((size_t)b * SS) * DD + (size_t)h * HDIM;
    const fp16* gq = Qh + base + (size_t)(qt * 128) * DD;

    // ---- load Q (128 rows), grouped with kv stage0 ----
    {
        #pragma unroll
        for (int p = 0; p < 4; p++) {
            int i = tid + p * 256;          // 0..1023
            int row = i >> 3;
            int ch = i & 7;
            CP_ASYNC16(sbase + row * FSTR + ch * 16,
                       gq + (size_t)row * DD + ch * 8);
        }
    }

    const fp16* gkv[2] = {Kh + base, Vh + base};
    auto load_kv = [&](int kt, int st) {
        const uint32_t s0 = sbase + FQTILE + st * FSTAGEB;
        const size_t roff = (size_t)(kt * 64) * DD;
        #pragma unroll
        for (int p = 0; p < 4; p++) {
            int i = tid + p * 256;          // 0..1023
            int t = i >> 9;
            int rem = i & 511;
            int row = rem >> 3;
            int ch = rem & 7;
            CP_ASYNC16(s0 + t * FKTILE + row * FSTR + ch * 16,
                       gkv[t] + roff + (size_t)row * DD + ch * 8);
        }
        CP_COMMIT();
    };

    load_kv(0, 0);

    const int qr = lane >> 2;
    const int ql2 = (lane & 3) * 2;
    const int lrow = lane & 15;
    const int lhalf = (lane >> 4) * 16;

    float oacc[8][4];
    #pragma unroll
    for (int nt = 0; nt < 8; nt++)
        #pragma unroll
        for (int j = 0; j < 4; j++) oacc[nt][j] = 0.f;
    float m0 = -CUDART_INF_F, m1 = -CUDART_INF_F;
    float l0 = 0.f, l1 = 0.f;

    const int wrow = w * 16;
    const int row0g = qt * 128 + wrow;
    const int nk = 2 * qt + 2;

    for (int kt = 0; kt < nk; kt++) {
        CP_WAIT(0);
        __syncthreads();
        if (kt + 1 < nk) load_kv(kt + 1, (kt + 1) & 1);

        if (kt * 64 <= row0g + 15) {      // warp early-out
            const uint32_t s0  = sbase + FQTILE + (kt & 1) * FSTAGEB;
            const uint32_t sQh = sbase;
            const uint32_t sKh = s0, sVh = s0 + FKTILE;

            // ---- S = Qh @ Kh^T, log2 units ----
            float sac[8][4];
            #pragma unroll
            for (int nt = 0; nt < 8; nt++)
                #pragma unroll
                for (int j = 0; j < 4; j++) sac[nt][j] = 0.f;

            #pragma unroll
            for (int kk = 0; kk < 4; kk++) {
                uint32_t aoff = (uint32_t)(wrow + lrow) * FSTR + lhalf + kk * 32;
                uint32_t qh_[4];
                ldsm_x4(qh_[0], qh_[1], qh_[2], qh_[3], sQh + aoff);
                #pragma unroll
                for (int ng = 0; ng < 4; ng++) {
                    uint32_t boff = (uint32_t)(ng * 16 + lrow) * FSTR + lhalf + kk * 32;
                    uint32_t kh_[4];
                    ldsm_x4(kh_[0], kh_[1], kh_[2], kh_[3], sKh + boff);
                    mma16816(sac[2 * ng],     qh_, kh_[0], kh_[2]);
                    mma16816(sac[2 * ng + 1], qh_, kh_[1], kh_[3]);
                }
            }

            // ---- causal mask when tile straddles this warp's diagonal ----
            if (kt * 64 + 63 > row0g) {
                const int r0 = row0g + qr, r1 = r0 + 8;
                #pragma unroll
                for (int nt = 0; nt < 8; nt++) {
                    int c = kt * 64 + nt * 8 + ql2;
                    if (c > r0)     sac[nt][0] = -CUDART_INF_F;
                    if (c + 1 > r0) sac[nt][1] = -CUDART_INF_F;
                    if (c > r1)     sac[nt][2] = -CUDART_INF_F;
                    if (c + 1 > r1) sac[nt][3] = -CUDART_INF_F;
                }
            }

            // ---- online softmax (base 2) ----
            float mx0 = -CUDART_INF_F, mx1 = -CUDART_INF_F;
            #pragma unroll
            for (int nt = 0; nt < 8; nt++) {
                mx0 = fmaxf(mx0, fmaxf(sac[nt][0], sac[nt][1]));
                mx1 = fmaxf(mx1, fmaxf(sac[nt][2], sac[nt][3]));
            }
            mx0 = fmaxf(mx0, __shfl_xor_sync(0xffffffffu, mx0, 1));
            mx0 = fmaxf(mx0, __shfl_xor_sync(0xffffffffu, mx0, 2));
            mx1 = fmaxf(mx1, __shfl_xor_sync(0xffffffffu, mx1, 1));
            mx1 = fmaxf(mx1, __shfl_xor_sync(0xffffffffu, mx1, 2));

            float mn0 = fmaxf(m0, mx0), mn1 = fmaxf(m1, mx1);
            float cr0 = exp2f(m0 - mn0), cr1 = exp2f(m1 - mn1);
            m0 = mn0; m1 = mn1;

            float ls0 = 0.f, ls1 = 0.f;
            #pragma unroll
            for (int nt = 0; nt < 8; nt++) {
                float p0 = exp2f(sac[nt][0] - m0);
                float p1 = exp2f(sac[nt][1] - m0);
                float p2 = exp2f(sac[nt][2] - m1);
                float p3 = exp2f(sac[nt][3] - m1);
                sac[nt][0] = p0; sac[nt][1] = p1; sac[nt][2] = p2; sac[nt][3] = p3;
                ls0 += p0 + p1;
                ls1 += p2 + p3;
            }
            ls0 += __shfl_xor_sync(0xffffffffu, ls0, 1);
            ls0 += __shfl_xor_sync(0xffffffffu, ls0, 2);
            ls1 += __shfl_xor_sync(0xffffffffu, ls1, 1);
            ls1 += __shfl_xor_sync(0xffffffffu, ls1, 2);
            l0 = l0 * cr0 + ls0;
            l1 = l1 * cr1 + ls1;

            #pragma unroll
            for (int nt = 0; nt < 8; nt++) {
                oacc[nt][0] *= cr0; oacc[nt][1] *= cr0;
                oacc[nt][2] *= cr1; oacc[nt][3] *= cr1;
            }

            // ---- O += Ph @ Vh ----
            #pragma unroll
            for (int kk = 0; kk < 4; kk++) {
                uint32_t ph_[4];
                ph_[0] = pack2h(sac[2 * kk][0],     sac[2 * kk][1]);
                ph_[1] = pack2h(sac[2 * kk][2],     sac[2 * kk][3]);
                ph_[2] = pack2h(sac[2 * kk + 1][0], sac[2 * kk + 1][1]);
                ph_[3] = pack2h(sac[2 * kk + 1][2], sac[2 * kk + 1][3]);
                #pragma unroll
                for (int ng = 0; ng < 4; ng++) {
                    uint32_t voff = (uint32_t)(kk * 16 + lrow) * FSTR + ng * 32 + lhalf;
                    uint32_t vh_[4];
                    ldsm_x4_t(vh_[0], vh_[1], vh_[2], vh_[3], sVh + voff);
                    mma16816(oacc[2 * ng],     ph_, vh_[0], vh_[1]);
                    mma16816(oacc[2 * ng + 1], ph_, vh_[2], vh_[3]);
                }
            }
        }
    }

    // ---- epilogue: normalize, store fp16 ----
    const float inv0 = 1.0f / l0, inv1 = 1.0f / l1;
    const size_t orow0 = base + (size_t)(qt * 128 + wrow + qr) * DD;
    const size_t orow1 = orow0 + 8 * DD;
    #pragma unroll
    for (int nt = 0; nt < 8; nt++) {
        int d = nt * 8 + ql2;
        *(uint32_t*)(Oh + orow0 + d) = pack2h(oacc[nt][0] * inv0, oacc[nt][1] * inv0);
        *(uint32_t*)(Oh + orow1 + d) = pack2h(oacc[nt][2] * inv1, oacc[nt][3] * inv1);
    }
}

// ============================================================
// Launch
// ============================================================
extern "C" void kernel_launch(void* const* d_in, const int* in_sizes, int n_in,
                              void* d_out, int out_size)
{
    const float* x  = (const float*)d_in[0];
    const float* Wq = (const float*)d_in[1];
    const float* Wk = (const float*)d_in[2];
    const float* Wv = (const float*)d_in[3];
    const float* Wo = (const float*)d_in[4];
    const float* bo = (const float*)d_in[5];
    float* out = (float*)d_out;

    fp16 *xh, *qkvh, *wqkvh, *woh;
    cudaGetSymbolAddress((void**)&xh, g_xh);
    cudaGetSymbolAddress((void**)&qkvh, g_qkvh);
    cudaGetSymbolAddress((void**)&wqkvh, g_wqkvh);
    cudaGetSymbolAddress((void**)&woh, g_woh);

    // 1. convert x -> fp16
    const int n4 = MTOK * DD / 4;
    convert_kernel<<<n4 / 256, 256>>>(x, xh, n4);

    // 2. fused transpose of all 4 weights -> fp16
    transpose4_kernel<<<dim3(DD / 32, DD / 32, 4), dim3(32, 8)>>>(
        Wq, Wk, Wv, Wo, wqkvh, woh);

    // 3. fused QKV projection (single launch, N=3072), fp16 outputs
    const float qscale = 0.125f * 1.4426950408889634f;
    cudaFuncSetAttribute(gemm_mma_kernel,
                         cudaFuncAttributeMaxDynamicSharedMemorySize, GSMEM);
    gemm_mma_kernel<<<dim3(24, MTOK / 128), 256, GSMEM>>>(
        xh, wqkvh, nullptr, nullptr, qkvh, qscale);

    // 4. flash attention; writes fp16 output into xh
    const size_t seg = (size_t)MTOK * DD;
    cudaFuncSetAttribute(flash_mma_kernel,
                         cudaFuncAttributeMaxDynamicSharedMemorySize, FSMEM);
    flash_mma_kernel<<<dim3(SS / 128, HH, BB), 256, FSMEM>>>(
        qkvh, qkvh + seg, qkvh + 2 * seg, xh);

    // 5. output projection (+bias), fp32 out
    gemm_mma_kernel<<<dim3(8, MTOK / 128), 256, GSMEM>>>(
        xh, woh, bo, out, nullptr, 1.0f);
}

// round 12
// speedup vs baseline: 7.5672x; 1.0181x over previous
#include <cuda_runtime.h>
#include <cuda_fp16.h>
#include <math_constants.h>
#include <cstdint>

// Problem constants
#define BB 4
#define SS 2048
#define DD 1024
#define HH 16
#define HDIM 64
#define MTOK (BB * SS)   // 8192
#define GK DD            // GEMM K = 1024

typedef __half fp16;

// ---------------- scratch (__device__ globals; allocation-free rule) -------
__device__ fp16 g_xh[MTOK * DD];                        // x fp16; reused for attn out
__device__ fp16 g_qkvh[3 * MTOK * DD];                  // Q|K|V (fp16)
__device__ fp16 g_wqkvh[3 * DD * DD];                   // Wq|Wk|Wv transposed, fp16
__device__ fp16 g_woh[DD * DD];

// ---------------- helpers (plain sm_90-era PTX only) ------------------------
__device__ __forceinline__ uint32_t smem_u32(const void* p) {
    uint32_t a;
    asm("{ .reg .u64 t; cvta.to.shared.u64 t, %1; cvt.u32.u64 %0, t; }"
        : "=r"(a) : "l"(p));
    return a;
}
__device__ __forceinline__ void ldsm_x4(uint32_t& r0, uint32_t& r1,
                                        uint32_t& r2, uint32_t& r3, uint32_t addr) {
    asm volatile("ldmatrix.sync.aligned.m8n8.x4.shared.b16 {%0,%1,%2,%3}, [%4];"
                 : "=r"(r0), "=r"(r1), "=r"(r2), "=r"(r3) : "r"(addr));
}
__device__ __forceinline__ void ldsm_x4_t(uint32_t& r0, uint32_t& r1,
                                          uint32_t& r2, uint32_t& r3, uint32_t addr) {
    asm volatile("ldmatrix.sync.aligned.m8n8.x4.trans.shared.b16 {%0,%1,%2,%3}, [%4];"
                 : "=r"(r0), "=r"(r1), "=r"(r2), "=r"(r3) : "r"(addr));
}
__device__ __forceinline__ void mma16816(float* c, const uint32_t* a,
                                         uint32_t b0, uint32_t b1) {
    asm volatile(
        "mma.sync.aligned.m16n8k16.row.col.f32.f16.f16.f32 "
        "{%0,%1,%2,%3}, {%4,%5,%6,%7}, {%8,%9}, {%0,%1,%2,%3};"
        : "+f"(c[0]), "+f"(c[1]), "+f"(c[2]), "+f"(c[3])
        : "r"(a[0]), "r"(a[1]), "r"(a[2]), "r"(a[3]), "r"(b0), "r"(b1));
}
#define CP_ASYNC16(saddr, gaddr) \
    asm volatile("cp.async.cg.shared.global [%0], [%1], 16;" :: "r"(saddr), "l"(gaddr))
#define CP_COMMIT() asm volatile("cp.async.commit_group;" ::: "memory")
#define CP_WAIT(n)  asm volatile("cp.async.wait_group %0;" :: "n"(n) : "memory")

// SW64 swizzle: permutes 16B chunks within the 128B bank period
#define SW64(off) ((off) ^ (((off) >> 3) & 0x30))

__device__ __forceinline__ uint32_t pack2h(float a, float b) {
    __half2 t = __floats2half2_rn(a, b);
    return *reinterpret_cast<uint32_t*>(&t);
}
// fast exp2 via MUFU.EX2 (flag-independent)
__device__ __forceinline__ float ex2(float x) {
    float y;
    asm("ex2.approx.ftz.f32 %0, %1;" : "=f"(y) : "f"(x));
    return y;
}

// ============================================================
// convert: fp32 -> fp16 (x)
// ============================================================
__global__ __launch_bounds__(256) void convert_kernel(
    const float* __restrict__ in, fp16* __restrict__ hi, int n4)
{
    int i = blockIdx.x * blockDim.x + threadIdx.x;
    if (i >= n4) return;
    float4 v = reinterpret_cast<const float4*>(in)[i];
    uint2 hh;
    hh.x = pack2h(v.x, v.y);
    hh.y = pack2h(v.z, v.w);
    reinterpret_cast<uint2*>(hi)[i] = hh;
}

// ============================================================
// fused transpose of all 4 weights -> fp16
// ============================================================
__global__ __launch_bounds__(256) void transpose4_kernel(
    const float* __restrict__ Wq, const float* __restrict__ Wk,
    const float* __restrict__ Wv, const float* __restrict__ Wo,
    fp16* __restrict__ Wqkvh, fp16* __restrict__ Woh)
{
    __shared__ float t[32][33];
    const int z = blockIdx.z;
    const float* W = (z == 0) ? Wq : (z == 1) ? Wk : (z == 2) ? Wv : Wo;
    fp16* Th = (z < 3) ? Wqkvh + (size_t)z * DD * DD : Woh;

    const int bx = blockIdx.x, by = blockIdx.y;
    const int x = threadIdx.x, y = threadIdx.y;  // 32 x 8
    #pragma unroll
    for (int i = 0; i < 4; i++)
        t[y + 8 * i][x] = W[(size_t)(by * 32 + y + 8 * i) * DD + bx * 32 + x];
    __syncthreads();
    #pragma unroll
    for (int i = 0; i < 4; i++) {
        float v = t[x][y + 8 * i];
        Th[(size_t)(bx * 32 + y + 8 * i) * DD + by * 32 + x] = __float2half_rn(v);
    }
}

// ============================================================
// fp16 GEMM on mma.sync (unchanged from R11)
// ============================================================
#define CHK 32
#define GTILE 8192               // 128 rows x 64 B
#define GSTAGE (2 * GTILE)       // Ah, Bh = 16384 B
#define GSMEM (4 * GSTAGE)       // 65536 B

__global__ __launch_bounds__(256, 2) void gemm_mma_kernel(
    const fp16* __restrict__ Ah, const fp16* __restrict__ Bh,
    const float* __restrict__ bias, float* __restrict__ Cf,
    fp16* __restrict__ Ch, float qscale)
{
    extern __shared__ __align__(1024) char dsm[];
    const uint32_t sbase = smem_u32(dsm);

    const int tid = threadIdx.x;
    const int lane = tid & 31;
    const int wid = tid >> 5;
    const int warp_m = wid & 3;
    const int warp_n = wid >> 2;
    const int br = blockIdx.y, bc = blockIdx.x;

    const fp16* gsrc[2] = {
        Ah + (size_t)(br * 128) * GK,
        Bh + (size_t)(bc * 128) * GK
    };

    auto load_stage = [&](int k0, int st) {
        const uint32_t s0 = sbase + st * GSTAGE;
        #pragma unroll
        for (int p = 0; p < 4; p++) {
            int idx = tid + p * 256;        // 0..1023
            int t   = idx >> 9;
            int rem = idx & 511;
            int row = rem >> 2;
            int ch  = rem & 3;
            uint32_t sa = s0 + t * GTILE + SW64((uint32_t)(row * 64 + ch * 16));
            const fp16* g = gsrc[t] + (size_t)row * GK + k0 + ch * 8;
            CP_ASYNC16(sa, g);
        }
        CP_COMMIT();
    };

    float acc[2][8][4];
    #pragma unroll
    for (int mt = 0; mt < 2; mt++)
        #pragma unroll
        for (int nt = 0; nt < 8; nt++)
            #pragma unroll
            for (int j = 0; j < 4; j++) acc[mt][nt][j] = 0.f;

    const int NC = GK / CHK;   // 32
    load_stage(0, 0);
    load_stage(CHK, 1);
    load_stage(2 * CHK, 2);

    const int lrow = lane & 15;
    const int lsel = (lane >> 4) * 16;

    int st = 0;
    for (int c = 0; c < NC; c++) {
        if (c <= NC - 3)      { CP_WAIT(2); }
        else if (c == NC - 2) { CP_WAIT(1); }
        else                  { CP_WAIT(0); }
        __syncthreads();
        if (c + 3 < NC) load_stage((c + 3) * CHK, (c + 3) & 3);

        const uint32_t s0  = sbase + st * GSTAGE;
        const uint32_t sAh = s0, sBh = s0 + GTILE;

        #pragma unroll
        for (int kk = 0; kk < 2; kk++) {
            const int lcol = lsel + kk * 32;
            uint32_t ah[2][4];
            #pragma unroll
            for (int mt = 0; mt < 2; mt++) {
                uint32_t off = SW64((uint32_t)((warp_m * 32 + mt * 16 + lrow) * 64 + lcol));
                ldsm_x4(ah[mt][0], ah[mt][1], ah[mt][2], ah[mt][3], sAh + off);
            }
            #pragma unroll
            for (int ng = 0; ng < 4; ng++) {
                uint32_t off = SW64((uint32_t)((warp_n * 64 + ng * 16 + lrow) * 64 + lcol));
                uint32_t bh[4];
                ldsm_x4(bh[0], bh[1], bh[2], bh[3], sBh + off);
                #pragma unroll
                for (int mt = 0; mt < 2; mt++) {
                    mma16816(acc[mt][2 * ng],     ah[mt], bh[0], bh[2]);
                    mma16816(acc[mt][2 * ng + 1], ah[mt], bh[1], bh[3]);
                }
            }
        }
        if (++st == 4) st = 0;
    }

    const int row0 = br * 128 + warp_m * 32;
    const int col0 = (bc & 7) * 128 + warp_n * 64;
    const int qr = lane >> 2;
    const int qc = (lane & 3) * 2;

    if (Cf) {
        #pragma unroll
        for (int mt = 0; mt < 2; mt++) {
            #pragma unroll
            for (int nt = 0; nt < 8; nt++) {
                int col = col0 + nt * 8 + qc;
                float b0 = 0.f, b1 = 0.f;
                if (bias) { b0 = bias[col]; b1 = bias[col + 1]; }
                size_t o0 = (size_t)(row0 + mt * 16 + qr) * DD + col;
                size_t o1 = o0 + 8 * DD;
                float2 w0, w1;
                w0.x = acc[mt][nt][0] + b0; w0.y = acc[mt][nt][1] + b1;
                w1.x = acc[mt][nt][2] + b0; w1.y = acc[mt][nt][3] + b1;
                *(float2*)(Cf + o0) = w0;
                *(float2*)(Cf + o1) = w1;
            }
        }
    } else {
        const int sel = bc >> 3;                 // 0=Q 1=K 2=V
        const float scale = (sel == 0) ? qscale : 1.0f;
        fp16* Chs = Ch + (size_t)sel * MTOK * DD;
        #pragma unroll
        for (int mt = 0; mt < 2; mt++) {
            #pragma unroll
            for (int nt = 0; nt < 8; nt++) {
                int col = col0 + nt * 8 + qc;
                size_t o0 = (size_t)(row0 + mt * 16 + qr) * DD + col;
                size_t o1 = o0 + 8 * DD;
                *(uint32_t*)(Chs + o0) = pack2h(acc[mt][nt][0] * scale,
                                                acc[mt][nt][1] * scale);
                *(uint32_t*)(Chs + o1) = pack2h(acc[mt][nt][2] * scale,
                                                acc[mt][nt][3] * scale);
            }
        }
    }
}

// ============================================================
// Flash attention (causal) on mma.sync, fp16 single-stream,
// base-2 softmax via MUFU.EX2, Q fragments register-resident.
// CTA: 256 threads / 8 warps; tile 128 q-rows x 64 kv.
// ============================================================
#define FSTR 144
#define FKTILE (64 * FSTR)            // 9216 B
#define FQTILE (128 * FSTR)           // 18432 B
#define FSTAGEB (2 * FKTILE)          // Kh, Vh = 18432 B
#define FSMEM (FQTILE + 2 * FSTAGEB)  // 55296 B

__global__ __launch_bounds__(256, 2) void flash_mma_kernel(
    const fp16* __restrict__ Qh,
    const fp16* __restrict__ Kh, const fp16* __restrict__ Vh,
    fp16* __restrict__ Oh)
{
    extern __shared__ __align__(1024) char dsm[];
    const uint32_t sbase = smem_u32(dsm);

    const int tid = threadIdx.x;
    const int lane = tid & 31;
    const int w = tid >> 5;                 // 0..7
    const int qt = (int)gridDim.x - 1 - (int)blockIdx.x;   // big tiles first
    const int h = blockIdx.y, b = blockIdx.z;

    const size_t base = ((size_t)b * SS) * DD + (size_t)h * HDIM;
    const fp16* gq = Qh + base + (size_t)(qt * 128) * DD;

    // ---- load Q (128 rows), grouped with kv stage0 ----
    {
        #pragma unroll
        for (int p = 0; p < 4; p++) {
            int i = tid + p * 256;          // 0..1023
            int row = i >> 3;
            int ch = i & 7;
            CP_ASYNC16(sbase + row * FSTR + ch * 16,
                       gq + (size_t)row * DD + ch * 8);
        }
    }

    const fp16* gkv[2] = {Kh + base, Vh + base};
    auto load_kv = [&](int kt, int st) {
        const uint32_t s0 = sbase + FQTILE + st * FSTAGEB;
        const size_t roff = (size_t)(kt * 64) * DD;
        #pragma unroll
        for (int p = 0; p < 4; p++) {
            int i = tid + p * 256;          // 0..1023
            int t = i >> 9;
            int rem = i & 511;
            int row = rem >> 3;
            int ch = rem & 7;
            CP_ASYNC16(s0 + t * FKTILE + row * FSTR + ch * 16,
                       gkv[t] + roff + (size_t)row * DD + ch * 8);
        }
        CP_COMMIT();
    };

    load_kv(0, 0);

    const int qr = lane >> 2;
    const int ql2 = (lane & 3) * 2;
    const int lrow = lane & 15;
    const int lhalf = (lane >> 4) * 16;

    float oacc[8][4];
    #pragma unroll
    for (int nt = 0; nt < 8; nt++)
        #pragma unroll
        for (int j = 0; j < 4; j++) oacc[nt][j] = 0.f;
    float m0 = -CUDART_INF_F, m1 = -CUDART_INF_F;
    float l0 = 0.f, l1 = 0.f;

    uint32_t qfrag[4][4];                   // Q fragments, register-resident

    const int wrow = w * 16;
    const int row0g = qt * 128 + wrow;
    const int nk = 2 * qt + 2;

    for (int kt = 0; kt < nk; kt++) {
        CP_WAIT(0);
        __syncthreads();
        if (kt + 1 < nk) load_kv(kt + 1, (kt + 1) & 1);

        if (kt == 0) {
            // load Q fragments once (Q landed with stage 0)
            #pragma unroll
            for (int kk = 0; kk < 4; kk++) {
                uint32_t aoff = (uint32_t)(wrow + lrow) * FSTR + lhalf + kk * 32;
                ldsm_x4(qfrag[kk][0], qfrag[kk][1], qfrag[kk][2], qfrag[kk][3],
                        sbase + aoff);
            }
        }

        if (kt * 64 <= row0g + 15) {      // warp early-out
            const uint32_t s0  = sbase + FQTILE + (kt & 1) * FSTAGEB;
            const uint32_t sKh = s0, sVh = s0 + FKTILE;

            // ---- S = Qh @ Kh^T, log2 units ----
            float sac[8][4];
            #pragma unroll
            for (int nt = 0; nt < 8; nt++)
                #pragma unroll
                for (int j = 0; j < 4; j++) sac[nt][j] = 0.f;

            #pragma unroll
            for (int kk = 0; kk < 4; kk++) {
                #pragma unroll
                for (int ng = 0; ng < 4; ng++) {
                    uint32_t boff = (uint32_t)(ng * 16 + lrow) * FSTR + lhalf + kk * 32;
                    uint32_t kh_[4];
                    ldsm_x4(kh_[0], kh_[1], kh_[2], kh_[3], sKh + boff);
                    mma16816(sac[2 * ng],     qfrag[kk], kh_[0], kh_[2]);
                    mma16816(sac[2 * ng + 1], qfrag[kk], kh_[1], kh_[3]);
                }
            }

            // ---- causal mask when tile straddles this warp's diagonal ----
            if (kt * 64 + 63 > row0g) {
                const int r0 = row0g + qr, r1 = r0 + 8;
                #pragma unroll
                for (int nt = 0; nt < 8; nt++) {
                    int c = kt * 64 + nt * 8 + ql2;
                    if (c > r0)     sac[nt][0] = -CUDART_INF_F;
                    if (c + 1 > r0) sac[nt][1] = -CUDART_INF_F;
                    if (c > r1)     sac[nt][2] = -CUDART_INF_F;
                    if (c + 1 > r1) sac[nt][3] = -CUDART_INF_F;
                }
            }

            // ---- online softmax (base 2, MUFU.EX2) ----
            float mx0 = -CUDART_INF_F, mx1 = -CUDART_INF_F;
            #pragma unroll
            for (int nt = 0; nt < 8; nt++) {
                mx0 = fmaxf(mx0, fmaxf(sac[nt][0], sac[nt][1]));
                mx1 = fmaxf(mx1, fmaxf(sac[nt][2], sac[nt][3]));
            }
            mx0 = fmaxf(mx0, __shfl_xor_sync(0xffffffffu, mx0, 1));
            mx0 = fmaxf(mx0, __shfl_xor_sync(0xffffffffu, mx0, 2));
            mx1 = fmaxf(mx1, __shfl_xor_sync(0xffffffffu, mx1, 1));
            mx1 = fmaxf(mx1, __shfl_xor_sync(0xffffffffu, mx1, 2));

            float mn0 = fmaxf(m0, mx0), mn1 = fmaxf(m1, mx1);
            float cr0 = ex2(m0 - mn0), cr1 = ex2(m1 - mn1);
            m0 = mn0; m1 = mn1;

            float ls0 = 0.f, ls1 = 0.f;
            #pragma unroll
            for (int nt = 0; nt < 8; nt++) {
                float p0 = ex2(sac[nt][0] - m0);
                float p1 = ex2(sac[nt][1] - m0);
                float p2 = ex2(sac[nt][2] - m1);
                float p3 = ex2(sac[nt][3] - m1);
                sac[nt][0] = p0; sac[nt][1] = p1; sac[nt][2] = p2; sac[nt][3] = p3;
                ls0 += p0 + p1;
                ls1 += p2 + p3;
            }
            ls0 += __shfl_xor_sync(0xffffffffu, ls0, 1);
            ls0 += __shfl_xor_sync(0xffffffffu, ls0, 2);
            ls1 += __shfl_xor_sync(0xffffffffu, ls1, 1);
            ls1 += __shfl_xor_sync(0xffffffffu, ls1, 2);
            l0 = l0 * cr0 + ls0;
            l1 = l1 * cr1 + ls1;

            #pragma unroll
            for (int nt = 0; nt < 8; nt++) {
                oacc[nt][0] *= cr0; oacc[nt][1] *= cr0;
                oacc[nt][2] *= cr1; oacc[nt][3] *= cr1;
            }

            // ---- O += Ph @ Vh ----
            #pragma unroll
            for (int kk = 0; kk < 4; kk++) {
                uint32_t ph_[4];
                ph_[0] = pack2h(sac[2 * kk][0],     sac[2 * kk][1]);
                ph_[1] = pack2h(sac[2 * kk][2],     sac[2 * kk][3]);
                ph_[2] = pack2h(sac[2 * kk + 1][0], sac[2 * kk + 1][1]);
                ph_[3] = pack2h(sac[2 * kk + 1][2], sac[2 * kk + 1][3]);
                #pragma unroll
                for (int ng = 0; ng < 4; ng++) {
                    uint32_t voff = (uint32_t)(kk * 16 + lrow) * FSTR + ng * 32 + lhalf;
                    uint32_t vh_[4];
                    ldsm_x4_t(vh_[0], vh_[1], vh_[2], vh_[3], sVh + voff);
                    mma16816(oacc[2 * ng],     ph_, vh_[0], vh_[1]);
                    mma16816(oacc[2 * ng + 1], ph_, vh_[2], vh_[3]);
                }
            }
        }
    }

    // ---- epilogue: normalize, store fp16 ----
    const float inv0 = 1.0f / l0, inv1 = 1.0f / l1;
    const size_t orow0 = base + (size_t)(qt * 128 + wrow + qr) * DD;
    const size_t orow1 = orow0 + 8 * DD;
    #pragma unroll
    for (int nt = 0; nt < 8; nt++) {
        int d = nt * 8 + ql2;
        *(uint32_t*)(Oh + orow0 + d) = pack2h(oacc[nt][0] * inv0, oacc[nt][1] * inv0);
        *(uint32_t*)(Oh + orow1 + d) = pack2h(oacc[nt][2] * inv1, oacc[nt][3] * inv1);
    }
}

// ============================================================
// Launch
// ============================================================
extern "C" void kernel_launch(void* const* d_in, const int* in_sizes, int n_in,
                              void* d_out, int out_size)
{
    const float* x  = (const float*)d_in[0];
    const float* Wq = (const float*)d_in[1];
    const float* Wk = (const float*)d_in[2];
    const float* Wv = (const float*)d_in[3];
    const float* Wo = (const float*)d_in[4];
    const float* bo = (const float*)d_in[5];
    float* out = (float*)d_out;

    fp16 *xh, *qkvh, *wqkvh, *woh;
    cudaGetSymbolAddress((void**)&xh, g_xh);
    cudaGetSymbolAddress((void**)&qkvh, g_qkvh);
    cudaGetSymbolAddress((void**)&wqkvh, g_wqkvh);
    cudaGetSymbolAddress((void**)&woh, g_woh);

    // 1. convert x -> fp16
    const int n4 = MTOK * DD / 4;
    convert_kernel<<<n4 / 256, 256>>>(x, xh, n4);

    // 2. fused transpose of all 4 weights -> fp16
    transpose4_kernel<<<dim3(DD / 32, DD / 32, 4), dim3(32, 8)>>>(
        Wq, Wk, Wv, Wo, wqkvh, woh);

    // 3. fused QKV projection (single launch, N=3072), fp16 outputs
    const float qscale = 0.125f * 1.4426950408889634f;
    cudaFuncSetAttribute(gemm_mma_kernel,
                         cudaFuncAttributeMaxDynamicSharedMemorySize, GSMEM);
    gemm_mma_kernel<<<dim3(24, MTOK / 128), 256, GSMEM>>>(
        xh, wqkvh, nullptr, nullptr, qkvh, qscale);

    // 4. flash attention; writes fp16 output into xh
    const size_t seg = (size_t)MTOK * DD;
    cudaFuncSetAttribute(flash_mma_kernel,
                         cudaFuncAttributeMaxDynamicSharedMemorySize, FSMEM);
    flash_mma_kernel<<<dim3(SS / 128, HH, BB), 256, FSMEM>>>(
        qkvh, qkvh + seg, qkvh + 2 * seg, xh);

    // 5. output projection (+bias), fp32 out
    gemm_mma_kernel<<<dim3(8, MTOK / 128), 256, GSMEM>>>(
        xh, woh, bo, out, nullptr, 1.0f);
}

// round 13
// speedup vs baseline: 8.1718x; 1.0799x over previous
#include <cuda_runtime.h>
#include <cuda_fp16.h>
#include <math_constants.h>
#include <cstdint>

// Problem constants
#define BB 4
#define SS 2048
#define DD 1024
#define HH 16
#define HDIM 64
#define MTOK (BB * SS)   // 8192
#define GK DD            // GEMM K = 1024

typedef __half fp16;

// ---------------- scratch (__device__ globals; allocation-free rule) -------
__device__ fp16 g_xh[MTOK * DD];                        // x fp16; reused for attn out
__device__ fp16 g_qkvh[3 * MTOK * DD];                  // Q|K|V (fp16)
__device__ fp16 g_wqkvh[3 * DD * DD];                   // Wq|Wk|Wv transposed, fp16
__device__ fp16 g_woh[DD * DD];

// ---------------- helpers (plain sm_90-era PTX only) ------------------------
__device__ __forceinline__ uint32_t smem_u32(const void* p) {
    uint32_t a;
    asm("{ .reg .u64 t; cvta.to.shared.u64 t, %1; cvt.u32.u64 %0, t; }"
        : "=r"(a) : "l"(p));
    return a;
}
__device__ __forceinline__ void ldsm_x4(uint32_t& r0, uint32_t& r1,
                                        uint32_t& r2, uint32_t& r3, uint32_t addr) {
    asm volatile("ldmatrix.sync.aligned.m8n8.x4.shared.b16 {%0,%1,%2,%3}, [%4];"
                 : "=r"(r0), "=r"(r1), "=r"(r2), "=r"(r3) : "r"(addr));
}
__device__ __forceinline__ void ldsm_x4_t(uint32_t& r0, uint32_t& r1,
                                          uint32_t& r2, uint32_t& r3, uint32_t addr) {
    asm volatile("ldmatrix.sync.aligned.m8n8.x4.trans.shared.b16 {%0,%1,%2,%3}, [%4];"
                 : "=r"(r0), "=r"(r1), "=r"(r2), "=r"(r3) : "r"(addr));
}
__device__ __forceinline__ void mma16816(float* c, const uint32_t* a,
                                         uint32_t b0, uint32_t b1) {
    asm volatile(
        "mma.sync.aligned.m16n8k16.row.col.f32.f16.f16.f32 "
        "{%0,%1,%2,%3}, {%4,%5,%6,%7}, {%8,%9}, {%0,%1,%2,%3};"
        : "+f"(c[0]), "+f"(c[1]), "+f"(c[2]), "+f"(c[3])
        : "r"(a[0]), "r"(a[1]), "r"(a[2]), "r"(a[3]), "r"(b0), "r"(b1));
}
#define CP_ASYNC16(saddr, gaddr) \
    asm volatile("cp.async.cg.shared.global [%0], [%1], 16;" :: "r"(saddr), "l"(gaddr))
#define CP_COMMIT() asm volatile("cp.async.commit_group;" ::: "memory")
#define CP_WAIT(n)  asm volatile("cp.async.wait_group %0;" :: "n"(n) : "memory")

// swizzles
#define SW64(off)  ((off) ^ (((off) >> 3) & 0x30))   // 64B rows
#define SW128(off) ((off) ^ (((off) >> 3) & 0x70))   // 128B rows

__device__ __forceinline__ uint32_t pack2h(float a, float b) {
    __half2 t = __floats2half2_rn(a, b);
    return *reinterpret_cast<uint32_t*>(&t);
}
// fast exp2 via MUFU.EX2 (flag-independent)
__device__ __forceinline__ float ex2(float x) {
    float y;
    asm("ex2.approx.ftz.f32 %0, %1;" : "=f"(y) : "f"(x));
    return y;
}

// ============================================================
// convert: fp32 -> fp16 (x)
// ============================================================
__global__ __launch_bounds__(256) void convert_kernel(
    const float* __restrict__ in, fp16* __restrict__ hi, int n4)
{
    int i = blockIdx.x * blockDim.x + threadIdx.x;
    if (i >= n4) return;
    float4 v = reinterpret_cast<const float4*>(in)[i];
    uint2 hh;
    hh.x = pack2h(v.x, v.y);
    hh.y = pack2h(v.z, v.w);
    reinterpret_cast<uint2*>(hi)[i] = hh;
}

// ============================================================
// fused transpose of all 4 weights -> fp16
// ============================================================
__global__ __launch_bounds__(256) void transpose4_kernel(
    const float* __restrict__ Wq, const float* __restrict__ Wk,
    const float* __restrict__ Wv, const float* __restrict__ Wo,
    fp16* __restrict__ Wqkvh, fp16* __restrict__ Woh)
{
    __shared__ float t[32][33];
    const int z = blockIdx.z;
    const float* W = (z == 0) ? Wq : (z == 1) ? Wk : (z == 2) ? Wv : Wo;
    fp16* Th = (z < 3) ? Wqkvh + (size_t)z * DD * DD : Woh;

    const int bx = blockIdx.x, by = blockIdx.y;
    const int x = threadIdx.x, y = threadIdx.y;  // 32 x 8
    #pragma unroll
    for (int i = 0; i < 4; i++)
        t[y + 8 * i][x] = W[(size_t)(by * 32 + y + 8 * i) * DD + bx * 32 + x];
    __syncthreads();
    #pragma unroll
    for (int i = 0; i < 4; i++) {
        float v = t[x][y + 8 * i];
        Th[(size_t)(bx * 32 + y + 8 * i) * DD + by * 32 + x] = __float2half_rn(v);
    }
}

// ============================================================
// fp16 GEMM on mma.sync: C = Ah[M,K] @ Bh[N,K]^T.
// K-chunk 64 (SW128, 128B rows), 3-stage cp.async pipeline,
// 1 barrier per chunk (16 total).
// ============================================================
#define CHK 64
#define GTILE 16384              // 128 rows x 128 B
#define GSTAGE (2 * GTILE)       // Ah, Bh = 32768 B
#define GSMEM (3 * GSTAGE)       // 98304 B

__global__ __launch_bounds__(256, 2) void gemm_mma_kernel(
    const fp16* __restrict__ Ah, const fp16* __restrict__ Bh,
    const float* __restrict__ bias, float* __restrict__ Cf,
    fp16* __restrict__ Ch, float qscale)
{
    extern __shared__ __align__(1024) char dsm[];
    const uint32_t sbase = smem_u32(dsm);

    const int tid = threadIdx.x;
    const int lane = tid & 31;
    const int wid = tid >> 5;
    const int warp_m = wid & 3;
    const int warp_n = wid >> 2;
    const int br = blockIdx.y, bc = blockIdx.x;

    const fp16* gsrc[2] = {
        Ah + (size_t)(br * 128) * GK,
        Bh + (size_t)(bc * 128) * GK
    };

    auto load_stage = [&](int k0, int st) {
        const uint32_t s0 = sbase + st * GSTAGE;
        #pragma unroll
        for (int p = 0; p < 8; p++) {
            int idx = tid + p * 256;        // 0..2047
            int t   = idx >> 10;
            int rem = idx & 1023;
            int row = rem >> 3;
            int ch  = rem & 7;
            uint32_t sa = s0 + t * GTILE + SW128((uint32_t)(row * 128 + ch * 16));
            const fp16* g = gsrc[t] + (size_t)row * GK + k0 + ch * 8;
            CP_ASYNC16(sa, g);
        }
        CP_COMMIT();
    };

    float acc[2][8][4];
    #pragma unroll
    for (int mt = 0; mt < 2; mt++)
        #pragma unroll
        for (int nt = 0; nt < 8; nt++)
            #pragma unroll
            for (int j = 0; j < 4; j++) acc[mt][nt][j] = 0.f;

    const int NC = GK / CHK;   // 16
    load_stage(0, 0);
    load_stage(CHK, 1);

    const int lrow = lane & 15;
    const int lsel = (lane >> 4) * 16;

    int st = 0;                 // stage of chunk c (mod 3)
    for (int c = 0; c < NC; c++) {
        if (c + 1 < NC) { CP_WAIT(1); } else { CP_WAIT(0); }
        __syncthreads();
        if (c + 2 < NC) {
            int nst = st + 2; if (nst >= 3) nst -= 3;
            load_stage((c + 2) * CHK, nst);
        }

        const uint32_t s0  = sbase + st * GSTAGE;
        const uint32_t sAh = s0, sBh = s0 + GTILE;

        #pragma unroll
        for (int kk = 0; kk < 4; kk++) {
            const int lcol = lsel + kk * 32;
            uint32_t ah[2][4];
            #pragma unroll
            for (int mt = 0; mt < 2; mt++) {
                uint32_t off = SW128((uint32_t)((warp_m * 32 + mt * 16 + lrow) * 128 + lcol));
                ldsm_x4(ah[mt][0], ah[mt][1], ah[mt][2], ah[mt][3], sAh + off);
            }
            #pragma unroll
            for (int ng = 0; ng < 4; ng++) {
                uint32_t off = SW128((uint32_t)((warp_n * 64 + ng * 16 + lrow) * 128 + lcol));
                uint32_t bh[4];
                ldsm_x4(bh[0], bh[1], bh[2], bh[3], sBh + off);
                #pragma unroll
                for (int mt = 0; mt < 2; mt++) {
                    mma16816(acc[mt][2 * ng],     ah[mt], bh[0], bh[2]);
                    mma16816(acc[mt][2 * ng + 1], ah[mt], bh[1], bh[3]);
                }
            }
        }
        if (++st == 3) st = 0;
    }

    const int row0 = br * 128 + warp_m * 32;
    const int col0 = (bc & 7) * 128 + warp_n * 64;
    const int qr = lane >> 2;
    const int qc = (lane & 3) * 2;

    if (Cf) {
        #pragma unroll
        for (int mt = 0; mt < 2; mt++) {
            #pragma unroll
            for (int nt = 0; nt < 8; nt++) {
                int col = col0 + nt * 8 + qc;
                float b0 = 0.f, b1 = 0.f;
                if (bias) { b0 = bias[col]; b1 = bias[col + 1]; }
                size_t o0 = (size_t)(row0 + mt * 16 + qr) * DD + col;
                size_t o1 = o0 + 8 * DD;
                float2 w0, w1;
                w0.x = acc[mt][nt][0] + b0; w0.y = acc[mt][nt][1] + b1;
                w1.x = acc[mt][nt][2] + b0; w1.y = acc[mt][nt][3] + b1;
                *(float2*)(Cf + o0) = w0;
                *(float2*)(Cf + o1) = w1;
            }
        }
    } else {
        const int sel = bc >> 3;                 // 0=Q 1=K 2=V
        const float scale = (sel == 0) ? qscale : 1.0f;
        fp16* Chs = Ch + (size_t)sel * MTOK * DD;
        #pragma unroll
        for (int mt = 0; mt < 2; mt++) {
            #pragma unroll
            for (int nt = 0; nt < 8; nt++) {
                int col = col0 + nt * 8 + qc;
                size_t o0 = (size_t)(row0 + mt * 16 + qr) * DD + col;
                size_t o1 = o0 + 8 * DD;
                *(uint32_t*)(Chs + o0) = pack2h(acc[mt][nt][0] * scale,
                                                acc[mt][nt][1] * scale);
                *(uint32_t*)(Chs + o1) = pack2h(acc[mt][nt][2] * scale,
                                                acc[mt][nt][3] * scale);
            }
        }
    }
}

// ============================================================
// Flash attention (causal) on mma.sync, fp16 single-stream,
// base-2 softmax via MUFU.EX2, Q fragments register-resident,
// 3-stage KV pipeline.
// CTA: 256 threads / 8 warps; tile 128 q-rows x 64 kv.
// ============================================================
#define FSTR 144
#define FKTILE (64 * FSTR)            // 9216 B
#define FQTILE (128 * FSTR)           // 18432 B
#define FSTAGEB (2 * FKTILE)          // Kh, Vh = 18432 B
#define FSMEM (FQTILE + 3 * FSTAGEB)  // 73728 B

__global__ __launch_bounds__(256, 2) void flash_mma_kernel(
    const fp16* __restrict__ Qh,
    const fp16* __restrict__ Kh, const fp16* __restrict__ Vh,
    fp16* __restrict__ Oh)
{
    extern __shared__ __align__(1024) char dsm[];
    const uint32_t sbase = smem_u32(dsm);

    const int tid = threadIdx.x;
    const int lane = tid & 31;
    const int w = tid >> 5;                 // 0..7
    const int qt = (int)gridDim.x - 1 - (int)blockIdx.x;   // big tiles first
    const int h = blockIdx.y, b = blockIdx.z;

    const size_t base = ((size_t)b * SS) * DD + (size_t)h * HDIM;
    const fp16* gq = Qh + base + (size_t)(qt * 128) * DD;

    // ---- load Q (128 rows), grouped with kv stage0 ----
    {
        #pragma unroll
        for (int p = 0; p < 4; p++) {
            int i = tid + p * 256;          // 0..1023
            int row = i >> 3;
            int ch = i & 7;
            CP_ASYNC16(sbase + row * FSTR + ch * 16,
                       gq + (size_t)row * DD + ch * 8);
        }
    }

    const fp16* gkv[2] = {Kh + base, Vh + base};
    auto load_kv = [&](int kt, int st) {
        const uint32_t s0 = sbase + FQTILE + st * FSTAGEB;
        const size_t roff = (size_t)(kt * 64) * DD;
        #pragma unroll
        for (int p = 0; p < 4; p++) {
            int i = tid + p * 256;          // 0..1023
            int t = i >> 9;
            int rem = i & 511;
            int row = rem >> 3;
            int ch = rem & 7;
            CP_ASYNC16(s0 + t * FKTILE + row * FSTR + ch * 16,
                       gkv[t] + roff + (size_t)row * DD + ch * 8);
        }
        CP_COMMIT();
    };

    const int nk = 2 * qt + 2;              // >= 2 always
    load_kv(0, 0);                           // commits Q + kv0
    load_kv(1, 1);

    const int qr = lane >> 2;
    const int ql2 = (lane & 3) * 2;
    const int lrow = lane & 15;
    const int lhalf = (lane >> 4) * 16;

    float oacc[8][4];
    #pragma unroll
    for (int nt = 0; nt < 8; nt++)
        #pragma unroll
        for (int j = 0; j < 4; j++) oacc[nt][j] = 0.f;
    float m0 = -CUDART_INF_F, m1 = -CUDART_INF_F;
    float l0 = 0.f, l1 = 0.f;

    uint32_t qfrag[4][4];                   // Q fragments, register-resident

    const int wrow = w * 16;
    const int row0g = qt * 128 + wrow;

    int fst = 0;                             // stage of tile kt (mod 3)
    for (int kt = 0; kt < nk; kt++) {
        if (kt + 1 < nk) { CP_WAIT(1); } else { CP_WAIT(0); }
        __syncthreads();
        if (kt + 2 < nk) {
            int nst = fst + 2; if (nst >= 3) nst -= 3;
            load_kv(kt + 2, nst);
        }

        if (kt == 0) {
            // load Q fragments once (Q landed with stage 0)
            #pragma unroll
            for (int kk = 0; kk < 4; kk++) {
                uint32_t aoff = (uint32_t)(wrow + lrow) * FSTR + lhalf + kk * 32;
                ldsm_x4(qfrag[kk][0], qfrag[kk][1], qfrag[kk][2], qfrag[kk][3],
                        sbase + aoff);
            }
        }

        if (kt * 64 <= row0g + 15) {      // warp early-out
            const uint32_t s0  = sbase + FQTILE + fst * FSTAGEB;
            const uint32_t sKh = s0, sVh = s0 + FKTILE;

            // ---- S = Qh @ Kh^T, log2 units ----
            float sac[8][4];
            #pragma unroll
            for (int nt = 0; nt < 8; nt++)
                #pragma unroll
                for (int j = 0; j < 4; j++) sac[nt][j] = 0.f;

            #pragma unroll
            for (int kk = 0; kk < 4; kk++) {
                #pragma unroll
                for (int ng = 0; ng < 4; ng++) {
                    uint32_t boff = (uint32_t)(ng * 16 + lrow) * FSTR + lhalf + kk * 32;
                    uint32_t kh_[4];
                    ldsm_x4(kh_[0], kh_[1], kh_[2], kh_[3], sKh + boff);
                    mma16816(sac[2 * ng],     qfrag[kk], kh_[0], kh_[2]);
                    mma16816(sac[2 * ng + 1], qfrag[kk], kh_[1], kh_[3]);
                }
            }

            // ---- causal mask when tile straddles this warp's diagonal ----
            if (kt * 64 + 63 > row0g) {
                const int r0 = row0g + qr, r1 = r0 + 8;
                #pragma unroll
                for (int nt = 0; nt < 8; nt++) {
                    int c = kt * 64 + nt * 8 + ql2;
                    if (c > r0)     sac[nt][0] = -CUDART_INF_F;
                    if (c + 1 > r0) sac[nt][1] = -CUDART_INF_F;
                    if (c > r1)     sac[nt][2] = -CUDART_INF_F;
                    if (c + 1 > r1) sac[nt][3] = -CUDART_INF_F;
                }
            }

            // ---- online softmax (base 2, MUFU.EX2) ----
            float mx0 = -CUDART_INF_F, mx1 = -CUDART_INF_F;
            #pragma unroll
            for (int nt = 0; nt < 8; nt++) {
                mx0 = fmaxf(mx0, fmaxf(sac[nt][0], sac[nt][1]));
                mx1 = fmaxf(mx1, fmaxf(sac[nt][2], sac[nt][3]));
            }
            mx0 = fmaxf(mx0, __shfl_xor_sync(0xffffffffu, mx0, 1));
            mx0 = fmaxf(mx0, __shfl_xor_sync(0xffffffffu, mx0, 2));
            mx1 = fmaxf(mx1, __shfl_xor_sync(0xffffffffu, mx1, 1));
            mx1 = fmaxf(mx1, __shfl_xor_sync(0xffffffffu, mx1, 2));

            float mn0 = fmaxf(m0, mx0), mn1 = fmaxf(m1, mx1);
            float cr0 = ex2(m0 - mn0), cr1 = ex2(m1 - mn1);
            m0 = mn0; m1 = mn1;

            float ls0 = 0.f, ls1 = 0.f;
            #pragma unroll
            for (int nt = 0; nt < 8; nt++) {
                float p0 = ex2(sac[nt][0] - m0);
                float p1 = ex2(sac[nt][1] - m0);
                float p2 = ex2(sac[nt][2] - m1);
                float p3 = ex2(sac[nt][3] - m1);
                sac[nt][0] = p0; sac[nt][1] = p1; sac[nt][2] = p2; sac[nt][3] = p3;
                ls0 += p0 + p1;
                ls1 += p2 + p3;
            }
            ls0 += __shfl_xor_sync(0xffffffffu, ls0, 1);
            ls0 += __shfl_xor_sync(0xffffffffu, ls0, 2);
            ls1 += __shfl_xor_sync(0xffffffffu, ls1, 1);
            ls1 += __shfl_xor_sync(0xffffffffu, ls1, 2);
            l0 = l0 * cr0 + ls0;
            l1 = l1 * cr1 + ls1;

            #pragma unroll
            for (int nt = 0; nt < 8; nt++) {
                oacc[nt][0] *= cr0; oacc[nt][1] *= cr0;
                oacc[nt][2] *= cr1; oacc[nt][3] *= cr1;
            }

            // ---- O += Ph @ Vh ----
            #pragma unroll
            for (int kk = 0; kk < 4; kk++) {
                uint32_t ph_[4];
                ph_[0] = pack2h(sac[2 * kk][0],     sac[2 * kk][1]);
                ph_[1] = pack2h(sac[2 * kk][2],     sac[2 * kk][3]);
                ph_[2] = pack2h(sac[2 * kk + 1][0], sac[2 * kk + 1][1]);
                ph_[3] = pack2h(sac[2 * kk + 1][2], sac[2 * kk + 1][3]);
                #pragma unroll
                for (int ng = 0; ng < 4; ng++) {
                    uint32_t voff = (uint32_t)(kk * 16 + lrow) * FSTR + ng * 32 + lhalf;
                    uint32_t vh_[4];
                    ldsm_x4_t(vh_[0], vh_[1], vh_[2], vh_[3], sVh + voff);
                    mma16816(oacc[2 * ng],     ph_, vh_[0], vh_[1]);
                    mma16816(oacc[2 * ng + 1], ph_, vh_[2], vh_[3]);
                }
            }
        }
        if (++fst == 3) fst = 0;
    }

    // ---- epilogue: normalize, store fp16 ----
    const float inv0 = 1.0f / l0, inv1 = 1.0f / l1;
    const size_t orow0 = base + (size_t)(qt * 128 + wrow + qr) * DD;
    const size_t orow1 = orow0 + 8 * DD;
    #pragma unroll
    for (int nt = 0; nt < 8; nt++) {
        int d = nt * 8 + ql2;
        *(uint32_t*)(Oh + orow0 + d) = pack2h(oacc[nt][0] * inv0, oacc[nt][1] * inv0);
        *(uint32_t*)(Oh + orow1 + d) = pack2h(oacc[nt][2] * inv1, oacc[nt][3] * inv1);
    }
}

// ============================================================
// Launch
// ============================================================
extern "C" void kernel_launch(void* const* d_in, const int* in_sizes, int n_in,
                              void* d_out, int out_size)
{
    const float* x  = (const float*)d_in[0];
    const float* Wq = (const float*)d_in[1];
    const float* Wk = (const float*)d_in[2];
    const float* Wv = (const float*)d_in[3];
    const float* Wo = (const float*)d_in[4];
    const float* bo = (const float*)d_in[5];
    float* out = (float*)d_out;

    fp16 *xh, *qkvh, *wqkvh, *woh;
    cudaGetSymbolAddress((void**)&xh, g_xh);
    cudaGetSymbolAddress((void**)&qkvh, g_qkvh);
    cudaGetSymbolAddress((void**)&wqkvh, g_wqkvh);
    cudaGetSymbolAddress((void**)&woh, g_woh);

    // 1. convert x -> fp16
    const int n4 = MTOK * DD / 4;
    convert_kernel<<<n4 / 256, 256>>>(x, xh, n4);

    // 2. fused transpose of all 4 weights -> fp16
    transpose4_kernel<<<dim3(DD / 32, DD / 32, 4), dim3(32, 8)>>>(
        Wq, Wk, Wv, Wo, wqkvh, woh);

    // 3. fused QKV projection (single launch, N=3072), fp16 outputs
    const float qscale = 0.125f * 1.4426950408889634f;
    cudaFuncSetAttribute(gemm_mma_kernel,
                         cudaFuncAttributeMaxDynamicSharedMemorySize, GSMEM);
    gemm_mma_kernel<<<dim3(24, MTOK / 128), 256, GSMEM>>>(
        xh, wqkvh, nullptr, nullptr, qkvh, qscale);

    // 4. flash attention; writes fp16 output into xh
    const size_t seg = (size_t)MTOK * DD;
    cudaFuncSetAttribute(flash_mma_kernel,
                         cudaFuncAttributeMaxDynamicSharedMemorySize, FSMEM);
    flash_mma_kernel<<<dim3(SS / 128, HH, BB), 256, FSMEM>>>(
        qkvh, qkvh + seg, qkvh + 2 * seg, xh);

    // 5. output projection (+bias), fp32 out
    gemm_mma_kernel<<<dim3(8, MTOK / 128), 256, GSMEM>>>(
        xh, woh, bo, out, nullptr, 1.0f);
}